// round 10
// baseline (speedup 1.0000x reference)
#include <cuda_runtime.h>
#include <cuda_bf16.h>
#include <math.h>
#include <stdint.h>

#define BB   4
#define TT   1024
#define DD   1024
#define HH   16
#define HSZ  64
#define EE   8
#define DFF_ 4096
#define BT   4096
#define NSLOT (BT*2)

// ---------------- device scratch ----------------
__device__ float g_x2 [BT*DD];
__device__ float g_xn2[BT*DD];
__device__ float g_eo [NSLOT*DD];

__device__ __align__(16) __nv_bfloat16 g_qh[BT*DD], g_ql[BT*DD];
__device__ __align__(16) __nv_bfloat16 g_kh[BT*DD], g_kl[BT*DD];
__device__ __align__(16) __nv_bfloat16 g_vh[BT*DD], g_vl[BT*DD];
__device__ __align__(16) __nv_bfloat16 g_xn_h [BT*DD], g_xn_l [BT*DD];
__device__ __align__(16) __nv_bfloat16 g_hd_h [BT*DD], g_hd_l [BT*DD];
__device__ __align__(16) __nv_bfloat16 g_xn2_h[BT*DD], g_xn2_l[BT*DD];
__device__ __align__(16) __nv_bfloat16 g_h_h  [NSLOT*DFF_], g_h_l[NSLOT*DFF_];
__device__ __align__(16) __nv_bfloat16 g_wqkv_h[DD*3*DD], g_wqkv_l[DD*3*DD];
__device__ __align__(16) __nv_bfloat16 g_wp_h  [DD*DD],   g_wp_l  [DD*DD];
__device__ __align__(16) __nv_bfloat16 g_w1_h[EE*DD*DFF_], g_w1_l[EE*DD*DFF_];
__device__ __align__(16) __nv_bfloat16 g_w2_h[EE*DFF_*DD], g_w2_l[EE*DFF_*DD];

__device__ int   g_cnt [EE];
__device__ int   g_base[EE];
__device__ int   g_tok [EE*BT];
__device__ int   g_texp[BT*2];
__device__ int   g_tpos[BT*2];
__device__ float g_tgate[BT*2];

// ---------------- helpers ----------------
__device__ __forceinline__ uint32_t smem_u32(const void* p) {
    uint32_t a;
    asm("{ .reg .u64 t; cvta.to.shared.u64 t, %1; cvt.u32.u64 %0, t; }" : "=r"(a) : "l"(p));
    return a;
}
__device__ __forceinline__ void cpa16(uint32_t dst, const void* src, int valid) {
    asm volatile("cp.async.cg.shared.global [%0], [%1], 16, %2;"
                 :: "r"(dst), "l"(src), "r"(valid ? 16 : 0) : "memory");
}
__device__ __forceinline__ void ldsm4(uint32_t* r, uint32_t addr) {
    asm volatile("ldmatrix.sync.aligned.m8n8.x4.shared.b16 {%0,%1,%2,%3}, [%4];"
                 : "=r"(r[0]), "=r"(r[1]), "=r"(r[2]), "=r"(r[3]) : "r"(addr));
}
__device__ __forceinline__ void ldsm4t(uint32_t* r, uint32_t addr) {
    asm volatile("ldmatrix.sync.aligned.m8n8.x4.trans.shared.b16 {%0,%1,%2,%3}, [%4];"
                 : "=r"(r[0]), "=r"(r[1]), "=r"(r[2]), "=r"(r[3]) : "r"(addr));
}
__device__ __forceinline__ void mma16816(float* c, const uint32_t* a, const uint32_t* b) {
    asm volatile(
        "mma.sync.aligned.m16n8k16.row.col.f32.bf16.bf16.f32 "
        "{%0,%1,%2,%3},{%4,%5,%6,%7},{%8,%9},{%0,%1,%2,%3};"
        : "+f"(c[0]), "+f"(c[1]), "+f"(c[2]), "+f"(c[3])
        : "r"(a[0]), "r"(a[1]), "r"(a[2]), "r"(a[3]), "r"(b[0]), "r"(b[1]));
}
__device__ __forceinline__ void bf16_split(float v, __nv_bfloat16& h, __nv_bfloat16& l) {
    h = __float2bfloat16(v);
    l = __float2bfloat16(v - __bfloat162float(h));
}
__device__ __forceinline__ uint32_t pack2(__nv_bfloat16 a, __nv_bfloat16 b) {
    return ((uint32_t)__bfloat16_as_ushort(b) << 16) | (uint32_t)__bfloat16_as_ushort(a);
}

// ---------------- LayerNorm ----------------
__global__ void ln_kernel(const float* __restrict__ x,
                          const float* __restrict__ g,
                          const float* __restrict__ b,
                          float* __restrict__ out,
                          __nv_bfloat16* __restrict__ oh,
                          __nv_bfloat16* __restrict__ ol) {
    int row = blockIdx.x;
    const float* xr = x + (size_t)row * DD;
    float s = 0.f, s2 = 0.f;
    for (int i = threadIdx.x; i < DD; i += 256) {
        float v = xr[i]; s += v; s2 += v * v;
    }
    for (int o = 16; o; o >>= 1) {
        s  += __shfl_xor_sync(0xffffffffu, s,  o);
        s2 += __shfl_xor_sync(0xffffffffu, s2, o);
    }
    __shared__ float ss[8], ss2[8];
    __shared__ float mu, rs;
    if ((threadIdx.x & 31) == 0) { ss[threadIdx.x >> 5] = s; ss2[threadIdx.x >> 5] = s2; }
    __syncthreads();
    if (threadIdx.x == 0) {
        float t = 0.f, t2 = 0.f;
        for (int i = 0; i < 8; i++) { t += ss[i]; t2 += ss2[i]; }
        float m = t / (float)DD;
        mu = m; rs = rsqrtf(t2 / (float)DD - m * m + 1e-5f);
    }
    __syncthreads();
    float m = mu, r = rs;
    for (int i = threadIdx.x; i < DD; i += 256) {
        float v = (xr[i] - m) * r * g[i] + b[i];
        if (out) out[(size_t)row * DD + i] = v;
        __nv_bfloat16 hh, ll;
        bf16_split(v, hh, ll);
        oh[(size_t)row * DD + i] = hh;
        ol[(size_t)row * DD + i] = ll;
    }
}

// ---------------- streaming weight convert ----------------
__global__ void conv_stream(const float4* __restrict__ in,
                            uint2* __restrict__ oh, uint2* __restrict__ ol, int n4) {
    for (int i = blockIdx.x * blockDim.x + threadIdx.x; i < n4;
         i += gridDim.x * blockDim.x) {
        float4 v = in[i];
        __nv_bfloat16 h0, l0, h1, l1, h2, l2, h3, l3;
        bf16_split(v.x, h0, l0); bf16_split(v.y, h1, l1);
        bf16_split(v.z, h2, l2); bf16_split(v.w, h3, l3);
        oh[i] = make_uint2(pack2(h0, h1), pack2(h2, h3));
        ol[i] = make_uint2(pack2(l0, l1), pack2(l2, l3));
    }
}

__global__ void conv_qkv(const float* __restrict__ in,
                         __nv_bfloat16* __restrict__ oh,
                         __nv_bfloat16* __restrict__ ol) {
    int idx = blockIdx.x * 256 + threadIdx.x;
    int hs4 = idx & 15;
    int d   = (idx >> 4) & 1023;
    int h   = idx >> 14;
    float4 v = *(const float4*)(in + (((size_t)h << 10) + d) * 64 + hs4 * 4);
    __nv_bfloat16 h0, l0, h1, l1, h2, l2, h3, l3;
    bf16_split(v.x, h0, l0); bf16_split(v.y, h1, l1);
    bf16_split(v.z, h2, l2); bf16_split(v.w, h3, l3);
    size_t o = (size_t)d * 3072 + h * 64 + hs4 * 4;
    *(uint2*)(oh + o) = make_uint2(pack2(h0, h1), pack2(h2, h3));
    *(uint2*)(ol + o) = make_uint2(pack2(l0, l1), pack2(l2, l3));
}

// ---------------- HMMA bf16x3 GEMM: 128x256 tile, warp 64x64 ----------------
#define APLANE  10240
#define BPLANE  16896
#define OBH     (2*APLANE)
#define OBL     (2*APLANE + BPLANE)
#define BUFSZ   (2*APLANE + 2*BPLANE)
#define SMEM_BYTES (2*BUFSZ)

template<int MODE>
__global__ void __launch_bounds__(256, 1)
hmma_gemm(const float* __restrict__ bias, const float* __restrict__ resid) {
    constexpr int KD  = (MODE == 3) ? DFF_ : DD;
    constexpr int LDN = (MODE == 0) ? 3 * DD : ((MODE == 2) ? DFF_ : DD);
    constexpr int NST = KD / 32;
    const int n0 = blockIdx.x * 256, m0 = blockIdx.y * 128, e = blockIdx.z;

    int cnt = 1 << 30, base = 0;
    const __nv_bfloat16 *Ah, *Al, *Bh, *Bl;
    if (MODE == 0)      { Ah = g_xn_h;  Al = g_xn_l;  Bh = g_wqkv_h; Bl = g_wqkv_l; }
    else if (MODE == 1) { Ah = g_hd_h;  Al = g_hd_l;  Bh = g_wp_h;   Bl = g_wp_l; }
    else if (MODE == 2) { Ah = g_xn2_h; Al = g_xn2_l; Bh = g_w1_h;   Bl = g_w1_l; }
    else                { Ah = g_h_h;   Al = g_h_l;   Bh = g_w2_h;   Bl = g_w2_l; }
    if (MODE == 2 || MODE == 3) {
        cnt = g_cnt[e];
        if (m0 >= cnt) return;
        base = g_base[e];
        size_t woff = (size_t)e * DD * DFF_;
        Bh += woff; Bl += woff;
    }

    extern __shared__ __align__(16) char smem[];
    const uint32_t sb = smem_u32(smem);
    const int tid = threadIdx.x;
    const int wid = tid >> 5, lane = tid & 31;
    const int wm = wid >> 2, wn = wid & 3;

    const int rloc = tid >> 2, kc = tid & 3;
    int gA0, gA1, vA0 = 1, vA1 = 1;
    {
        int i0 = m0 + rloc, i1 = m0 + rloc + 64;
        if (MODE == 2) {
            vA0 = i0 < cnt; vA1 = i1 < cnt;
            gA0 = vA0 ? g_tok[e * BT + i0] : 0;
            gA1 = vA1 ? g_tok[e * BT + i1] : 0;
        } else if (MODE == 3) {
            vA0 = i0 < cnt; vA1 = i1 < cnt;
            gA0 = base + (vA0 ? i0 : 0);
            gA1 = base + (vA1 ? i1 : 0);
        } else { gA0 = i0; gA1 = i1; }
    }
    const char* pA0h = (const char*)(Ah + (size_t)gA0 * KD) + kc * 16;
    const char* pA0l = (const char*)(Al + (size_t)gA0 * KD) + kc * 16;
    const char* pA1h = (const char*)(Ah + (size_t)gA1 * KD) + kc * 16;
    const char* pA1l = (const char*)(Al + (size_t)gA1 * KD) + kc * 16;
    const uint32_t ad0 = rloc * 80 + kc * 16;
    const uint32_t ad1 = (rloc + 64) * 80 + kc * 16;

    const int brow = tid >> 3, bc = tid & 7;
    const char* pBh = (const char*)(Bh + (size_t)brow * LDN + n0 + bc * 8);
    const char* pBl = (const char*)(Bl + (size_t)brow * LDN + n0 + bc * 8);
    const uint32_t bd0 = brow * 528 + bc * 16;

    const uint32_t aoff = (uint32_t)((lane & 15) * 80 + (lane >> 4) * 16);
    const uint32_t blane = (uint32_t)((((lane >> 3) & 1) * 8 + (lane & 7)) * 528 + (lane >> 4) * 16);

    float c[4][8][4];
#pragma unroll
    for (int i = 0; i < 4; i++)
#pragma unroll
        for (int j = 0; j < 8; j++)
#pragma unroll
            for (int q = 0; q < 4; q++) c[i][j][q] = 0.f;

    auto issue = [&](int s) {
        const uint32_t bb = sb + (uint32_t)(s & 1) * BUFSZ;
        const size_t ao = (size_t)s * 64;
        const size_t bo = (size_t)s * 32 * LDN * 2;
        cpa16(bb + ad0,          pA0h + ao, vA0);
        cpa16(bb + ad1,          pA1h + ao, vA1);
        cpa16(bb + APLANE + ad0, pA0l + ao, vA0);
        cpa16(bb + APLANE + ad1, pA1l + ao, vA1);
#pragma unroll
        for (int j = 0; j < 4; j++) {
            cpa16(bb + OBH + bd0 + j * 128, pBh + bo + j * 128, 1);
            cpa16(bb + OBL + bd0 + j * 128, pBl + bo + j * 128, 1);
        }
        asm volatile("cp.async.commit_group;" ::: "memory");
    };

    issue(0);
#pragma unroll 1
    for (int s = 0; s < NST; s++) {
        if (s + 1 < NST) {
            issue(s + 1);
            asm volatile("cp.async.wait_group 1;" ::: "memory");
        } else {
            asm volatile("cp.async.wait_group 0;" ::: "memory");
        }
        __syncthreads();

        const uint32_t bb = sb + (uint32_t)(s & 1) * BUFSZ;
        const uint32_t abase  = bb + (uint32_t)(wm * 64) * 80 + aoff;
        const uint32_t bbaseH = bb + OBH + blane + (uint32_t)wn * 128;
        const uint32_t bbaseL = bbaseH + BPLANE;
#pragma unroll
        for (int kk = 0; kk < 2; kk++) {
            const uint32_t kbA = kk * 32;
            const uint32_t kbB = kk * 8448;
            uint32_t aH[4][4], aL[4][4], bH[8][2], bL[8][2];
#pragma unroll
            for (int mt = 0; mt < 4; mt++) {
                ldsm4(aH[mt], abase + mt * (16 * 80) + kbA);
                ldsm4(aL[mt], abase + APLANE + mt * (16 * 80) + kbA);
            }
#pragma unroll
            for (int nn = 0; nn < 4; nn++) {
                uint32_t r[4];
                ldsm4t(r, bbaseH + kbB + nn * 32);
                bH[2 * nn][0] = r[0]; bH[2 * nn][1] = r[1];
                bH[2 * nn + 1][0] = r[2]; bH[2 * nn + 1][1] = r[3];
                ldsm4t(r, bbaseL + kbB + nn * 32);
                bL[2 * nn][0] = r[0]; bL[2 * nn][1] = r[1];
                bL[2 * nn + 1][0] = r[2]; bL[2 * nn + 1][1] = r[3];
            }
#pragma unroll
            for (int mt = 0; mt < 4; mt++)
#pragma unroll
                for (int nt = 0; nt < 8; nt++) {
                    mma16816(c[mt][nt], aH[mt], bH[nt]);
                    mma16816(c[mt][nt], aH[mt], bL[nt]);
                    mma16816(c[mt][nt], aL[mt], bH[nt]);
                }
        }
        __syncthreads();
    }

    const int gid = lane >> 2, tig = lane & 3;
#pragma unroll
    for (int mt = 0; mt < 4; mt++) {
#pragma unroll
        for (int nt = 0; nt < 8; nt++) {
            const int ng = n0 + wn * 64 + nt * 8 + tig * 2;
#pragma unroll
            for (int h = 0; h < 2; h++) {
                const int ml = wm * 64 + mt * 16 + gid + 8 * h;
                float v0 = c[mt][nt][2 * h], v1 = c[mt][nt][2 * h + 1];
                if (MODE == 0) {
                    const int m = m0 + ml;
                    const int which = ng >> 10, hh = (ng >> 6) & 15, hs = ng & 63;
                    const int bb_ = m >> 10, t = m & 1023;
                    float sc = (which == 0) ? 0.03125f : 1.0f;
                    __nv_bfloat16 hA, lA, hB, lB;
                    bf16_split(v0 * sc, hA, lA);
                    bf16_split(v1 * sc, hB, lB);
                    __nv_bfloat16 *ph_, *pl_;
                    if (which == 0)      { ph_ = g_qh; pl_ = g_ql; }
                    else if (which == 1) { ph_ = g_kh; pl_ = g_kl; }
                    else                 { ph_ = g_vh; pl_ = g_vl; }
                    size_t idx = (((size_t)(bb_ * HH + hh)) * TT + t) * HSZ + hs;
                    *(uint32_t*)&ph_[idx] = pack2(hA, hB);
                    *(uint32_t*)&pl_[idx] = pack2(lA, lB);
                } else if (MODE == 1) {
                    const int m = m0 + ml;
                    const size_t o = (size_t)m * DD + ng;
                    float2 rr = *(const float2*)&resid[o];
                    *(float2*)&g_x2[o] = make_float2(v0 + bias[ng] + rr.x,
                                                     v1 + bias[ng + 1] + rr.y);
                } else if (MODE == 2) {
                    const int i = m0 + ml;
                    if (i < cnt) {
                        float a0 = fmaxf(v0 + bias[(size_t)e * DFF_ + ng], 0.f);
                        float a1 = fmaxf(v1 + bias[(size_t)e * DFF_ + ng + 1], 0.f);
                        __nv_bfloat16 h0, l0, h1, l1;
                        bf16_split(a0, h0, l0);
                        bf16_split(a1, h1, l1);
                        size_t idx = (size_t)(base + i) * DFF_ + ng;
                        *(uint32_t*)&g_h_h[idx] = pack2(h0, h1);
                        *(uint32_t*)&g_h_l[idx] = pack2(l0, l1);
                    }
                } else {
                    const int i = m0 + ml;
                    if (i < cnt) {
                        *(float2*)&g_eo[(size_t)(base + i) * DD + ng] =
                            make_float2(v0 + bias[(size_t)e * DD + ng],
                                        v1 + bias[(size_t)e * DD + ng + 1]);
                    }
                }
            }
        }
    }
}

// ---------------- HMMA flash attention: 64q x 64k tiles, bf16x3 ----------------
#define ASTR 144
#define AQH 0
#define AQL 9216
#define AKH 18432
#define AKL 27648
#define AVH 36864
#define AVL 46080
#define ATT_SMEM 55296

__global__ void __launch_bounds__(128, 1) attn_kernel() {
    extern __shared__ __align__(16) char sma[];
    const uint32_t sb = smem_u32(sma);
    const int tid = threadIdx.x;
    const int wid = tid >> 5, lane = tid & 31;
    const int bh = blockIdx.x, qt = blockIdx.y;

    const __nv_bfloat16* qh = g_qh + (size_t)bh * TT * HSZ + (size_t)qt * 64 * HSZ;
    const __nv_bfloat16* ql = g_ql + (size_t)bh * TT * HSZ + (size_t)qt * 64 * HSZ;
    const __nv_bfloat16* kh0 = g_kh + (size_t)bh * TT * HSZ;
    const __nv_bfloat16* kl0 = g_kl + (size_t)bh * TT * HSZ;
    const __nv_bfloat16* vh0 = g_vh + (size_t)bh * TT * HSZ;
    const __nv_bfloat16* vl0 = g_vl + (size_t)bh * TT * HSZ;

    // load Q planes (row = tid>>1, 64B half-row per thread)
    {
        const int row = tid >> 1, cb = (tid & 1) * 64;
        const char* sh = (const char*)qh + row * 128 + cb;
        const char* sl = (const char*)ql + row * 128 + cb;
#pragma unroll
        for (int j = 0; j < 4; j++) {
            *(uint4*)(sma + AQH + row * ASTR + cb + j * 16) = *(const uint4*)(sh + j * 16);
            *(uint4*)(sma + AQL + row * ASTR + cb + j * 16) = *(const uint4*)(sl + j * 16);
        }
    }

    const uint32_t aoff = (uint32_t)(wid * 16 * ASTR + (lane & 15) * ASTR + (lane >> 4) * 16);
    const uint32_t kbo  = (uint32_t)(((lane & 7) + ((lane >> 4) << 3)) * ASTR + (((lane >> 3) & 1) << 4));
    const uint32_t vbo  = (uint32_t)(((((lane >> 3) & 1) << 3) + (lane & 7)) * ASTR + ((lane >> 4) << 4));

    float O[8][4];
#pragma unroll
    for (int nt = 0; nt < 8; nt++)
#pragma unroll
        for (int q = 0; q < 4; q++) O[nt][q] = 0.f;
    float m0 = -1e30f, m1 = -1e30f, l0 = 0.f, l1 = 0.f;

    for (int kt = 0; kt < 16; kt++) {
        __syncthreads();   // previous iteration's reads complete (and Q stores on kt=0)
        {
            const int row = tid >> 1, cb = (tid & 1) * 64;
            const size_t go = (size_t)kt * 64 * HSZ + row * HSZ + (cb >> 1);
#pragma unroll
            for (int j = 0; j < 4; j++) {
                *(uint4*)(sma + AKH + row * ASTR + cb + j * 16) = *(const uint4*)((const char*)(kh0 + go) + j * 16);
                *(uint4*)(sma + AKL + row * ASTR + cb + j * 16) = *(const uint4*)((const char*)(kl0 + go) + j * 16);
                *(uint4*)(sma + AVH + row * ASTR + cb + j * 16) = *(const uint4*)((const char*)(vh0 + go) + j * 16);
                *(uint4*)(sma + AVL + row * ASTR + cb + j * 16) = *(const uint4*)((const char*)(vl0 + go) + j * 16);
            }
        }
        __syncthreads();

        // ---- S = Q K^T (bf16x3) ----
        float S[8][4];
#pragma unroll
        for (int nt = 0; nt < 8; nt++)
#pragma unroll
            for (int q = 0; q < 4; q++) S[nt][q] = 0.f;
#pragma unroll
        for (int kc = 0; kc < 4; kc++) {
            uint32_t aH[4], aL[4], bKh[8][2], bKl[8][2];
            ldsm4(aH, sb + AQH + aoff + kc * 32);
            ldsm4(aL, sb + AQL + aoff + kc * 32);
#pragma unroll
            for (int nn = 0; nn < 4; nn++) {
                uint32_t r[4];
                ldsm4(r, sb + AKH + kbo + nn * (16 * ASTR) + kc * 32);
                bKh[2 * nn][0] = r[0]; bKh[2 * nn][1] = r[1];
                bKh[2 * nn + 1][0] = r[2]; bKh[2 * nn + 1][1] = r[3];
                ldsm4(r, sb + AKL + kbo + nn * (16 * ASTR) + kc * 32);
                bKl[2 * nn][0] = r[0]; bKl[2 * nn][1] = r[1];
                bKl[2 * nn + 1][0] = r[2]; bKl[2 * nn + 1][1] = r[3];
            }
#pragma unroll
            for (int nt = 0; nt < 8; nt++) {
                mma16816(S[nt], aH, bKh[nt]);
                mma16816(S[nt], aH, bKl[nt]);
                mma16816(S[nt], aL, bKh[nt]);
            }
        }

        // ---- online softmax ----
        float mx0 = -1e30f, mx1 = -1e30f;
#pragma unroll
        for (int nt = 0; nt < 8; nt++) {
            mx0 = fmaxf(mx0, fmaxf(S[nt][0], S[nt][1]));
            mx1 = fmaxf(mx1, fmaxf(S[nt][2], S[nt][3]));
        }
        mx0 = fmaxf(mx0, __shfl_xor_sync(0xffffffffu, mx0, 1));
        mx0 = fmaxf(mx0, __shfl_xor_sync(0xffffffffu, mx0, 2));
        mx1 = fmaxf(mx1, __shfl_xor_sync(0xffffffffu, mx1, 1));
        mx1 = fmaxf(mx1, __shfl_xor_sync(0xffffffffu, mx1, 2));
        float mn0 = fmaxf(m0, mx0), mn1 = fmaxf(m1, mx1);
        float al0 = __expf(m0 - mn0), al1 = __expf(m1 - mn1);
        float rs0 = 0.f, rs1 = 0.f;
        uint32_t ph[8][2], pl[8][2];
#pragma unroll
        for (int nt = 0; nt < 8; nt++) {
            float p0 = __expf(S[nt][0] - mn0), p1 = __expf(S[nt][1] - mn0);
            float p2 = __expf(S[nt][2] - mn1), p3 = __expf(S[nt][3] - mn1);
            rs0 += p0 + p1; rs1 += p2 + p3;
            __nv_bfloat16 h0, q0, h1, q1, h2, q2, h3, q3;
            bf16_split(p0, h0, q0); bf16_split(p1, h1, q1);
            bf16_split(p2, h2, q2); bf16_split(p3, h3, q3);
            ph[nt][0] = pack2(h0, h1); pl[nt][0] = pack2(q0, q1);
            ph[nt][1] = pack2(h2, h3); pl[nt][1] = pack2(q2, q3);
        }
        rs0 += __shfl_xor_sync(0xffffffffu, rs0, 1);
        rs0 += __shfl_xor_sync(0xffffffffu, rs0, 2);
        rs1 += __shfl_xor_sync(0xffffffffu, rs1, 1);
        rs1 += __shfl_xor_sync(0xffffffffu, rs1, 2);
        l0 = l0 * al0 + rs0; l1 = l1 * al1 + rs1;
        m0 = mn0; m1 = mn1;
#pragma unroll
        for (int nt = 0; nt < 8; nt++) {
            O[nt][0] *= al0; O[nt][1] *= al0;
            O[nt][2] *= al1; O[nt][3] *= al1;
        }

        // ---- O += P V (bf16x3) ----
#pragma unroll
        for (int kc = 0; kc < 4; kc++) {
            uint32_t aPh[4] = {ph[2 * kc][0], ph[2 * kc][1], ph[2 * kc + 1][0], ph[2 * kc + 1][1]};
            uint32_t aPl[4] = {pl[2 * kc][0], pl[2 * kc][1], pl[2 * kc + 1][0], pl[2 * kc + 1][1]};
            uint32_t bVh[8][2], bVl[8][2];
#pragma unroll
            for (int nn = 0; nn < 4; nn++) {
                uint32_t r[4];
                ldsm4t(r, sb + AVH + vbo + kc * (16 * ASTR) + nn * 32);
                bVh[2 * nn][0] = r[0]; bVh[2 * nn][1] = r[1];
                bVh[2 * nn + 1][0] = r[2]; bVh[2 * nn + 1][1] = r[3];
                ldsm4t(r, sb + AVL + vbo + kc * (16 * ASTR) + nn * 32);
                bVl[2 * nn][0] = r[0]; bVl[2 * nn][1] = r[1];
                bVl[2 * nn + 1][0] = r[2]; bVl[2 * nn + 1][1] = r[3];
            }
#pragma unroll
            for (int nt = 0; nt < 8; nt++) {
                mma16816(O[nt], aPh, bVh[nt]);
                mma16816(O[nt], aPl, bVh[nt]);
                mma16816(O[nt], aPh, bVl[nt]);
            }
        }
    }

    // ---- epilogue: O / l -> g_hd hi/lo ----
    const int b = bh >> 4, head = bh & 15;
    const float inv0 = 1.f / l0, inv1 = 1.f / l1;
    const int r0 = qt * 64 + wid * 16 + (lane >> 2);
#pragma unroll
    for (int nt = 0; nt < 8; nt++) {
        const int col = head * 64 + nt * 8 + (lane & 3) * 2;
#pragma unroll
        for (int h = 0; h < 2; h++) {
            const int t = r0 + 8 * h;
            float inv = h ? inv1 : inv0;
            float v0 = O[nt][2 * h] * inv, v1 = O[nt][2 * h + 1] * inv;
            __nv_bfloat16 hA, lA, hB, lB;
            bf16_split(v0, hA, lA); bf16_split(v1, hB, lB);
            size_t idx = ((size_t)(b * TT + t)) * DD + col;
            *(uint32_t*)&g_hd_h[idx] = pack2(hA, hB);
            *(uint32_t*)&g_hd_l[idx] = pack2(lA, lB);
        }
    }
}

// ---------------- routing ----------------
__global__ void zero_cnt_kernel() {
    if (threadIdx.x < EE) g_cnt[threadIdx.x] = 0;
}

__global__ void route_kernel(const float* __restrict__ noise,
                             const float* __restrict__ w_route,
                             const float* __restrict__ b_route,
                             const float* __restrict__ w_noise,
                             const float* __restrict__ b_noise) {
    int tok = blockIdx.x;
    __shared__ float xs[DD];
    __shared__ float dots[16];
    for (int i = threadIdx.x; i < DD; i += 256)
        xs[i] = g_xn2[(size_t)tok * DD + i];
    __syncthreads();

    int j = threadIdx.x >> 4, lane = threadIdx.x & 15;
    const float* W = (j < 8) ? w_route : w_noise;
    int col = j & 7;
    float s = 0.f;
    for (int d = lane; d < DD; d += 16) s += xs[d] * W[(size_t)d * EE + col];
    for (int o = 8; o; o >>= 1) s += __shfl_down_sync(0xffffffffu, s, o, 16);
    if (lane == 0) dots[j] = s + ((j < 8) ? b_route[col] : b_noise[col]);
    __syncthreads();

    if (threadIdx.x == 0) {
        float noisy[EE];
        for (int ee = 0; ee < EE; ee++) {
            float nl = dots[8 + ee];
            float sp = (nl > 20.f) ? nl : log1pf(expf(nl));
            noisy[ee] = dots[ee] + noise[(size_t)tok * EE + ee] * sp;
        }
        int i1 = 0;
        for (int ee = 1; ee < EE; ee++) if (noisy[ee] > noisy[i1]) i1 = ee;
        int i2 = -1;
        for (int ee = 0; ee < EE; ee++) {
            if (ee == i1) continue;
            if (i2 < 0 || noisy[ee] > noisy[i2]) i2 = ee;
        }
        float e2 = expf(noisy[i2] - noisy[i1]);
        float inv = 1.f / (1.f + e2);
        float p1 = inv, p2 = e2 * inv;
        int pos1 = atomicAdd(&g_cnt[i1], 1);
        g_tok[i1 * BT + pos1] = tok;
        int pos2 = atomicAdd(&g_cnt[i2], 1);
        g_tok[i2 * BT + pos2] = tok;
        g_texp[tok * 2] = i1; g_tpos[tok * 2] = pos1; g_tgate[tok * 2] = p1;
        g_texp[tok * 2 + 1] = i2; g_tpos[tok * 2 + 1] = pos2; g_tgate[tok * 2 + 1] = p2;
    }
}

__global__ void scan_kernel() {
    if (threadIdx.x == 0) {
        int b = 0;
        for (int e = 0; e < EE; e++) { g_base[e] = b; b += g_cnt[e]; }
    }
}

// ---------------- final combine ----------------
__global__ void combine_kernel(float* __restrict__ out) {
    int tok = blockIdx.x;
    int e1 = g_texp[tok * 2], e2 = g_texp[tok * 2 + 1];
    float gt1 = g_tgate[tok * 2], gt2 = g_tgate[tok * 2 + 1];
    size_t s1 = (size_t)(g_base[e1] + g_tpos[tok * 2]) * DD;
    size_t s2 = (size_t)(g_base[e2] + g_tpos[tok * 2 + 1]) * DD;
    size_t o = (size_t)tok * DD;
    for (int i = threadIdx.x * 4; i < DD; i += 256 * 4) {
        float4 a = *(float4*)&g_xn2[o + i];
        float4 u = *(float4*)&g_eo[s1 + i];
        float4 w = *(float4*)&g_eo[s2 + i];
        float4 r = make_float4(a.x + gt1 * u.x + gt2 * w.x,
                               a.y + gt1 * u.y + gt2 * w.y,
                               a.z + gt1 * u.z + gt2 * w.z,
                               a.w + gt1 * u.w + gt2 * w.w);
        *(float4*)&out[o + i] = r;
    }
}

// ---------------- launch ----------------
extern "C" void kernel_launch(void* const* d_in, const int* in_sizes, int n_in,
                              void* d_out, int out_size) {
    const float* x       = (const float*)d_in[0];
    const float* noise   = (const float*)d_in[1];
    const float* ln1_g   = (const float*)d_in[2];
    const float* ln1_b   = (const float*)d_in[3];
    const float* wq      = (const float*)d_in[4];
    const float* wk      = (const float*)d_in[5];
    const float* wv      = (const float*)d_in[6];
    const float* w_proj  = (const float*)d_in[7];
    const float* b_proj  = (const float*)d_in[8];
    const float* ln2_g   = (const float*)d_in[9];
    const float* ln2_b   = (const float*)d_in[10];
    const float* w_route = (const float*)d_in[11];
    const float* b_route = (const float*)d_in[12];
    const float* w_noise = (const float*)d_in[13];
    const float* b_noise = (const float*)d_in[14];
    const float* w1      = (const float*)d_in[15];
    const float* b1      = (const float*)d_in[16];
    const float* w2      = (const float*)d_in[17];
    const float* b2      = (const float*)d_in[18];
    float* out = (float*)d_out;

    cudaFuncSetAttribute(hmma_gemm<0>, cudaFuncAttributeMaxDynamicSharedMemorySize, SMEM_BYTES);
    cudaFuncSetAttribute(hmma_gemm<1>, cudaFuncAttributeMaxDynamicSharedMemorySize, SMEM_BYTES);
    cudaFuncSetAttribute(hmma_gemm<2>, cudaFuncAttributeMaxDynamicSharedMemorySize, SMEM_BYTES);
    cudaFuncSetAttribute(hmma_gemm<3>, cudaFuncAttributeMaxDynamicSharedMemorySize, SMEM_BYTES);
    cudaFuncSetAttribute(attn_kernel, cudaFuncAttributeMaxDynamicSharedMemorySize, ATT_SMEM);

    __nv_bfloat16 *xn_h, *xn_l, *xn2_h, *xn2_l;
    __nv_bfloat16 *wqkv_h, *wqkv_l, *wp_h, *wp_l, *w1_h, *w1_l, *w2_h, *w2_l;
    float *x2, *xn2;
    cudaGetSymbolAddress((void**)&xn_h,  g_xn_h);
    cudaGetSymbolAddress((void**)&xn_l,  g_xn_l);
    cudaGetSymbolAddress((void**)&xn2_h, g_xn2_h);
    cudaGetSymbolAddress((void**)&xn2_l, g_xn2_l);
    cudaGetSymbolAddress((void**)&wqkv_h, g_wqkv_h);
    cudaGetSymbolAddress((void**)&wqkv_l, g_wqkv_l);
    cudaGetSymbolAddress((void**)&wp_h, g_wp_h);
    cudaGetSymbolAddress((void**)&wp_l, g_wp_l);
    cudaGetSymbolAddress((void**)&w1_h, g_w1_h);
    cudaGetSymbolAddress((void**)&w1_l, g_w1_l);
    cudaGetSymbolAddress((void**)&w2_h, g_w2_h);
    cudaGetSymbolAddress((void**)&w2_l, g_w2_l);
    cudaGetSymbolAddress((void**)&x2,   g_x2);
    cudaGetSymbolAddress((void**)&xn2,  g_xn2);

    // weight prep
    conv_qkv<<<1024, 256>>>(wq, wqkv_h,        wqkv_l);
    conv_qkv<<<1024, 256>>>(wk, wqkv_h + 1024, wqkv_l + 1024);
    conv_qkv<<<1024, 256>>>(wv, wqkv_h + 2048, wqkv_l + 2048);
    conv_stream<<<1024, 256>>>((const float4*)w_proj, (uint2*)wp_h, (uint2*)wp_l, DD * DD / 4);
    conv_stream<<<4096, 256>>>((const float4*)w1, (uint2*)w1_h, (uint2*)w1_l, EE * DD * DFF_ / 4);
    conv_stream<<<4096, 256>>>((const float4*)w2, (uint2*)w2_h, (uint2*)w2_l, EE * DFF_ * DD / 4);

    // LN1
    ln_kernel<<<BT, 256>>>(x, ln1_g, ln1_b, nullptr, xn_h, xn_l);

    // fused QKV (N = 3072) -> q/k/v bf16 hi/lo planes (q pre-scaled by 1/32)
    hmma_gemm<0><<<dim3(12, 32, 1), 256, SMEM_BYTES>>>(nullptr, nullptr);

    // HMMA flash attention -> g_hd hi/lo
    attn_kernel<<<dim3(BB * HH, TT / 64), 128, ATT_SMEM>>>();

    // out proj + bias + residual -> g_x2
    hmma_gemm<1><<<dim3(4, 32, 1), 256, SMEM_BYTES>>>(b_proj, x);

    // LN2
    ln_kernel<<<BT, 256>>>(x2, ln2_g, ln2_b, xn2, xn2_h, xn2_l);

    // routing
    zero_cnt_kernel<<<1, 32>>>();
    route_kernel<<<BT, 256>>>(noise, w_route, b_route, w_noise, b_noise);
    scan_kernel<<<1, 32>>>();

    // MoE expert GEMMs
    hmma_gemm<2><<<dim3(16, 32, EE), 256, SMEM_BYTES>>>(b1, nullptr);
    hmma_gemm<3><<<dim3(4, 32, EE), 256, SMEM_BYTES>>>(b2, nullptr);

    // combine
    combine_kernel<<<BT, 256>>>(out);
}

// round 11
// speedup vs baseline: 1.2038x; 1.2038x over previous
#include <cuda_runtime.h>
#include <cuda_bf16.h>
#include <math.h>
#include <stdint.h>

#define BB   4
#define TT   1024
#define DD   1024
#define HH   16
#define HSZ  64
#define EE   8
#define DFF_ 4096
#define BT   4096
#define NSLOT (BT*2)

// ---------------- device scratch ----------------
__device__ float g_q  [BT*DD];
__device__ float g_k  [BT*DD];
__device__ float g_v  [BT*DD];
__device__ float g_x2 [BT*DD];
__device__ float g_xn2[BT*DD];
__device__ float g_eo [NSLOT*DD];

__device__ __align__(16) __nv_bfloat16 g_xn_h [BT*DD], g_xn_l [BT*DD];
__device__ __align__(16) __nv_bfloat16 g_hd_h [BT*DD], g_hd_l [BT*DD];
__device__ __align__(16) __nv_bfloat16 g_xn2_h[BT*DD], g_xn2_l[BT*DD];
__device__ __align__(16) __nv_bfloat16 g_h_h  [NSLOT*DFF_], g_h_l[NSLOT*DFF_];
__device__ __align__(16) __nv_bfloat16 g_wqkv_h[DD*3*DD], g_wqkv_l[DD*3*DD];   // [K][N=3072]
__device__ __align__(16) __nv_bfloat16 g_wp_h  [DD*DD],   g_wp_l  [DD*DD];     // [K][N]
__device__ __align__(16) __nv_bfloat16 g_w1_h[EE*DD*DFF_], g_w1_l[EE*DD*DFF_];
__device__ __align__(16) __nv_bfloat16 g_w2_h[EE*DFF_*DD], g_w2_l[EE*DFF_*DD];

__device__ int   g_cnt [EE];
__device__ int   g_base[EE];
__device__ int   g_tok [EE*BT];
__device__ int   g_texp[BT*2];
__device__ int   g_tpos[BT*2];
__device__ float g_tgate[BT*2];

// ---------------- helpers ----------------
__device__ __forceinline__ uint32_t smem_u32(const void* p) {
    uint32_t a;
    asm("{ .reg .u64 t; cvta.to.shared.u64 t, %1; cvt.u32.u64 %0, t; }" : "=r"(a) : "l"(p));
    return a;
}
__device__ __forceinline__ void cpa16(uint32_t dst, const void* src, int valid) {
    asm volatile("cp.async.cg.shared.global [%0], [%1], 16, %2;"
                 :: "r"(dst), "l"(src), "r"(valid ? 16 : 0) : "memory");
}
__device__ __forceinline__ void ldsm4(uint32_t* r, uint32_t addr) {
    asm volatile("ldmatrix.sync.aligned.m8n8.x4.shared.b16 {%0,%1,%2,%3}, [%4];"
                 : "=r"(r[0]), "=r"(r[1]), "=r"(r[2]), "=r"(r[3]) : "r"(addr));
}
__device__ __forceinline__ void ldsm4t(uint32_t* r, uint32_t addr) {
    asm volatile("ldmatrix.sync.aligned.m8n8.x4.trans.shared.b16 {%0,%1,%2,%3}, [%4];"
                 : "=r"(r[0]), "=r"(r[1]), "=r"(r[2]), "=r"(r[3]) : "r"(addr));
}
__device__ __forceinline__ void mma16816(float* c, const uint32_t* a, const uint32_t* b) {
    asm volatile(
        "mma.sync.aligned.m16n8k16.row.col.f32.bf16.bf16.f32 "
        "{%0,%1,%2,%3},{%4,%5,%6,%7},{%8,%9},{%0,%1,%2,%3};"
        : "+f"(c[0]), "+f"(c[1]), "+f"(c[2]), "+f"(c[3])
        : "r"(a[0]), "r"(a[1]), "r"(a[2]), "r"(a[3]), "r"(b[0]), "r"(b[1]));
}
__device__ __forceinline__ void bf16_split(float v, __nv_bfloat16& h, __nv_bfloat16& l) {
    h = __float2bfloat16(v);
    l = __float2bfloat16(v - __bfloat162float(h));
}
__device__ __forceinline__ uint32_t pack2(__nv_bfloat16 a, __nv_bfloat16 b) {
    return ((uint32_t)__bfloat16_as_ushort(b) << 16) | (uint32_t)__bfloat16_as_ushort(a);
}

// ---------------- LayerNorm (+ bf16 hi/lo split outputs) ----------------
__global__ void ln_kernel(const float* __restrict__ x,
                          const float* __restrict__ g,
                          const float* __restrict__ b,
                          float* __restrict__ out,
                          __nv_bfloat16* __restrict__ oh,
                          __nv_bfloat16* __restrict__ ol) {
    int row = blockIdx.x;
    const float* xr = x + (size_t)row * DD;
    float s = 0.f, s2 = 0.f;
    for (int i = threadIdx.x; i < DD; i += 256) {
        float v = xr[i]; s += v; s2 += v * v;
    }
    for (int o = 16; o; o >>= 1) {
        s  += __shfl_xor_sync(0xffffffffu, s,  o);
        s2 += __shfl_xor_sync(0xffffffffu, s2, o);
    }
    __shared__ float ss[8], ss2[8];
    __shared__ float mu, rs;
    if ((threadIdx.x & 31) == 0) { ss[threadIdx.x >> 5] = s; ss2[threadIdx.x >> 5] = s2; }
    __syncthreads();
    if (threadIdx.x == 0) {
        float t = 0.f, t2 = 0.f;
        for (int i = 0; i < 8; i++) { t += ss[i]; t2 += ss2[i]; }
        float m = t / (float)DD;
        mu = m; rs = rsqrtf(t2 / (float)DD - m * m + 1e-5f);
    }
    __syncthreads();
    float m = mu, r = rs;
    for (int i = threadIdx.x; i < DD; i += 256) {
        float v = (xr[i] - m) * r * g[i] + b[i];
        if (out) out[(size_t)row * DD + i] = v;
        __nv_bfloat16 hh, ll;
        bf16_split(v, hh, ll);
        oh[(size_t)row * DD + i] = hh;
        ol[(size_t)row * DD + i] = ll;
    }
}

// ---------------- streaming weight convert (4-way MLP) ----------------
__global__ void conv_stream(const float4* __restrict__ in,
                            uint2* __restrict__ oh, uint2* __restrict__ ol, int n4) {
    const int stride = gridDim.x * blockDim.x;
    int i = blockIdx.x * blockDim.x + threadIdx.x;
    for (; i + 3 * stride < n4; i += 4 * stride) {
        float4 v0 = in[i];
        float4 v1 = in[i + stride];
        float4 v2 = in[i + 2 * stride];
        float4 v3 = in[i + 3 * stride];
#pragma unroll
        for (int u = 0; u < 4; u++) {
            float4 v = (u == 0) ? v0 : ((u == 1) ? v1 : ((u == 2) ? v2 : v3));
            int ii = i + u * stride;
            __nv_bfloat16 h0, l0, h1, l1, h2, l2, h3, l3;
            bf16_split(v.x, h0, l0); bf16_split(v.y, h1, l1);
            bf16_split(v.z, h2, l2); bf16_split(v.w, h3, l3);
            oh[ii] = make_uint2(pack2(h0, h1), pack2(h2, h3));
            ol[ii] = make_uint2(pack2(l0, l1), pack2(l2, l3));
        }
    }
    for (; i < n4; i += stride) {
        float4 v = in[i];
        __nv_bfloat16 h0, l0, h1, l1, h2, l2, h3, l3;
        bf16_split(v.x, h0, l0); bf16_split(v.y, h1, l1);
        bf16_split(v.z, h2, l2); bf16_split(v.w, h3, l3);
        oh[i] = make_uint2(pack2(h0, h1), pack2(h2, h3));
        ol[i] = make_uint2(pack2(l0, l1), pack2(l2, l3));
    }
}

// QKV: [H][D][HS] fp32 -> rows d of [1024][3072]
__global__ void conv_qkv(const float* __restrict__ in,
                         __nv_bfloat16* __restrict__ oh,
                         __nv_bfloat16* __restrict__ ol) {
    int idx = blockIdx.x * 256 + threadIdx.x;
    int hs4 = idx & 15;
    int d   = (idx >> 4) & 1023;
    int h   = idx >> 14;
    float4 v = *(const float4*)(in + (((size_t)h << 10) + d) * 64 + hs4 * 4);
    __nv_bfloat16 h0, l0, h1, l1, h2, l2, h3, l3;
    bf16_split(v.x, h0, l0); bf16_split(v.y, h1, l1);
    bf16_split(v.z, h2, l2); bf16_split(v.w, h3, l3);
    size_t o = (size_t)d * 3072 + h * 64 + hs4 * 4;
    *(uint2*)(oh + o) = make_uint2(pack2(h0, h1), pack2(h2, h3));
    *(uint2*)(ol + o) = make_uint2(pack2(l0, l1), pack2(l2, l3));
}

// ---------------- HMMA bf16x3 GEMM: 128x256 tile, warp 64x64 ----------------
#define APLANE  10240
#define BPLANE  16896
#define OBH     (2*APLANE)
#define OBL     (2*APLANE + BPLANE)
#define BUFSZ   (2*APLANE + 2*BPLANE)
#define SMEM_BYTES (2*BUFSZ)

template<int MODE>
__global__ void __launch_bounds__(256, 1)
hmma_gemm(const float* __restrict__ bias, const float* __restrict__ resid) {
    constexpr int KD  = (MODE == 3) ? DFF_ : DD;
    constexpr int LDN = (MODE == 0) ? 3 * DD : ((MODE == 2) ? DFF_ : DD);
    constexpr int NST = KD / 32;
    const int n0 = blockIdx.x * 256, m0 = blockIdx.y * 128, e = blockIdx.z;

    int cnt = 1 << 30, base = 0;
    const __nv_bfloat16 *Ah, *Al, *Bh, *Bl;
    if (MODE == 0)      { Ah = g_xn_h;  Al = g_xn_l;  Bh = g_wqkv_h; Bl = g_wqkv_l; }
    else if (MODE == 1) { Ah = g_hd_h;  Al = g_hd_l;  Bh = g_wp_h;   Bl = g_wp_l; }
    else if (MODE == 2) { Ah = g_xn2_h; Al = g_xn2_l; Bh = g_w1_h;   Bl = g_w1_l; }
    else                { Ah = g_h_h;   Al = g_h_l;   Bh = g_w2_h;   Bl = g_w2_l; }
    if (MODE == 2 || MODE == 3) {
        cnt = g_cnt[e];
        if (m0 >= cnt) return;
        base = g_base[e];
        size_t woff = (size_t)e * DD * DFF_;
        Bh += woff; Bl += woff;
    }

    extern __shared__ __align__(16) char smem[];
    const uint32_t sb = smem_u32(smem);
    const int tid = threadIdx.x;
    const int wid = tid >> 5, lane = tid & 31;
    const int wm = wid >> 2, wn = wid & 3;

    const int rloc = tid >> 2, kc = tid & 3;
    int gA0, gA1, vA0 = 1, vA1 = 1;
    {
        int i0 = m0 + rloc, i1 = m0 + rloc + 64;
        if (MODE == 2) {
            vA0 = i0 < cnt; vA1 = i1 < cnt;
            gA0 = vA0 ? g_tok[e * BT + i0] : 0;
            gA1 = vA1 ? g_tok[e * BT + i1] : 0;
        } else if (MODE == 3) {
            vA0 = i0 < cnt; vA1 = i1 < cnt;
            gA0 = base + (vA0 ? i0 : 0);
            gA1 = base + (vA1 ? i1 : 0);
        } else { gA0 = i0; gA1 = i1; }
    }
    const char* pA0h = (const char*)(Ah + (size_t)gA0 * KD) + kc * 16;
    const char* pA0l = (const char*)(Al + (size_t)gA0 * KD) + kc * 16;
    const char* pA1h = (const char*)(Ah + (size_t)gA1 * KD) + kc * 16;
    const char* pA1l = (const char*)(Al + (size_t)gA1 * KD) + kc * 16;
    const uint32_t ad0 = rloc * 80 + kc * 16;
    const uint32_t ad1 = (rloc + 64) * 80 + kc * 16;

    const int brow = tid >> 3, bc = tid & 7;
    const char* pBh = (const char*)(Bh + (size_t)brow * LDN + n0 + bc * 8);
    const char* pBl = (const char*)(Bl + (size_t)brow * LDN + n0 + bc * 8);
    const uint32_t bd0 = brow * 528 + bc * 16;

    const uint32_t aoff = (uint32_t)((lane & 15) * 80 + (lane >> 4) * 16);
    const uint32_t blane = (uint32_t)((((lane >> 3) & 1) * 8 + (lane & 7)) * 528 + (lane >> 4) * 16);

    float c[4][8][4];
#pragma unroll
    for (int i = 0; i < 4; i++)
#pragma unroll
        for (int j = 0; j < 8; j++)
#pragma unroll
            for (int q = 0; q < 4; q++) c[i][j][q] = 0.f;

    auto issue = [&](int s) {
        const uint32_t bb = sb + (uint32_t)(s & 1) * BUFSZ;
        const size_t ao = (size_t)s * 64;
        const size_t bo = (size_t)s * 32 * LDN * 2;
        cpa16(bb + ad0,          pA0h + ao, vA0);
        cpa16(bb + ad1,          pA1h + ao, vA1);
        cpa16(bb + APLANE + ad0, pA0l + ao, vA0);
        cpa16(bb + APLANE + ad1, pA1l + ao, vA1);
#pragma unroll
        for (int j = 0; j < 4; j++) {
            cpa16(bb + OBH + bd0 + j * 128, pBh + bo + j * 128, 1);
            cpa16(bb + OBL + bd0 + j * 128, pBl + bo + j * 128, 1);
        }
        asm volatile("cp.async.commit_group;" ::: "memory");
    };

    issue(0);
#pragma unroll 1
    for (int s = 0; s < NST; s++) {
        if (s + 1 < NST) {
            issue(s + 1);
            asm volatile("cp.async.wait_group 1;" ::: "memory");
        } else {
            asm volatile("cp.async.wait_group 0;" ::: "memory");
        }
        __syncthreads();

        const uint32_t bb = sb + (uint32_t)(s & 1) * BUFSZ;
        const uint32_t abase  = bb + (uint32_t)(wm * 64) * 80 + aoff;
        const uint32_t bbaseH = bb + OBH + blane + (uint32_t)wn * 128;
        const uint32_t bbaseL = bbaseH + BPLANE;
#pragma unroll
        for (int kk = 0; kk < 2; kk++) {
            const uint32_t kbA = kk * 32;
            const uint32_t kbB = kk * 8448;
            uint32_t aH[4][4], aL[4][4], bH[8][2], bL[8][2];
#pragma unroll
            for (int mt = 0; mt < 4; mt++) {
                ldsm4(aH[mt], abase + mt * (16 * 80) + kbA);
                ldsm4(aL[mt], abase + APLANE + mt * (16 * 80) + kbA);
            }
#pragma unroll
            for (int nn = 0; nn < 4; nn++) {
                uint32_t r[4];
                ldsm4t(r, bbaseH + kbB + nn * 32);
                bH[2 * nn][0] = r[0]; bH[2 * nn][1] = r[1];
                bH[2 * nn + 1][0] = r[2]; bH[2 * nn + 1][1] = r[3];
                ldsm4t(r, bbaseL + kbB + nn * 32);
                bL[2 * nn][0] = r[0]; bL[2 * nn][1] = r[1];
                bL[2 * nn + 1][0] = r[2]; bL[2 * nn + 1][1] = r[3];
            }
#pragma unroll
            for (int mt = 0; mt < 4; mt++)
#pragma unroll
                for (int nt = 0; nt < 8; nt++) {
                    mma16816(c[mt][nt], aH[mt], bH[nt]);
                    mma16816(c[mt][nt], aH[mt], bL[nt]);
                    mma16816(c[mt][nt], aL[mt], bH[nt]);
                }
        }
        __syncthreads();
    }

    const int gid = lane >> 2, tig = lane & 3;
#pragma unroll
    for (int mt = 0; mt < 4; mt++) {
#pragma unroll
        for (int nt = 0; nt < 8; nt++) {
            const int ng = n0 + wn * 64 + nt * 8 + tig * 2;
#pragma unroll
            for (int h = 0; h < 2; h++) {
                const int ml = wm * 64 + mt * 16 + gid + 8 * h;
                float v0 = c[mt][nt][2 * h], v1 = c[mt][nt][2 * h + 1];
                if (MODE == 0) {
                    const int m = m0 + ml;
                    const int which = ng >> 10, hh = (ng >> 6) & 15, hs = ng & 63;
                    const int bb_ = m >> 10, t = m & 1023;
                    float* outp = (which == 0) ? g_q : ((which == 1) ? g_k : g_v);
                    *(float2*)&outp[(((size_t)(bb_ * HH + hh)) * TT + t) * HSZ + hs] =
                        make_float2(v0, v1);
                } else if (MODE == 1) {
                    const int m = m0 + ml;
                    const size_t o = (size_t)m * DD + ng;
                    float2 rr = *(const float2*)&resid[o];
                    *(float2*)&g_x2[o] = make_float2(v0 + bias[ng] + rr.x,
                                                     v1 + bias[ng + 1] + rr.y);
                } else if (MODE == 2) {
                    const int i = m0 + ml;
                    if (i < cnt) {
                        float a0 = fmaxf(v0 + bias[(size_t)e * DFF_ + ng], 0.f);
                        float a1 = fmaxf(v1 + bias[(size_t)e * DFF_ + ng + 1], 0.f);
                        __nv_bfloat16 h0, l0, h1, l1;
                        bf16_split(a0, h0, l0);
                        bf16_split(a1, h1, l1);
                        size_t idx = (size_t)(base + i) * DFF_ + ng;
                        *(uint32_t*)&g_h_h[idx] = pack2(h0, h1);
                        *(uint32_t*)&g_h_l[idx] = pack2(l0, l1);
                    }
                } else {
                    const int i = m0 + ml;
                    if (i < cnt) {
                        *(float2*)&g_eo[(size_t)(base + i) * DD + ng] =
                            make_float2(v0 + bias[(size_t)e * DD + ng],
                                        v1 + bias[(size_t)e * DD + ng + 1]);
                    }
                }
            }
        }
    }
}

// ---------------- flash attention (fp32; bf16 hi/lo output) ----------------
__global__ void __launch_bounds__(256, 1) attn_kernel() {
    __shared__ float Qs[64 * 64];
    __shared__ float Ks[64 * 64];
    __shared__ float Vs[64 * 64];
    const int bh = blockIdx.x;
    const int qt = blockIdx.y;
    const int tid = threadIdx.x;
    const int rt = tid >> 4, ct = tid & 15;

    const float* qb  = g_q + (size_t)bh * (TT * HSZ) + (size_t)qt * 64 * HSZ;
    const float* kb0 = g_k + (size_t)bh * (TT * HSZ);
    const float* vb0 = g_v + (size_t)bh * (TT * HSZ);

    for (int idx = tid; idx < 4096; idx += 256) {
        int t = idx >> 6, ee = idx & 63;
        Qs[ee * 64 + t] = qb[idx] * 0.03125f;
    }

    float m[4], l[4], O[4][4];
#pragma unroll
    for (int i = 0; i < 4; i++) {
        m[i] = -1e30f; l[i] = 0.f;
#pragma unroll
        for (int j = 0; j < 4; j++) O[i][j] = 0.f;
    }

    for (int kt = 0; kt < 16; kt++) {
        __syncthreads();
        const float* kb = kb0 + kt * 64 * HSZ;
        const float* vb = vb0 + kt * 64 * HSZ;
        for (int idx = tid; idx < 4096; idx += 256) {
            int s = idx >> 6, ee = idx & 63;
            Ks[ee * 64 + s] = kb[idx];
            Vs[idx] = vb[idx];
        }
        __syncthreads();

        float S[4][4];
#pragma unroll
        for (int i = 0; i < 4; i++)
#pragma unroll
            for (int j = 0; j < 4; j++) S[i][j] = 0.f;

#pragma unroll 8
        for (int kk = 0; kk < 64; kk++) {
            float4 a = *(float4*)&Qs[kk * 64 + rt * 4];
            float4 b = *(float4*)&Ks[kk * 64 + ct * 4];
            float av[4] = {a.x, a.y, a.z, a.w};
            float bv[4] = {b.x, b.y, b.z, b.w};
#pragma unroll
            for (int i = 0; i < 4; i++)
#pragma unroll
                for (int j = 0; j < 4; j++) S[i][j] += av[i] * bv[j];
        }

#pragma unroll
        for (int i = 0; i < 4; i++) {
            float mt = fmaxf(fmaxf(S[i][0], S[i][1]), fmaxf(S[i][2], S[i][3]));
            for (int o = 1; o < 16; o <<= 1)
                mt = fmaxf(mt, __shfl_xor_sync(0xffffffffu, mt, o));
            float mnew = fmaxf(m[i], mt);
            float alpha = __expf(m[i] - mnew);
            float rs = 0.f;
#pragma unroll
            for (int j = 0; j < 4; j++) {
                float p = __expf(S[i][j] - mnew);
                S[i][j] = p; rs += p;
            }
            for (int o = 1; o < 16; o <<= 1)
                rs += __shfl_xor_sync(0xffffffffu, rs, o);
            l[i] = l[i] * alpha + rs;
            m[i] = mnew;
#pragma unroll
            for (int j = 0; j < 4; j++) O[i][j] *= alpha;
        }

        __syncthreads();
#pragma unroll
        for (int j = 0; j < 4; j++) {
            float4 p = make_float4(S[0][j], S[1][j], S[2][j], S[3][j]);
            *(float4*)&Ks[(ct * 4 + j) * 64 + rt * 4] = p;
        }
        __syncthreads();

#pragma unroll 8
        for (int kk = 0; kk < 64; kk++) {
            float4 a = *(float4*)&Ks[kk * 64 + rt * 4];
            float4 b = *(float4*)&Vs[kk * 64 + ct * 4];
            float av[4] = {a.x, a.y, a.z, a.w};
            float bv[4] = {b.x, b.y, b.z, b.w};
#pragma unroll
            for (int i = 0; i < 4; i++)
#pragma unroll
                for (int j = 0; j < 4; j++) O[i][j] += av[i] * bv[j];
        }
    }

    const int b = bh >> 4, h = bh & 15;
#pragma unroll
    for (int i = 0; i < 4; i++) {
        float inv = 1.f / l[i];
        int t = qt * 64 + rt * 4 + i;
        size_t bidx = ((size_t)(b * TT + t)) * DD + h * HSZ + ct * 4;
#pragma unroll
        for (int j = 0; j < 4; j++) {
            float val = O[i][j] * inv;
            __nv_bfloat16 hh, ll;
            bf16_split(val, hh, ll);
            g_hd_h[bidx + j] = hh;
            g_hd_l[bidx + j] = ll;
        }
    }
}

// ---------------- routing ----------------
__global__ void zero_cnt_kernel() {
    if (threadIdx.x < EE) g_cnt[threadIdx.x] = 0;
}

__global__ void route_kernel(const float* __restrict__ noise,
                             const float* __restrict__ w_route,
                             const float* __restrict__ b_route,
                             const float* __restrict__ w_noise,
                             const float* __restrict__ b_noise) {
    int tok = blockIdx.x;
    __shared__ float xs[DD];
    __shared__ float dots[16];
    for (int i = threadIdx.x; i < DD; i += 256)
        xs[i] = g_xn2[(size_t)tok * DD + i];
    __syncthreads();

    int j = threadIdx.x >> 4, lane = threadIdx.x & 15;
    const float* W = (j < 8) ? w_route : w_noise;
    int col = j & 7;
    float s = 0.f;
    for (int d = lane; d < DD; d += 16) s += xs[d] * W[(size_t)d * EE + col];
    for (int o = 8; o; o >>= 1) s += __shfl_down_sync(0xffffffffu, s, o, 16);
    if (lane == 0) dots[j] = s + ((j < 8) ? b_route[col] : b_noise[col]);
    __syncthreads();

    if (threadIdx.x == 0) {
        float noisy[EE];
        for (int ee = 0; ee < EE; ee++) {
            float nl = dots[8 + ee];
            float sp = (nl > 20.f) ? nl : log1pf(expf(nl));
            noisy[ee] = dots[ee] + noise[(size_t)tok * EE + ee] * sp;
        }
        int i1 = 0;
        for (int ee = 1; ee < EE; ee++) if (noisy[ee] > noisy[i1]) i1 = ee;
        int i2 = -1;
        for (int ee = 0; ee < EE; ee++) {
            if (ee == i1) continue;
            if (i2 < 0 || noisy[ee] > noisy[i2]) i2 = ee;
        }
        float e2 = expf(noisy[i2] - noisy[i1]);
        float inv = 1.f / (1.f + e2);
        float p1 = inv, p2 = e2 * inv;
        int pos1 = atomicAdd(&g_cnt[i1], 1);
        g_tok[i1 * BT + pos1] = tok;
        int pos2 = atomicAdd(&g_cnt[i2], 1);
        g_tok[i2 * BT + pos2] = tok;
        g_texp[tok * 2] = i1; g_tpos[tok * 2] = pos1; g_tgate[tok * 2] = p1;
        g_texp[tok * 2 + 1] = i2; g_tpos[tok * 2 + 1] = pos2; g_tgate[tok * 2 + 1] = p2;
    }
}

__global__ void scan_kernel() {
    if (threadIdx.x == 0) {
        int b = 0;
        for (int e = 0; e < EE; e++) { g_base[e] = b; b += g_cnt[e]; }
    }
}

// ---------------- final combine ----------------
__global__ void combine_kernel(float* __restrict__ out) {
    int tok = blockIdx.x;
    int e1 = g_texp[tok * 2], e2 = g_texp[tok * 2 + 1];
    float gt1 = g_tgate[tok * 2], gt2 = g_tgate[tok * 2 + 1];
    size_t s1 = (size_t)(g_base[e1] + g_tpos[tok * 2]) * DD;
    size_t s2 = (size_t)(g_base[e2] + g_tpos[tok * 2 + 1]) * DD;
    size_t o = (size_t)tok * DD;
    for (int i = threadIdx.x * 4; i < DD; i += 256 * 4) {
        float4 a = *(float4*)&g_xn2[o + i];
        float4 u = *(float4*)&g_eo[s1 + i];
        float4 w = *(float4*)&g_eo[s2 + i];
        float4 r = make_float4(a.x + gt1 * u.x + gt2 * w.x,
                               a.y + gt1 * u.y + gt2 * w.y,
                               a.z + gt1 * u.z + gt2 * w.z,
                               a.w + gt1 * u.w + gt2 * w.w);
        *(float4*)&out[o + i] = r;
    }
}

// ---------------- launch ----------------
extern "C" void kernel_launch(void* const* d_in, const int* in_sizes, int n_in,
                              void* d_out, int out_size) {
    const float* x       = (const float*)d_in[0];
    const float* noise   = (const float*)d_in[1];
    const float* ln1_g   = (const float*)d_in[2];
    const float* ln1_b   = (const float*)d_in[3];
    const float* wq      = (const float*)d_in[4];
    const float* wk      = (const float*)d_in[5];
    const float* wv      = (const float*)d_in[6];
    const float* w_proj  = (const float*)d_in[7];
    const float* b_proj  = (const float*)d_in[8];
    const float* ln2_g   = (const float*)d_in[9];
    const float* ln2_b   = (const float*)d_in[10];
    const float* w_route = (const float*)d_in[11];
    const float* b_route = (const float*)d_in[12];
    const float* w_noise = (const float*)d_in[13];
    const float* b_noise = (const float*)d_in[14];
    const float* w1      = (const float*)d_in[15];
    const float* b1      = (const float*)d_in[16];
    const float* w2      = (const float*)d_in[17];
    const float* b2      = (const float*)d_in[18];
    float* out = (float*)d_out;

    cudaFuncSetAttribute(hmma_gemm<0>, cudaFuncAttributeMaxDynamicSharedMemorySize, SMEM_BYTES);
    cudaFuncSetAttribute(hmma_gemm<1>, cudaFuncAttributeMaxDynamicSharedMemorySize, SMEM_BYTES);
    cudaFuncSetAttribute(hmma_gemm<2>, cudaFuncAttributeMaxDynamicSharedMemorySize, SMEM_BYTES);
    cudaFuncSetAttribute(hmma_gemm<3>, cudaFuncAttributeMaxDynamicSharedMemorySize, SMEM_BYTES);

    __nv_bfloat16 *xn_h, *xn_l, *xn2_h, *xn2_l;
    __nv_bfloat16 *wqkv_h, *wqkv_l, *wp_h, *wp_l, *w1_h, *w1_l, *w2_h, *w2_l;
    float *x2, *xn2;
    cudaGetSymbolAddress((void**)&xn_h,  g_xn_h);
    cudaGetSymbolAddress((void**)&xn_l,  g_xn_l);
    cudaGetSymbolAddress((void**)&xn2_h, g_xn2_h);
    cudaGetSymbolAddress((void**)&xn2_l, g_xn2_l);
    cudaGetSymbolAddress((void**)&wqkv_h, g_wqkv_h);
    cudaGetSymbolAddress((void**)&wqkv_l, g_wqkv_l);
    cudaGetSymbolAddress((void**)&wp_h, g_wp_h);
    cudaGetSymbolAddress((void**)&wp_l, g_wp_l);
    cudaGetSymbolAddress((void**)&w1_h, g_w1_h);
    cudaGetSymbolAddress((void**)&w1_l, g_w1_l);
    cudaGetSymbolAddress((void**)&w2_h, g_w2_h);
    cudaGetSymbolAddress((void**)&w2_l, g_w2_l);
    cudaGetSymbolAddress((void**)&x2,   g_x2);
    cudaGetSymbolAddress((void**)&xn2,  g_xn2);

    // weight prep
    conv_qkv<<<1024, 256>>>(wq, wqkv_h,        wqkv_l);
    conv_qkv<<<1024, 256>>>(wk, wqkv_h + 1024, wqkv_l + 1024);
    conv_qkv<<<1024, 256>>>(wv, wqkv_h + 2048, wqkv_l + 2048);
    conv_stream<<<1024, 256>>>((const float4*)w_proj, (uint2*)wp_h, (uint2*)wp_l, DD * DD / 4);
    conv_stream<<<2048, 256>>>((const float4*)w1, (uint2*)w1_h, (uint2*)w1_l, EE * DD * DFF_ / 4);
    conv_stream<<<2048, 256>>>((const float4*)w2, (uint2*)w2_h, (uint2*)w2_l, EE * DFF_ * DD / 4);

    // LN1 -> xn (bf16 hi/lo only)
    ln_kernel<<<BT, 256>>>(x, ln1_g, ln1_b, nullptr, xn_h, xn_l);

    // fused QKV (N = 3072)
    hmma_gemm<0><<<dim3(12, 32, 1), 256, SMEM_BYTES>>>(nullptr, nullptr);

    // attention -> g_hd hi/lo
    attn_kernel<<<dim3(BB * HH, TT / 64), 256>>>();

    // out proj + bias + residual -> g_x2
    hmma_gemm<1><<<dim3(4, 32, 1), 256, SMEM_BYTES>>>(b_proj, x);

    // LN2 -> xn2 (fp32 + hi/lo)
    ln_kernel<<<BT, 256>>>(x2, ln2_g, ln2_b, xn2, xn2_h, xn2_l);

    // routing
    zero_cnt_kernel<<<1, 32>>>();
    route_kernel<<<BT, 256>>>(noise, w_route, b_route, w_noise, b_noise);
    scan_kernel<<<1, 32>>>();

    // MoE expert GEMMs
    hmma_gemm<2><<<dim3(16, 32, EE), 256, SMEM_BYTES>>>(b1, nullptr);
    hmma_gemm<3><<<dim3(4, 32, EE), 256, SMEM_BYTES>>>(b2, nullptr);

    // combine
    combine_kernel<<<BT, 256>>>(out);
}

// round 12
// speedup vs baseline: 1.4815x; 1.2307x over previous
#include <cuda_runtime.h>
#include <cuda_fp16.h>
#include <math.h>
#include <stdint.h>

#define BB   4
#define TT   1024
#define DD   1024
#define HH   16
#define HSZ  64
#define EE   8
#define DFF_ 4096
#define BT   4096
#define NSLOT (BT*2)

// ---------------- device scratch ----------------
__device__ float g_q  [BT*DD];
__device__ float g_k  [BT*DD];
__device__ float g_v  [BT*DD];
__device__ float g_x2 [BT*DD];
__device__ float g_xn2[BT*DD];
__device__ float g_eo [NSLOT*DD];

__device__ __align__(16) __half g_xn_h [BT*DD], g_xn_l [BT*DD];
__device__ __align__(16) __half g_hd_h [BT*DD], g_hd_l [BT*DD];
__device__ __align__(16) __half g_xn2_h[BT*DD], g_xn2_l[BT*DD];
__device__ __align__(16) __half g_h_h  [NSLOT*DFF_], g_h_l[NSLOT*DFF_];
__device__ __align__(16) __half g_wqkv [DD*3*DD];   // [K][N=3072] fp16 single plane
__device__ __align__(16) __half g_wp   [DD*DD];
__device__ __align__(16) __half g_w1   [EE*DD*DFF_];
__device__ __align__(16) __half g_w2   [EE*DFF_*DD];

__device__ int   g_cnt [EE];
__device__ int   g_base[EE];
__device__ int   g_tok [EE*BT];
__device__ int   g_texp[BT*2];
__device__ int   g_tpos[BT*2];
__device__ float g_tgate[BT*2];

// ---------------- helpers ----------------
__device__ __forceinline__ uint32_t smem_u32(const void* p) {
    uint32_t a;
    asm("{ .reg .u64 t; cvta.to.shared.u64 t, %1; cvt.u32.u64 %0, t; }" : "=r"(a) : "l"(p));
    return a;
}
__device__ __forceinline__ void cpa16(uint32_t dst, const void* src, int valid) {
    asm volatile("cp.async.cg.shared.global [%0], [%1], 16, %2;"
                 :: "r"(dst), "l"(src), "r"(valid ? 16 : 0) : "memory");
}
__device__ __forceinline__ void ldsm4(uint32_t* r, uint32_t addr) {
    asm volatile("ldmatrix.sync.aligned.m8n8.x4.shared.b16 {%0,%1,%2,%3}, [%4];"
                 : "=r"(r[0]), "=r"(r[1]), "=r"(r[2]), "=r"(r[3]) : "r"(addr));
}
__device__ __forceinline__ void ldsm4t(uint32_t* r, uint32_t addr) {
    asm volatile("ldmatrix.sync.aligned.m8n8.x4.trans.shared.b16 {%0,%1,%2,%3}, [%4];"
                 : "=r"(r[0]), "=r"(r[1]), "=r"(r[2]), "=r"(r[3]) : "r"(addr));
}
__device__ __forceinline__ void mma_h(float* c, const uint32_t* a, const uint32_t* b) {
    asm volatile(
        "mma.sync.aligned.m16n8k16.row.col.f32.f16.f16.f32 "
        "{%0,%1,%2,%3},{%4,%5,%6,%7},{%8,%9},{%0,%1,%2,%3};"
        : "+f"(c[0]), "+f"(c[1]), "+f"(c[2]), "+f"(c[3])
        : "r"(a[0]), "r"(a[1]), "r"(a[2]), "r"(a[3]), "r"(b[0]), "r"(b[1]));
}
__device__ __forceinline__ void h_split(float v, __half& h, __half& l) {
    h = __float2half_rn(v);
    l = __float2half_rn(v - __half2float(h));
}
__device__ __forceinline__ uint32_t pack2h(__half a, __half b) {
    return ((uint32_t)__half_as_ushort(b) << 16) | (uint32_t)__half_as_ushort(a);
}

// ---------------- LayerNorm (+ fp16 hi/lo split outputs) ----------------
__global__ void ln_kernel(const float* __restrict__ x,
                          const float* __restrict__ g,
                          const float* __restrict__ b,
                          float* __restrict__ out,
                          __half* __restrict__ oh,
                          __half* __restrict__ ol) {
    int row = blockIdx.x;
    const float* xr = x + (size_t)row * DD;
    float s = 0.f, s2 = 0.f;
    for (int i = threadIdx.x; i < DD; i += 256) {
        float v = xr[i]; s += v; s2 += v * v;
    }
    for (int o = 16; o; o >>= 1) {
        s  += __shfl_xor_sync(0xffffffffu, s,  o);
        s2 += __shfl_xor_sync(0xffffffffu, s2, o);
    }
    __shared__ float ss[8], ss2[8];
    __shared__ float mu, rs;
    if ((threadIdx.x & 31) == 0) { ss[threadIdx.x >> 5] = s; ss2[threadIdx.x >> 5] = s2; }
    __syncthreads();
    if (threadIdx.x == 0) {
        float t = 0.f, t2 = 0.f;
        for (int i = 0; i < 8; i++) { t += ss[i]; t2 += ss2[i]; }
        float m = t / (float)DD;
        mu = m; rs = rsqrtf(t2 / (float)DD - m * m + 1e-5f);
    }
    __syncthreads();
    float m = mu, r = rs;
    for (int i = threadIdx.x; i < DD; i += 256) {
        float v = (xr[i] - m) * r * g[i] + b[i];
        if (out) out[(size_t)row * DD + i] = v;
        __half hh, ll;
        h_split(v, hh, ll);
        oh[(size_t)row * DD + i] = hh;
        ol[(size_t)row * DD + i] = ll;
    }
}

// ---------------- streaming weight convert: fp32 -> fp16 single plane ----------------
__global__ void conv_stream(const float4* __restrict__ in,
                            uint2* __restrict__ oh, int n4) {
    for (int i = blockIdx.x * blockDim.x + threadIdx.x; i < n4;
         i += gridDim.x * blockDim.x) {
        float4 v = in[i];
        oh[i] = make_uint2(pack2h(__float2half_rn(v.x), __float2half_rn(v.y)),
                           pack2h(__float2half_rn(v.z), __float2half_rn(v.w)));
    }
}

// QKV: [H][D][HS] fp32 -> rows d of [1024][3072] fp16
__global__ void conv_qkv(const float* __restrict__ in,
                         __half* __restrict__ oh) {
    int idx = blockIdx.x * 256 + threadIdx.x;
    int hs4 = idx & 15;
    int d   = (idx >> 4) & 1023;
    int h   = idx >> 14;
    float4 v = *(const float4*)(in + (((size_t)h << 10) + d) * 64 + hs4 * 4);
    size_t o = (size_t)d * 3072 + h * 64 + hs4 * 4;
    *(uint2*)(oh + o) = make_uint2(pack2h(__float2half_rn(v.x), __float2half_rn(v.y)),
                                   pack2h(__float2half_rn(v.z), __float2half_rn(v.w)));
}

// ---------------- HMMA fp16-hybrid GEMM: 128x256 tile, warp 64x64, 2 MMAs ----------------
// A = activations fp16 hi/lo (2 planes), B = weights fp16 single plane.
#define APLANE  10240            // 128 rows x 80B (32 k fp16 + pad)
#define BPLANE  16896            // 32 k-rows x 528B (256 cols fp16 + pad)
#define OBH     (2*APLANE)
#define BUFSZ   (2*APLANE + BPLANE)   // 37376
#define SMEM_BYTES (2*BUFSZ)          // 74752

template<int MODE>
__global__ void __launch_bounds__(256, 1)
hmma_gemm(const float* __restrict__ bias, const float* __restrict__ resid) {
    constexpr int KD  = (MODE == 3) ? DFF_ : DD;
    constexpr int LDN = (MODE == 0) ? 3 * DD : ((MODE == 2) ? DFF_ : DD);
    constexpr int NST = KD / 32;
    const int n0 = blockIdx.x * 256, m0 = blockIdx.y * 128, e = blockIdx.z;

    int cnt = 1 << 30, base = 0;
    const __half *Ah, *Al, *Bw;
    if (MODE == 0)      { Ah = g_xn_h;  Al = g_xn_l;  Bw = g_wqkv; }
    else if (MODE == 1) { Ah = g_hd_h;  Al = g_hd_l;  Bw = g_wp; }
    else if (MODE == 2) { Ah = g_xn2_h; Al = g_xn2_l; Bw = g_w1; }
    else                { Ah = g_h_h;   Al = g_h_l;   Bw = g_w2; }
    if (MODE == 2 || MODE == 3) {
        cnt = g_cnt[e];
        if (m0 >= cnt) return;
        base = g_base[e];
        Bw += (size_t)e * DD * DFF_;
    }

    extern __shared__ __align__(16) char smem[];
    const uint32_t sb = smem_u32(smem);
    const int tid = threadIdx.x;
    const int wid = tid >> 5, lane = tid & 31;
    const int wm = wid >> 2, wn = wid & 3;   // 2x4 warps, each 64m x 64n

    // ---- A load assignment: rows rloc & rloc+64, 16B chunk kc ----
    const int rloc = tid >> 2, kc = tid & 3;
    int gA0, gA1, vA0 = 1, vA1 = 1;
    {
        int i0 = m0 + rloc, i1 = m0 + rloc + 64;
        if (MODE == 2) {
            vA0 = i0 < cnt; vA1 = i1 < cnt;
            gA0 = vA0 ? g_tok[e * BT + i0] : 0;
            gA1 = vA1 ? g_tok[e * BT + i1] : 0;
        } else if (MODE == 3) {
            vA0 = i0 < cnt; vA1 = i1 < cnt;
            gA0 = base + (vA0 ? i0 : 0);
            gA1 = base + (vA1 ? i1 : 0);
        } else { gA0 = i0; gA1 = i1; }
    }
    const char* pA0h = (const char*)(Ah + (size_t)gA0 * KD) + kc * 16;
    const char* pA0l = (const char*)(Al + (size_t)gA0 * KD) + kc * 16;
    const char* pA1h = (const char*)(Ah + (size_t)gA1 * KD) + kc * 16;
    const char* pA1l = (const char*)(Al + (size_t)gA1 * KD) + kc * 16;
    const uint32_t ad0 = rloc * 80 + kc * 16;
    const uint32_t ad1 = (rloc + 64) * 80 + kc * 16;

    // ---- B load assignment: 32 k-rows x 512B; row=tid>>3, chunk bc, 4 chunks ----
    const int brow = tid >> 3, bc = tid & 7;
    const char* pB = (const char*)(Bw + (size_t)brow * LDN + n0 + bc * 8);
    const uint32_t bd0 = brow * 528 + bc * 16;

    // ---- ldmatrix lane addressing ----
    const uint32_t aoff = (uint32_t)((lane & 15) * 80 + (lane >> 4) * 16);
    const uint32_t blane = (uint32_t)((((lane >> 3) & 1) * 8 + (lane & 7)) * 528 + (lane >> 4) * 16);

    float c[4][8][4];
#pragma unroll
    for (int i = 0; i < 4; i++)
#pragma unroll
        for (int j = 0; j < 8; j++)
#pragma unroll
            for (int q = 0; q < 4; q++) c[i][j][q] = 0.f;

    auto issue = [&](int s) {
        const uint32_t bb = sb + (uint32_t)(s & 1) * BUFSZ;
        const size_t ao = (size_t)s * 64;                 // A: 32 k elems * 2B
        const size_t bo = (size_t)s * 32 * LDN * 2;       // B: 32 k-rows
        cpa16(bb + ad0,          pA0h + ao, vA0);
        cpa16(bb + ad1,          pA1h + ao, vA1);
        cpa16(bb + APLANE + ad0, pA0l + ao, vA0);
        cpa16(bb + APLANE + ad1, pA1l + ao, vA1);
#pragma unroll
        for (int j = 0; j < 4; j++)
            cpa16(bb + OBH + bd0 + j * 128, pB + bo + j * 128, 1);
        asm volatile("cp.async.commit_group;" ::: "memory");
    };

    issue(0);
#pragma unroll 1
    for (int s = 0; s < NST; s++) {
        if (s + 1 < NST) {
            issue(s + 1);
            asm volatile("cp.async.wait_group 1;" ::: "memory");
        } else {
            asm volatile("cp.async.wait_group 0;" ::: "memory");
        }
        __syncthreads();

        const uint32_t bb = sb + (uint32_t)(s & 1) * BUFSZ;
        const uint32_t abase = bb + (uint32_t)(wm * 64) * 80 + aoff;
        const uint32_t bbase = bb + OBH + blane + (uint32_t)wn * 128;   // 64 cols * 2B
#pragma unroll
        for (int kk = 0; kk < 2; kk++) {
            const uint32_t kbA = kk * 32;
            const uint32_t kbB = kk * 8448;     // 16 k-rows * 528B
            uint32_t aH[4][4], aL[4][4], bH[8][2];
#pragma unroll
            for (int mt = 0; mt < 4; mt++) {
                ldsm4(aH[mt], abase + mt * (16 * 80) + kbA);
                ldsm4(aL[mt], abase + APLANE + mt * (16 * 80) + kbA);
            }
#pragma unroll
            for (int nn = 0; nn < 4; nn++) {
                uint32_t r[4];
                ldsm4t(r, bbase + kbB + nn * 32);
                bH[2 * nn][0] = r[0]; bH[2 * nn][1] = r[1];
                bH[2 * nn + 1][0] = r[2]; bH[2 * nn + 1][1] = r[3];
            }
#pragma unroll
            for (int mt = 0; mt < 4; mt++)
#pragma unroll
                for (int nt = 0; nt < 8; nt++) {
                    mma_h(c[mt][nt], aH[mt], bH[nt]);
                    mma_h(c[mt][nt], aL[mt], bH[nt]);
                }
        }
        __syncthreads();
    }

    // ---- epilogue ----
    const int gid = lane >> 2, tig = lane & 3;
#pragma unroll
    for (int mt = 0; mt < 4; mt++) {
#pragma unroll
        for (int nt = 0; nt < 8; nt++) {
            const int ng = n0 + wn * 64 + nt * 8 + tig * 2;
#pragma unroll
            for (int h = 0; h < 2; h++) {
                const int ml = wm * 64 + mt * 16 + gid + 8 * h;
                float v0 = c[mt][nt][2 * h], v1 = c[mt][nt][2 * h + 1];
                if (MODE == 0) {
                    const int m = m0 + ml;
                    const int which = ng >> 10, hh = (ng >> 6) & 15, hs = ng & 63;
                    const int bb_ = m >> 10, t = m & 1023;
                    float* outp = (which == 0) ? g_q : ((which == 1) ? g_k : g_v);
                    *(float2*)&outp[(((size_t)(bb_ * HH + hh)) * TT + t) * HSZ + hs] =
                        make_float2(v0, v1);
                } else if (MODE == 1) {
                    const int m = m0 + ml;
                    const size_t o = (size_t)m * DD + ng;
                    float2 rr = *(const float2*)&resid[o];
                    *(float2*)&g_x2[o] = make_float2(v0 + bias[ng] + rr.x,
                                                     v1 + bias[ng + 1] + rr.y);
                } else if (MODE == 2) {
                    const int i = m0 + ml;
                    if (i < cnt) {
                        float a0 = fmaxf(v0 + bias[(size_t)e * DFF_ + ng], 0.f);
                        float a1 = fmaxf(v1 + bias[(size_t)e * DFF_ + ng + 1], 0.f);
                        __half h0, l0, h1, l1;
                        h_split(a0, h0, l0);
                        h_split(a1, h1, l1);
                        size_t idx = (size_t)(base + i) * DFF_ + ng;
                        *(uint32_t*)&g_h_h[idx] = pack2h(h0, h1);
                        *(uint32_t*)&g_h_l[idx] = pack2h(l0, l1);
                    }
                } else {
                    const int i = m0 + ml;
                    if (i < cnt) {
                        *(float2*)&g_eo[(size_t)(base + i) * DD + ng] =
                            make_float2(v0 + bias[(size_t)e * DD + ng],
                                        v1 + bias[(size_t)e * DD + ng + 1]);
                    }
                }
            }
        }
    }
}

// ---------------- flash attention (fp32; fp16 hi/lo output) ----------------
__global__ void __launch_bounds__(256, 1) attn_kernel() {
    __shared__ float Qs[64 * 64];
    __shared__ float Ks[64 * 64];
    __shared__ float Vs[64 * 64];
    const int bh = blockIdx.x;
    const int qt = blockIdx.y;
    const int tid = threadIdx.x;
    const int rt = tid >> 4, ct = tid & 15;

    const float* qb  = g_q + (size_t)bh * (TT * HSZ) + (size_t)qt * 64 * HSZ;
    const float* kb0 = g_k + (size_t)bh * (TT * HSZ);
    const float* vb0 = g_v + (size_t)bh * (TT * HSZ);

    for (int idx = tid; idx < 4096; idx += 256) {
        int t = idx >> 6, ee = idx & 63;
        Qs[ee * 64 + t] = qb[idx] * 0.03125f;
    }

    float m[4], l[4], O[4][4];
#pragma unroll
    for (int i = 0; i < 4; i++) {
        m[i] = -1e30f; l[i] = 0.f;
#pragma unroll
        for (int j = 0; j < 4; j++) O[i][j] = 0.f;
    }

    for (int kt = 0; kt < 16; kt++) {
        __syncthreads();
        const float* kb = kb0 + kt * 64 * HSZ;
        const float* vb = vb0 + kt * 64 * HSZ;
        for (int idx = tid; idx < 4096; idx += 256) {
            int s = idx >> 6, ee = idx & 63;
            Ks[ee * 64 + s] = kb[idx];
            Vs[idx] = vb[idx];
        }
        __syncthreads();

        float S[4][4];
#pragma unroll
        for (int i = 0; i < 4; i++)
#pragma unroll
            for (int j = 0; j < 4; j++) S[i][j] = 0.f;

#pragma unroll 8
        for (int kk = 0; kk < 64; kk++) {
            float4 a = *(float4*)&Qs[kk * 64 + rt * 4];
            float4 b = *(float4*)&Ks[kk * 64 + ct * 4];
            float av[4] = {a.x, a.y, a.z, a.w};
            float bv[4] = {b.x, b.y, b.z, b.w};
#pragma unroll
            for (int i = 0; i < 4; i++)
#pragma unroll
                for (int j = 0; j < 4; j++) S[i][j] += av[i] * bv[j];
        }

#pragma unroll
        for (int i = 0; i < 4; i++) {
            float mt = fmaxf(fmaxf(S[i][0], S[i][1]), fmaxf(S[i][2], S[i][3]));
            for (int o = 1; o < 16; o <<= 1)
                mt = fmaxf(mt, __shfl_xor_sync(0xffffffffu, mt, o));
            float mnew = fmaxf(m[i], mt);
            float alpha = __expf(m[i] - mnew);
            float rs = 0.f;
#pragma unroll
            for (int j = 0; j < 4; j++) {
                float p = __expf(S[i][j] - mnew);
                S[i][j] = p; rs += p;
            }
            for (int o = 1; o < 16; o <<= 1)
                rs += __shfl_xor_sync(0xffffffffu, rs, o);
            l[i] = l[i] * alpha + rs;
            m[i] = mnew;
#pragma unroll
            for (int j = 0; j < 4; j++) O[i][j] *= alpha;
        }

        __syncthreads();
#pragma unroll
        for (int j = 0; j < 4; j++) {
            float4 p = make_float4(S[0][j], S[1][j], S[2][j], S[3][j]);
            *(float4*)&Ks[(ct * 4 + j) * 64 + rt * 4] = p;
        }
        __syncthreads();

#pragma unroll 8
        for (int kk = 0; kk < 64; kk++) {
            float4 a = *(float4*)&Ks[kk * 64 + rt * 4];
            float4 b = *(float4*)&Vs[kk * 64 + ct * 4];
            float av[4] = {a.x, a.y, a.z, a.w};
            float bv[4] = {b.x, b.y, b.z, b.w};
#pragma unroll
            for (int i = 0; i < 4; i++)
#pragma unroll
                for (int j = 0; j < 4; j++) O[i][j] += av[i] * bv[j];
        }
    }

    const int b = bh >> 4, h = bh & 15;
#pragma unroll
    for (int i = 0; i < 4; i++) {
        float inv = 1.f / l[i];
        int t = qt * 64 + rt * 4 + i;
        size_t bidx = ((size_t)(b * TT + t)) * DD + h * HSZ + ct * 4;
#pragma unroll
        for (int j = 0; j < 4; j++) {
            float val = O[i][j] * inv;
            __half hh, ll;
            h_split(val, hh, ll);
            g_hd_h[bidx + j] = hh;
            g_hd_l[bidx + j] = ll;
        }
    }
}

// ---------------- routing ----------------
__global__ void zero_cnt_kernel() {
    if (threadIdx.x < EE) g_cnt[threadIdx.x] = 0;
}

__global__ void route_kernel(const float* __restrict__ noise,
                             const float* __restrict__ w_route,
                             const float* __restrict__ b_route,
                             const float* __restrict__ w_noise,
                             const float* __restrict__ b_noise) {
    int tok = blockIdx.x;
    __shared__ float xs[DD];
    __shared__ float dots[16];
    for (int i = threadIdx.x; i < DD; i += 256)
        xs[i] = g_xn2[(size_t)tok * DD + i];
    __syncthreads();

    int j = threadIdx.x >> 4, lane = threadIdx.x & 15;
    const float* W = (j < 8) ? w_route : w_noise;
    int col = j & 7;
    float s = 0.f;
    for (int d = lane; d < DD; d += 16) s += xs[d] * W[(size_t)d * EE + col];
    for (int o = 8; o; o >>= 1) s += __shfl_down_sync(0xffffffffu, s, o, 16);
    if (lane == 0) dots[j] = s + ((j < 8) ? b_route[col] : b_noise[col]);
    __syncthreads();

    if (threadIdx.x == 0) {
        float noisy[EE];
        for (int ee = 0; ee < EE; ee++) {
            float nl = dots[8 + ee];
            float sp = (nl > 20.f) ? nl : log1pf(expf(nl));
            noisy[ee] = dots[ee] + noise[(size_t)tok * EE + ee] * sp;
        }
        int i1 = 0;
        for (int ee = 1; ee < EE; ee++) if (noisy[ee] > noisy[i1]) i1 = ee;
        int i2 = -1;
        for (int ee = 0; ee < EE; ee++) {
            if (ee == i1) continue;
            if (i2 < 0 || noisy[ee] > noisy[i2]) i2 = ee;
        }
        float e2 = expf(noisy[i2] - noisy[i1]);
        float inv = 1.f / (1.f + e2);
        float p1 = inv, p2 = e2 * inv;
        int pos1 = atomicAdd(&g_cnt[i1], 1);
        g_tok[i1 * BT + pos1] = tok;
        int pos2 = atomicAdd(&g_cnt[i2], 1);
        g_tok[i2 * BT + pos2] = tok;
        g_texp[tok * 2] = i1; g_tpos[tok * 2] = pos1; g_tgate[tok * 2] = p1;
        g_texp[tok * 2 + 1] = i2; g_tpos[tok * 2 + 1] = pos2; g_tgate[tok * 2 + 1] = p2;
    }
}

__global__ void scan_kernel() {
    if (threadIdx.x == 0) {
        int b = 0;
        for (int e = 0; e < EE; e++) { g_base[e] = b; b += g_cnt[e]; }
    }
}

// ---------------- final combine ----------------
__global__ void combine_kernel(float* __restrict__ out) {
    int tok = blockIdx.x;
    int e1 = g_texp[tok * 2], e2 = g_texp[tok * 2 + 1];
    float gt1 = g_tgate[tok * 2], gt2 = g_tgate[tok * 2 + 1];
    size_t s1 = (size_t)(g_base[e1] + g_tpos[tok * 2]) * DD;
    size_t s2 = (size_t)(g_base[e2] + g_tpos[tok * 2 + 1]) * DD;
    size_t o = (size_t)tok * DD;
    for (int i = threadIdx.x * 4; i < DD; i += 256 * 4) {
        float4 a = *(float4*)&g_xn2[o + i];
        float4 u = *(float4*)&g_eo[s1 + i];
        float4 w = *(float4*)&g_eo[s2 + i];
        float4 r = make_float4(a.x + gt1 * u.x + gt2 * w.x,
                               a.y + gt1 * u.y + gt2 * w.y,
                               a.z + gt1 * u.z + gt2 * w.z,
                               a.w + gt1 * u.w + gt2 * w.w);
        *(float4*)&out[o + i] = r;
    }
}

// ---------------- launch ----------------
extern "C" void kernel_launch(void* const* d_in, const int* in_sizes, int n_in,
                              void* d_out, int out_size) {
    const float* x       = (const float*)d_in[0];
    const float* noise   = (const float*)d_in[1];
    const float* ln1_g   = (const float*)d_in[2];
    const float* ln1_b   = (const float*)d_in[3];
    const float* wq      = (const float*)d_in[4];
    const float* wk      = (const float*)d_in[5];
    const float* wv      = (const float*)d_in[6];
    const float* w_proj  = (const float*)d_in[7];
    const float* b_proj  = (const float*)d_in[8];
    const float* ln2_g   = (const float*)d_in[9];
    const float* ln2_b   = (const float*)d_in[10];
    const float* w_route = (const float*)d_in[11];
    const float* b_route = (const float*)d_in[12];
    const float* w_noise = (const float*)d_in[13];
    const float* b_noise = (const float*)d_in[14];
    const float* w1      = (const float*)d_in[15];
    const float* b1      = (const float*)d_in[16];
    const float* w2      = (const float*)d_in[17];
    const float* b2      = (const float*)d_in[18];
    float* out = (float*)d_out;

    cudaFuncSetAttribute(hmma_gemm<0>, cudaFuncAttributeMaxDynamicSharedMemorySize, SMEM_BYTES);
    cudaFuncSetAttribute(hmma_gemm<1>, cudaFuncAttributeMaxDynamicSharedMemorySize, SMEM_BYTES);
    cudaFuncSetAttribute(hmma_gemm<2>, cudaFuncAttributeMaxDynamicSharedMemorySize, SMEM_BYTES);
    cudaFuncSetAttribute(hmma_gemm<3>, cudaFuncAttributeMaxDynamicSharedMemorySize, SMEM_BYTES);

    __half *xn_h, *xn_l, *xn2_h, *xn2_l;
    __half *wqkv, *wp, *w1h, *w2h;
    float *x2, *xn2;
    cudaGetSymbolAddress((void**)&xn_h,  g_xn_h);
    cudaGetSymbolAddress((void**)&xn_l,  g_xn_l);
    cudaGetSymbolAddress((void**)&xn2_h, g_xn2_h);
    cudaGetSymbolAddress((void**)&xn2_l, g_xn2_l);
    cudaGetSymbolAddress((void**)&wqkv,  g_wqkv);
    cudaGetSymbolAddress((void**)&wp,    g_wp);
    cudaGetSymbolAddress((void**)&w1h,   g_w1);
    cudaGetSymbolAddress((void**)&w2h,   g_w2);
    cudaGetSymbolAddress((void**)&x2,    g_x2);
    cudaGetSymbolAddress((void**)&xn2,   g_xn2);

    // --- launches ordered so ncu slot 5 = hmma_gemm<0> (QKV GEMM) ---
    conv_qkv<<<1024, 256>>>(wq, wqkv);                      // 0
    conv_qkv<<<1024, 256>>>(wk, wqkv + 1024);               // 1
    conv_qkv<<<1024, 256>>>(wv, wqkv + 2048);               // 2
    ln_kernel<<<BT, 256>>>(x, ln1_g, ln1_b, nullptr, xn_h, xn_l);               // 3
    conv_stream<<<1024, 256>>>((const float4*)w_proj, (uint2*)wp, DD * DD / 4); // 4
    hmma_gemm<0><<<dim3(12, 32, 1), 256, SMEM_BYTES>>>(nullptr, nullptr);       // 5 (profiled)

    // attention -> g_hd fp16 hi/lo
    attn_kernel<<<dim3(BB * HH, TT / 64), 256>>>();

    // out proj + bias + residual -> g_x2
    hmma_gemm<1><<<dim3(4, 32, 1), 256, SMEM_BYTES>>>(b_proj, x);

    // LN2 -> xn2 (fp32 + fp16 hi/lo)
    ln_kernel<<<BT, 256>>>(x2, ln2_g, ln2_b, xn2, xn2_h, xn2_l);

    // routing
    zero_cnt_kernel<<<1, 32>>>();
    route_kernel<<<BT, 256>>>(noise, w_route, b_route, w_noise, b_noise);
    scan_kernel<<<1, 32>>>();

    // MoE weight conversion (only needed from here on)
    conv_stream<<<2048, 256>>>((const float4*)w1, (uint2*)w1h, EE * DD * DFF_ / 4);
    conv_stream<<<2048, 256>>>((const float4*)w2, (uint2*)w2h, EE * DFF_ * DD / 4);

    // MoE expert GEMMs
    hmma_gemm<2><<<dim3(16, 32, EE), 256, SMEM_BYTES>>>(b1, nullptr);
    hmma_gemm<3><<<dim3(4, 32, EE), 256, SMEM_BYTES>>>(b2, nullptr);

    // combine
    combine_kernel<<<BT, 256>>>(out);
}

// round 13
// speedup vs baseline: 1.8555x; 1.2524x over previous
#include <cuda_runtime.h>
#include <cuda_fp16.h>
#include <math.h>
#include <stdint.h>

#define BB   4
#define TT   1024
#define DD   1024
#define HH   16
#define HSZ  64
#define EE   8
#define DFF_ 4096
#define BT   4096
#define NSLOT (BT*2)

// ---------------- device scratch ----------------
__device__ float g_q  [BT*DD];
__device__ float g_k  [BT*DD];
__device__ float g_v  [BT*DD];
__device__ float g_x2 [BT*DD];
__device__ float g_xn2[BT*DD];
__device__ float g_eo [NSLOT*DD];

__device__ __align__(16) __half g_xn  [BT*DD];
__device__ __align__(16) __half g_hd  [BT*DD];
__device__ __align__(16) __half g_xn2h[BT*DD];
__device__ __align__(16) __half g_h   [NSLOT*DFF_];
__device__ __align__(16) __half g_wqkv[DD*3*DD];   // [K][N=3072] fp16
__device__ __align__(16) __half g_wp  [DD*DD];
__device__ __align__(16) __half g_w1  [EE*DD*DFF_];
__device__ __align__(16) __half g_w2  [EE*DFF_*DD];

__device__ int   g_cnt [EE];
__device__ int   g_base[EE];
__device__ int   g_tok [EE*BT];
__device__ int   g_texp[BT*2];
__device__ int   g_tpos[BT*2];
__device__ float g_tgate[BT*2];

// ---------------- helpers ----------------
__device__ __forceinline__ uint32_t smem_u32(const void* p) {
    uint32_t a;
    asm("{ .reg .u64 t; cvta.to.shared.u64 t, %1; cvt.u32.u64 %0, t; }" : "=r"(a) : "l"(p));
    return a;
}
__device__ __forceinline__ void cpa16(uint32_t dst, const void* src, int valid) {
    asm volatile("cp.async.cg.shared.global [%0], [%1], 16, %2;"
                 :: "r"(dst), "l"(src), "r"(valid ? 16 : 0) : "memory");
}
__device__ __forceinline__ void ldsm4(uint32_t* r, uint32_t addr) {
    asm volatile("ldmatrix.sync.aligned.m8n8.x4.shared.b16 {%0,%1,%2,%3}, [%4];"
                 : "=r"(r[0]), "=r"(r[1]), "=r"(r[2]), "=r"(r[3]) : "r"(addr));
}
__device__ __forceinline__ void ldsm4t(uint32_t* r, uint32_t addr) {
    asm volatile("ldmatrix.sync.aligned.m8n8.x4.trans.shared.b16 {%0,%1,%2,%3}, [%4];"
                 : "=r"(r[0]), "=r"(r[1]), "=r"(r[2]), "=r"(r[3]) : "r"(addr));
}
__device__ __forceinline__ void mma_h(float* c, const uint32_t* a, const uint32_t* b) {
    asm volatile(
        "mma.sync.aligned.m16n8k16.row.col.f32.f16.f16.f32 "
        "{%0,%1,%2,%3},{%4,%5,%6,%7},{%8,%9},{%0,%1,%2,%3};"
        : "+f"(c[0]), "+f"(c[1]), "+f"(c[2]), "+f"(c[3])
        : "r"(a[0]), "r"(a[1]), "r"(a[2]), "r"(a[3]), "r"(b[0]), "r"(b[1]));
}
__device__ __forceinline__ uint32_t pack2h(__half a, __half b) {
    return ((uint32_t)__half_as_ushort(b) << 16) | (uint32_t)__half_as_ushort(a);
}

// ---------------- LayerNorm (+ fp16 output) ----------------
__global__ void ln_kernel(const float* __restrict__ x,
                          const float* __restrict__ g,
                          const float* __restrict__ b,
                          float* __restrict__ out,
                          __half* __restrict__ oh) {
    int row = blockIdx.x;
    const float* xr = x + (size_t)row * DD;
    float s = 0.f, s2 = 0.f;
    for (int i = threadIdx.x; i < DD; i += 256) {
        float v = xr[i]; s += v; s2 += v * v;
    }
    for (int o = 16; o; o >>= 1) {
        s  += __shfl_xor_sync(0xffffffffu, s,  o);
        s2 += __shfl_xor_sync(0xffffffffu, s2, o);
    }
    __shared__ float ss[8], ss2[8];
    __shared__ float mu, rs;
    if ((threadIdx.x & 31) == 0) { ss[threadIdx.x >> 5] = s; ss2[threadIdx.x >> 5] = s2; }
    __syncthreads();
    if (threadIdx.x == 0) {
        float t = 0.f, t2 = 0.f;
        for (int i = 0; i < 8; i++) { t += ss[i]; t2 += ss2[i]; }
        float m = t / (float)DD;
        mu = m; rs = rsqrtf(t2 / (float)DD - m * m + 1e-5f);
    }
    __syncthreads();
    float m = mu, r = rs;
    for (int i = threadIdx.x; i < DD; i += 256) {
        float v = (xr[i] - m) * r * g[i] + b[i];
        if (out) out[(size_t)row * DD + i] = v;
        oh[(size_t)row * DD + i] = __float2half_rn(v);
    }
}

// ---------------- streaming weight convert: fp32 -> fp16 ----------------
__global__ void conv_stream(const float4* __restrict__ in,
                            uint2* __restrict__ oh, int n4) {
    for (int i = blockIdx.x * blockDim.x + threadIdx.x; i < n4;
         i += gridDim.x * blockDim.x) {
        float4 v = in[i];
        oh[i] = make_uint2(pack2h(__float2half_rn(v.x), __float2half_rn(v.y)),
                           pack2h(__float2half_rn(v.z), __float2half_rn(v.w)));
    }
}

// QKV: [H][D][HS] fp32 -> rows d of [1024][3072] fp16
__global__ void conv_qkv(const float* __restrict__ in,
                         __half* __restrict__ oh) {
    int idx = blockIdx.x * 256 + threadIdx.x;
    int hs4 = idx & 15;
    int d   = (idx >> 4) & 1023;
    int h   = idx >> 14;
    float4 v = *(const float4*)(in + (((size_t)h << 10) + d) * 64 + hs4 * 4);
    size_t o = (size_t)d * 3072 + h * 64 + hs4 * 4;
    *(uint2*)(oh + o) = make_uint2(pack2h(__float2half_rn(v.x), __float2half_rn(v.y)),
                                   pack2h(__float2half_rn(v.z), __float2half_rn(v.w)));
}

// ---------------- HMMA fp16 GEMM: 128x256 tile, warp 64x64, 1 MMA per frag ----------------
#define APLANE  10240            // 128 rows x 80B (32 k fp16 + pad)
#define BPLANE  16896            // 32 k-rows x 528B (256 cols fp16 + pad)
#define OBH     APLANE
#define BUFSZ   (APLANE + BPLANE)     // 27136
#define SMEM_BYTES (2*BUFSZ)          // 54272

template<int MODE>
__global__ void __launch_bounds__(256, 1)
hmma_gemm(const float* __restrict__ bias, const float* __restrict__ resid) {
    constexpr int KD  = (MODE == 3) ? DFF_ : DD;
    constexpr int LDN = (MODE == 0) ? 3 * DD : ((MODE == 2) ? DFF_ : DD);
    constexpr int NST = KD / 32;
    const int n0 = blockIdx.x * 256, m0 = blockIdx.y * 128, e = blockIdx.z;

    int cnt = 1 << 30, base = 0;
    const __half *Aw, *Bw;
    if (MODE == 0)      { Aw = g_xn;   Bw = g_wqkv; }
    else if (MODE == 1) { Aw = g_hd;   Bw = g_wp; }
    else if (MODE == 2) { Aw = g_xn2h; Bw = g_w1; }
    else                { Aw = g_h;    Bw = g_w2; }
    if (MODE == 2 || MODE == 3) {
        cnt = g_cnt[e];
        if (m0 >= cnt) return;
        base = g_base[e];
        Bw += (size_t)e * DD * DFF_;
    }

    extern __shared__ __align__(16) char smem[];
    const uint32_t sb = smem_u32(smem);
    const int tid = threadIdx.x;
    const int wid = tid >> 5, lane = tid & 31;
    const int wm = wid >> 2, wn = wid & 3;   // 2x4 warps, each 64m x 64n

    // ---- A load assignment: rows rloc & rloc+64, 16B chunk kc ----
    const int rloc = tid >> 2, kc = tid & 3;
    int gA0, gA1, vA0 = 1, vA1 = 1;
    {
        int i0 = m0 + rloc, i1 = m0 + rloc + 64;
        if (MODE == 2) {
            vA0 = i0 < cnt; vA1 = i1 < cnt;
            gA0 = vA0 ? g_tok[e * BT + i0] : 0;
            gA1 = vA1 ? g_tok[e * BT + i1] : 0;
        } else if (MODE == 3) {
            vA0 = i0 < cnt; vA1 = i1 < cnt;
            gA0 = base + (vA0 ? i0 : 0);
            gA1 = base + (vA1 ? i1 : 0);
        } else { gA0 = i0; gA1 = i1; }
    }
    const char* pA0 = (const char*)(Aw + (size_t)gA0 * KD) + kc * 16;
    const char* pA1 = (const char*)(Aw + (size_t)gA1 * KD) + kc * 16;
    const uint32_t ad0 = rloc * 80 + kc * 16;
    const uint32_t ad1 = (rloc + 64) * 80 + kc * 16;

    // ---- B load assignment: 32 k-rows x 512B; row=tid>>3, chunk bc, 4 chunks ----
    const int brow = tid >> 3, bc = tid & 7;
    const char* pB = (const char*)(Bw + (size_t)brow * LDN + n0 + bc * 8);
    const uint32_t bd0 = brow * 528 + bc * 16;

    // ---- ldmatrix lane addressing ----
    const uint32_t aoff = (uint32_t)((lane & 15) * 80 + (lane >> 4) * 16);
    const uint32_t blane = (uint32_t)((((lane >> 3) & 1) * 8 + (lane & 7)) * 528 + (lane >> 4) * 16);

    float c[4][8][4];
#pragma unroll
    for (int i = 0; i < 4; i++)
#pragma unroll
        for (int j = 0; j < 8; j++)
#pragma unroll
            for (int q = 0; q < 4; q++) c[i][j][q] = 0.f;

    auto issue = [&](int s) {
        const uint32_t bb = sb + (uint32_t)(s & 1) * BUFSZ;
        const size_t ao = (size_t)s * 64;                 // A: 32 k elems * 2B
        const size_t bo = (size_t)s * 32 * LDN * 2;       // B: 32 k-rows
        cpa16(bb + ad0, pA0 + ao, vA0);
        cpa16(bb + ad1, pA1 + ao, vA1);
#pragma unroll
        for (int j = 0; j < 4; j++)
            cpa16(bb + OBH + bd0 + j * 128, pB + bo + j * 128, 1);
        asm volatile("cp.async.commit_group;" ::: "memory");
    };

    issue(0);
#pragma unroll 1
    for (int s = 0; s < NST; s++) {
        if (s + 1 < NST) {
            issue(s + 1);
            asm volatile("cp.async.wait_group 1;" ::: "memory");
        } else {
            asm volatile("cp.async.wait_group 0;" ::: "memory");
        }
        __syncthreads();

        const uint32_t bb = sb + (uint32_t)(s & 1) * BUFSZ;
        const uint32_t abase = bb + (uint32_t)(wm * 64) * 80 + aoff;
        const uint32_t bbase = bb + OBH + blane + (uint32_t)wn * 128;   // 64 cols * 2B
#pragma unroll
        for (int kk = 0; kk < 2; kk++) {
            const uint32_t kbA = kk * 32;
            const uint32_t kbB = kk * 8448;     // 16 k-rows * 528B
            uint32_t aH[4][4], bH[8][2];
#pragma unroll
            for (int mt = 0; mt < 4; mt++)
                ldsm4(aH[mt], abase + mt * (16 * 80) + kbA);
#pragma unroll
            for (int nn = 0; nn < 4; nn++) {
                uint32_t r[4];
                ldsm4t(r, bbase + kbB + nn * 32);
                bH[2 * nn][0] = r[0]; bH[2 * nn][1] = r[1];
                bH[2 * nn + 1][0] = r[2]; bH[2 * nn + 1][1] = r[3];
            }
#pragma unroll
            for (int mt = 0; mt < 4; mt++)
#pragma unroll
                for (int nt = 0; nt < 8; nt++)
                    mma_h(c[mt][nt], aH[mt], bH[nt]);
        }
        __syncthreads();
    }

    // ---- epilogue ----
    const int gid = lane >> 2, tig = lane & 3;
#pragma unroll
    for (int mt = 0; mt < 4; mt++) {
#pragma unroll
        for (int nt = 0; nt < 8; nt++) {
            const int ng = n0 + wn * 64 + nt * 8 + tig * 2;
#pragma unroll
            for (int h = 0; h < 2; h++) {
                const int ml = wm * 64 + mt * 16 + gid + 8 * h;
                float v0 = c[mt][nt][2 * h], v1 = c[mt][nt][2 * h + 1];
                if (MODE == 0) {
                    const int m = m0 + ml;
                    const int which = ng >> 10, hh = (ng >> 6) & 15, hs = ng & 63;
                    const int bb_ = m >> 10, t = m & 1023;
                    float* outp = (which == 0) ? g_q : ((which == 1) ? g_k : g_v);
                    *(float2*)&outp[(((size_t)(bb_ * HH + hh)) * TT + t) * HSZ + hs] =
                        make_float2(v0, v1);
                } else if (MODE == 1) {
                    const int m = m0 + ml;
                    const size_t o = (size_t)m * DD + ng;
                    float2 rr = *(const float2*)&resid[o];
                    *(float2*)&g_x2[o] = make_float2(v0 + bias[ng] + rr.x,
                                                     v1 + bias[ng + 1] + rr.y);
                } else if (MODE == 2) {
                    const int i = m0 + ml;
                    if (i < cnt) {
                        float a0 = fmaxf(v0 + bias[(size_t)e * DFF_ + ng], 0.f);
                        float a1 = fmaxf(v1 + bias[(size_t)e * DFF_ + ng + 1], 0.f);
                        size_t idx = (size_t)(base + i) * DFF_ + ng;
                        *(uint32_t*)&g_h[idx] = pack2h(__float2half_rn(a0),
                                                       __float2half_rn(a1));
                    }
                } else {
                    const int i = m0 + ml;
                    if (i < cnt) {
                        *(float2*)&g_eo[(size_t)(base + i) * DD + ng] =
                            make_float2(v0 + bias[(size_t)e * DD + ng],
                                        v1 + bias[(size_t)e * DD + ng + 1]);
                    }
                }
            }
        }
    }
}

// ---------------- flash attention (fp32; fp16 output) ----------------
__global__ void __launch_bounds__(256, 1) attn_kernel() {
    __shared__ float Qs[64 * 64];
    __shared__ float Ks[64 * 64];
    __shared__ float Vs[64 * 64];
    const int bh = blockIdx.x;
    const int qt = blockIdx.y;
    const int tid = threadIdx.x;
    const int rt = tid >> 4, ct = tid & 15;

    const float* qb  = g_q + (size_t)bh * (TT * HSZ) + (size_t)qt * 64 * HSZ;
    const float* kb0 = g_k + (size_t)bh * (TT * HSZ);
    const float* vb0 = g_v + (size_t)bh * (TT * HSZ);

    for (int idx = tid; idx < 4096; idx += 256) {
        int t = idx >> 6, ee = idx & 63;
        Qs[ee * 64 + t] = qb[idx] * 0.03125f;
    }

    float m[4], l[4], O[4][4];
#pragma unroll
    for (int i = 0; i < 4; i++) {
        m[i] = -1e30f; l[i] = 0.f;
#pragma unroll
        for (int j = 0; j < 4; j++) O[i][j] = 0.f;
    }

    for (int kt = 0; kt < 16; kt++) {
        __syncthreads();
        const float* kb = kb0 + kt * 64 * HSZ;
        const float* vb = vb0 + kt * 64 * HSZ;
        for (int idx = tid; idx < 4096; idx += 256) {
            int s = idx >> 6, ee = idx & 63;
            Ks[ee * 64 + s] = kb[idx];
            Vs[idx] = vb[idx];
        }
        __syncthreads();

        float S[4][4];
#pragma unroll
        for (int i = 0; i < 4; i++)
#pragma unroll
            for (int j = 0; j < 4; j++) S[i][j] = 0.f;

#pragma unroll 8
        for (int kk = 0; kk < 64; kk++) {
            float4 a = *(float4*)&Qs[kk * 64 + rt * 4];
            float4 b = *(float4*)&Ks[kk * 64 + ct * 4];
            float av[4] = {a.x, a.y, a.z, a.w};
            float bv[4] = {b.x, b.y, b.z, b.w};
#pragma unroll
            for (int i = 0; i < 4; i++)
#pragma unroll
                for (int j = 0; j < 4; j++) S[i][j] += av[i] * bv[j];
        }

#pragma unroll
        for (int i = 0; i < 4; i++) {
            float mt = fmaxf(fmaxf(S[i][0], S[i][1]), fmaxf(S[i][2], S[i][3]));
            for (int o = 1; o < 16; o <<= 1)
                mt = fmaxf(mt, __shfl_xor_sync(0xffffffffu, mt, o));
            float mnew = fmaxf(m[i], mt);
            float alpha = __expf(m[i] - mnew);
            float rs = 0.f;
#pragma unroll
            for (int j = 0; j < 4; j++) {
                float p = __expf(S[i][j] - mnew);
                S[i][j] = p; rs += p;
            }
            for (int o = 1; o < 16; o <<= 1)
                rs += __shfl_xor_sync(0xffffffffu, rs, o);
            l[i] = l[i] * alpha + rs;
            m[i] = mnew;
#pragma unroll
            for (int j = 0; j < 4; j++) O[i][j] *= alpha;
        }

        __syncthreads();
#pragma unroll
        for (int j = 0; j < 4; j++) {
            float4 p = make_float4(S[0][j], S[1][j], S[2][j], S[3][j]);
            *(float4*)&Ks[(ct * 4 + j) * 64 + rt * 4] = p;
        }
        __syncthreads();

#pragma unroll 8
        for (int kk = 0; kk < 64; kk++) {
            float4 a = *(float4*)&Ks[kk * 64 + rt * 4];
            float4 b = *(float4*)&Vs[kk * 64 + ct * 4];
            float av[4] = {a.x, a.y, a.z, a.w};
            float bv[4] = {b.x, b.y, b.z, b.w};
#pragma unroll
            for (int i = 0; i < 4; i++)
#pragma unroll
                for (int j = 0; j < 4; j++) O[i][j] += av[i] * bv[j];
        }
    }

    const int b = bh >> 4, h = bh & 15;
#pragma unroll
    for (int i = 0; i < 4; i++) {
        float inv = 1.f / l[i];
        int t = qt * 64 + rt * 4 + i;
        size_t bidx = ((size_t)(b * TT + t)) * DD + h * HSZ + ct * 4;
#pragma unroll
        for (int j = 0; j < 4; j++)
            g_hd[bidx + j] = __float2half_rn(O[i][j] * inv);
    }
}

// ---------------- routing ----------------
__global__ void zero_cnt_kernel() {
    if (threadIdx.x < EE) g_cnt[threadIdx.x] = 0;
}

__global__ void route_kernel(const float* __restrict__ noise,
                             const float* __restrict__ w_route,
                             const float* __restrict__ b_route,
                             const float* __restrict__ w_noise,
                             const float* __restrict__ b_noise) {
    int tok = blockIdx.x;
    __shared__ float xs[DD];
    __shared__ float dots[16];
    for (int i = threadIdx.x; i < DD; i += 256)
        xs[i] = g_xn2[(size_t)tok * DD + i];
    __syncthreads();

    int j = threadIdx.x >> 4, lane = threadIdx.x & 15;
    const float* W = (j < 8) ? w_route : w_noise;
    int col = j & 7;
    float s = 0.f;
    for (int d = lane; d < DD; d += 16) s += xs[d] * W[(size_t)d * EE + col];
    for (int o = 8; o; o >>= 1) s += __shfl_down_sync(0xffffffffu, s, o, 16);
    if (lane == 0) dots[j] = s + ((j < 8) ? b_route[col] : b_noise[col]);
    __syncthreads();

    if (threadIdx.x == 0) {
        float noisy[EE];
        for (int ee = 0; ee < EE; ee++) {
            float nl = dots[8 + ee];
            float sp = (nl > 20.f) ? nl : log1pf(expf(nl));
            noisy[ee] = dots[ee] + noise[(size_t)tok * EE + ee] * sp;
        }
        int i1 = 0;
        for (int ee = 1; ee < EE; ee++) if (noisy[ee] > noisy[i1]) i1 = ee;
        int i2 = -1;
        for (int ee = 0; ee < EE; ee++) {
            if (ee == i1) continue;
            if (i2 < 0 || noisy[ee] > noisy[i2]) i2 = ee;
        }
        float e2 = expf(noisy[i2] - noisy[i1]);
        float inv = 1.f / (1.f + e2);
        float p1 = inv, p2 = e2 * inv;
        int pos1 = atomicAdd(&g_cnt[i1], 1);
        g_tok[i1 * BT + pos1] = tok;
        int pos2 = atomicAdd(&g_cnt[i2], 1);
        g_tok[i2 * BT + pos2] = tok;
        g_texp[tok * 2] = i1; g_tpos[tok * 2] = pos1; g_tgate[tok * 2] = p1;
        g_texp[tok * 2 + 1] = i2; g_tpos[tok * 2 + 1] = pos2; g_tgate[tok * 2 + 1] = p2;
    }
}

__global__ void scan_kernel() {
    if (threadIdx.x == 0) {
        int b = 0;
        for (int e = 0; e < EE; e++) { g_base[e] = b; b += g_cnt[e]; }
    }
}

// ---------------- final combine ----------------
__global__ void combine_kernel(float* __restrict__ out) {
    int tok = blockIdx.x;
    int e1 = g_texp[tok * 2], e2 = g_texp[tok * 2 + 1];
    float gt1 = g_tgate[tok * 2], gt2 = g_tgate[tok * 2 + 1];
    size_t s1 = (size_t)(g_base[e1] + g_tpos[tok * 2]) * DD;
    size_t s2 = (size_t)(g_base[e2] + g_tpos[tok * 2 + 1]) * DD;
    size_t o = (size_t)tok * DD;
    for (int i = threadIdx.x * 4; i < DD; i += 256 * 4) {
        float4 a = *(float4*)&g_xn2[o + i];
        float4 u = *(float4*)&g_eo[s1 + i];
        float4 w = *(float4*)&g_eo[s2 + i];
        float4 r = make_float4(a.x + gt1 * u.x + gt2 * w.x,
                               a.y + gt1 * u.y + gt2 * w.y,
                               a.z + gt1 * u.z + gt2 * w.z,
                               a.w + gt1 * u.w + gt2 * w.w);
        *(float4*)&out[o + i] = r;
    }
}

// ---------------- launch ----------------
extern "C" void kernel_launch(void* const* d_in, const int* in_sizes, int n_in,
                              void* d_out, int out_size) {
    const float* x       = (const float*)d_in[0];
    const float* noise   = (const float*)d_in[1];
    const float* ln1_g   = (const float*)d_in[2];
    const float* ln1_b   = (const float*)d_in[3];
    const float* wq      = (const float*)d_in[4];
    const float* wk      = (const float*)d_in[5];
    const float* wv      = (const float*)d_in[6];
    const float* w_proj  = (const float*)d_in[7];
    const float* b_proj  = (const float*)d_in[8];
    const float* ln2_g   = (const float*)d_in[9];
    const float* ln2_b   = (const float*)d_in[10];
    const float* w_route = (const float*)d_in[11];
    const float* b_route = (const float*)d_in[12];
    const float* w_noise = (const float*)d_in[13];
    const float* b_noise = (const float*)d_in[14];
    const float* w1      = (const float*)d_in[15];
    const float* b1      = (const float*)d_in[16];
    const float* w2      = (const float*)d_in[17];
    const float* b2      = (const float*)d_in[18];
    float* out = (float*)d_out;

    cudaFuncSetAttribute(hmma_gemm<0>, cudaFuncAttributeMaxDynamicSharedMemorySize, SMEM_BYTES);
    cudaFuncSetAttribute(hmma_gemm<1>, cudaFuncAttributeMaxDynamicSharedMemorySize, SMEM_BYTES);
    cudaFuncSetAttribute(hmma_gemm<2>, cudaFuncAttributeMaxDynamicSharedMemorySize, SMEM_BYTES);
    cudaFuncSetAttribute(hmma_gemm<3>, cudaFuncAttributeMaxDynamicSharedMemorySize, SMEM_BYTES);

    __half *xn, *xn2h, *wqkv, *wp, *w1h, *w2h;
    float *x2, *xn2;
    cudaGetSymbolAddress((void**)&xn,    g_xn);
    cudaGetSymbolAddress((void**)&xn2h,  g_xn2h);
    cudaGetSymbolAddress((void**)&wqkv,  g_wqkv);
    cudaGetSymbolAddress((void**)&wp,    g_wp);
    cudaGetSymbolAddress((void**)&w1h,   g_w1);
    cudaGetSymbolAddress((void**)&w2h,   g_w2);
    cudaGetSymbolAddress((void**)&x2,    g_x2);
    cudaGetSymbolAddress((void**)&xn2,   g_xn2);

    // --- launches ordered so ncu slot 5 = hmma_gemm<0> (QKV GEMM) ---
    conv_qkv<<<1024, 256>>>(wq, wqkv);                      // 0
    conv_qkv<<<1024, 256>>>(wk, wqkv + 1024);               // 1
    conv_qkv<<<1024, 256>>>(wv, wqkv + 2048);               // 2
    ln_kernel<<<BT, 256>>>(x, ln1_g, ln1_b, nullptr, xn);                       // 3
    conv_stream<<<1024, 256>>>((const float4*)w_proj, (uint2*)wp, DD * DD / 4); // 4
    hmma_gemm<0><<<dim3(12, 32, 1), 256, SMEM_BYTES>>>(nullptr, nullptr);       // 5 (profiled)

    // attention -> g_hd fp16
    attn_kernel<<<dim3(BB * HH, TT / 64), 256>>>();

    // out proj + bias + residual -> g_x2
    hmma_gemm<1><<<dim3(4, 32, 1), 256, SMEM_BYTES>>>(b_proj, x);

    // LN2 -> xn2 (fp32 + fp16)
    ln_kernel<<<BT, 256>>>(x2, ln2_g, ln2_b, xn2, xn2h);

    // routing
    zero_cnt_kernel<<<1, 32>>>();
    route_kernel<<<BT, 256>>>(noise, w_route, b_route, w_noise, b_noise);
    scan_kernel<<<1, 32>>>();

    // MoE weight conversion
    conv_stream<<<2048, 256>>>((const float4*)w1, (uint2*)w1h, EE * DD * DFF_ / 4);
    conv_stream<<<2048, 256>>>((const float4*)w2, (uint2*)w2h, EE * DFF_ * DD / 4);

    // MoE expert GEMMs
    hmma_gemm<2><<<dim3(16, 32, EE), 256, SMEM_BYTES>>>(b1, nullptr);
    hmma_gemm<3><<<dim3(4, 32, EE), 256, SMEM_BYTES>>>(b2, nullptr);

    // combine
    combine_kernel<<<BT, 256>>>(out);
}

// round 14
// speedup vs baseline: 3.1177x; 1.6802x over previous
#include <cuda_runtime.h>
#include <cuda_fp16.h>
#include <math.h>
#include <stdint.h>

#define BB   4
#define TT   1024
#define DD   1024
#define HH   16
#define HSZ  64
#define EE   8
#define DFF_ 4096
#define BT   4096
#define NSLOT (BT*2)

// ---------------- device scratch ----------------
__device__ float g_x2 [BT*DD];
__device__ float g_xn2[BT*DD];
__device__ float g_eo [NSLOT*DD];

__device__ __align__(16) __half g_qh  [BT*DD];
__device__ __align__(16) __half g_kh  [BT*DD];
__device__ __align__(16) __half g_vh  [BT*DD];
__device__ __align__(16) __half g_xn  [BT*DD];
__device__ __align__(16) __half g_hd  [BT*DD];
__device__ __align__(16) __half g_xn2h[BT*DD];
__device__ __align__(16) __half g_h   [NSLOT*DFF_];
__device__ __align__(16) __half g_wqkv[DD*3*DD];
__device__ __align__(16) __half g_wp  [DD*DD];
__device__ __align__(16) __half g_w1  [EE*DD*DFF_];
__device__ __align__(16) __half g_w2  [EE*DFF_*DD];

__device__ int   g_cnt [EE];
__device__ int   g_base[EE];
__device__ int   g_tok [EE*BT];
__device__ int   g_texp[BT*2];
__device__ int   g_tpos[BT*2];
__device__ float g_tgate[BT*2];

// ---------------- helpers ----------------
__device__ __forceinline__ uint32_t smem_u32(const void* p) {
    uint32_t a;
    asm("{ .reg .u64 t; cvta.to.shared.u64 t, %1; cvt.u32.u64 %0, t; }" : "=r"(a) : "l"(p));
    return a;
}
__device__ __forceinline__ void cpa16(uint32_t dst, const void* src, int valid) {
    asm volatile("cp.async.cg.shared.global [%0], [%1], 16, %2;"
                 :: "r"(dst), "l"(src), "r"(valid ? 16 : 0) : "memory");
}
__device__ __forceinline__ void ldsm4(uint32_t* r, uint32_t addr) {
    asm volatile("ldmatrix.sync.aligned.m8n8.x4.shared.b16 {%0,%1,%2,%3}, [%4];"
                 : "=r"(r[0]), "=r"(r[1]), "=r"(r[2]), "=r"(r[3]) : "r"(addr));
}
__device__ __forceinline__ void ldsm4t(uint32_t* r, uint32_t addr) {
    asm volatile("ldmatrix.sync.aligned.m8n8.x4.trans.shared.b16 {%0,%1,%2,%3}, [%4];"
                 : "=r"(r[0]), "=r"(r[1]), "=r"(r[2]), "=r"(r[3]) : "r"(addr));
}
__device__ __forceinline__ void mma_h(float* c, const uint32_t* a, const uint32_t* b) {
    asm volatile(
        "mma.sync.aligned.m16n8k16.row.col.f32.f16.f16.f32 "
        "{%0,%1,%2,%3},{%4,%5,%6,%7},{%8,%9},{%0,%1,%2,%3};"
        : "+f"(c[0]), "+f"(c[1]), "+f"(c[2]), "+f"(c[3])
        : "r"(a[0]), "r"(a[1]), "r"(a[2]), "r"(a[3]), "r"(b[0]), "r"(b[1]));
}
__device__ __forceinline__ uint32_t pack2h(__half a, __half b) {
    return ((uint32_t)__half_as_ushort(b) << 16) | (uint32_t)__half_as_ushort(a);
}

// ---------------- LayerNorm (+ fp16 output) ----------------
__global__ void ln_kernel(const float* __restrict__ x,
                          const float* __restrict__ g,
                          const float* __restrict__ b,
                          float* __restrict__ out,
                          __half* __restrict__ oh) {
    int row = blockIdx.x;
    const float* xr = x + (size_t)row * DD;
    float s = 0.f, s2 = 0.f;
    for (int i = threadIdx.x; i < DD; i += 256) {
        float v = xr[i]; s += v; s2 += v * v;
    }
    for (int o = 16; o; o >>= 1) {
        s  += __shfl_xor_sync(0xffffffffu, s,  o);
        s2 += __shfl_xor_sync(0xffffffffu, s2, o);
    }
    __shared__ float ss[8], ss2[8];
    __shared__ float mu, rs;
    if ((threadIdx.x & 31) == 0) { ss[threadIdx.x >> 5] = s; ss2[threadIdx.x >> 5] = s2; }
    __syncthreads();
    if (threadIdx.x == 0) {
        float t = 0.f, t2 = 0.f;
        for (int i = 0; i < 8; i++) { t += ss[i]; t2 += ss2[i]; }
        float m = t / (float)DD;
        mu = m; rs = rsqrtf(t2 / (float)DD - m * m + 1e-5f);
    }
    __syncthreads();
    float m = mu, r = rs;
    for (int i = threadIdx.x; i < DD; i += 256) {
        float v = (xr[i] - m) * r * g[i] + b[i];
        if (out) out[(size_t)row * DD + i] = v;
        oh[(size_t)row * DD + i] = __float2half_rn(v);
    }
}

// ---------------- streaming weight convert: fp32 -> fp16 ----------------
__global__ void conv_stream(const float4* __restrict__ in,
                            uint2* __restrict__ oh, int n4) {
    for (int i = blockIdx.x * blockDim.x + threadIdx.x; i < n4;
         i += gridDim.x * blockDim.x) {
        float4 v = in[i];
        oh[i] = make_uint2(pack2h(__float2half_rn(v.x), __float2half_rn(v.y)),
                           pack2h(__float2half_rn(v.z), __float2half_rn(v.w)));
    }
}

// QKV: [H][D][HS] fp32 -> rows d of [1024][3072] fp16
__global__ void conv_qkv(const float* __restrict__ in,
                         __half* __restrict__ oh) {
    int idx = blockIdx.x * 256 + threadIdx.x;
    int hs4 = idx & 15;
    int d   = (idx >> 4) & 1023;
    int h   = idx >> 14;
    float4 v = *(const float4*)(in + (((size_t)h << 10) + d) * 64 + hs4 * 4);
    size_t o = (size_t)d * 3072 + h * 64 + hs4 * 4;
    *(uint2*)(oh + o) = make_uint2(pack2h(__float2half_rn(v.x), __float2half_rn(v.y)),
                                   pack2h(__float2half_rn(v.z), __float2half_rn(v.w)));
}

// ---------------- HMMA fp16 GEMM: 128x256 tile, warp 64x64 ----------------
#define APLANE  10240
#define BPLANE  16896
#define OBH     APLANE
#define BUFSZ   (APLANE + BPLANE)
#define SMEM_BYTES (2*BUFSZ)

template<int MODE>
__global__ void __launch_bounds__(256, 1)
hmma_gemm(const float* __restrict__ bias, const float* __restrict__ resid) {
    constexpr int KD  = (MODE == 3) ? DFF_ : DD;
    constexpr int LDN = (MODE == 0) ? 3 * DD : ((MODE == 2) ? DFF_ : DD);
    constexpr int NST = KD / 32;
    const int n0 = blockIdx.x * 256, m0 = blockIdx.y * 128, e = blockIdx.z;

    int cnt = 1 << 30, base = 0;
    const __half *Aw, *Bw;
    if (MODE == 0)      { Aw = g_xn;   Bw = g_wqkv; }
    else if (MODE == 1) { Aw = g_hd;   Bw = g_wp; }
    else if (MODE == 2) { Aw = g_xn2h; Bw = g_w1; }
    else                { Aw = g_h;    Bw = g_w2; }
    if (MODE == 2 || MODE == 3) {
        cnt = g_cnt[e];
        if (m0 >= cnt) return;
        base = g_base[e];
        Bw += (size_t)e * DD * DFF_;
    }

    extern __shared__ __align__(16) char smem[];
    const uint32_t sb = smem_u32(smem);
    const int tid = threadIdx.x;
    const int wid = tid >> 5, lane = tid & 31;
    const int wm = wid >> 2, wn = wid & 3;

    const int rloc = tid >> 2, kc = tid & 3;
    int gA0, gA1, vA0 = 1, vA1 = 1;
    {
        int i0 = m0 + rloc, i1 = m0 + rloc + 64;
        if (MODE == 2) {
            vA0 = i0 < cnt; vA1 = i1 < cnt;
            gA0 = vA0 ? g_tok[e * BT + i0] : 0;
            gA1 = vA1 ? g_tok[e * BT + i1] : 0;
        } else if (MODE == 3) {
            vA0 = i0 < cnt; vA1 = i1 < cnt;
            gA0 = base + (vA0 ? i0 : 0);
            gA1 = base + (vA1 ? i1 : 0);
        } else { gA0 = i0; gA1 = i1; }
    }
    const char* pA0 = (const char*)(Aw + (size_t)gA0 * KD) + kc * 16;
    const char* pA1 = (const char*)(Aw + (size_t)gA1 * KD) + kc * 16;
    const uint32_t ad0 = rloc * 80 + kc * 16;
    const uint32_t ad1 = (rloc + 64) * 80 + kc * 16;

    const int brow = tid >> 3, bc = tid & 7;
    const char* pB = (const char*)(Bw + (size_t)brow * LDN + n0 + bc * 8);
    const uint32_t bd0 = brow * 528 + bc * 16;

    const uint32_t aoff = (uint32_t)((lane & 15) * 80 + (lane >> 4) * 16);
    const uint32_t blane = (uint32_t)((((lane >> 3) & 1) * 8 + (lane & 7)) * 528 + (lane >> 4) * 16);

    float c[4][8][4];
#pragma unroll
    for (int i = 0; i < 4; i++)
#pragma unroll
        for (int j = 0; j < 8; j++)
#pragma unroll
            for (int q = 0; q < 4; q++) c[i][j][q] = 0.f;

    auto issue = [&](int s) {
        const uint32_t bb = sb + (uint32_t)(s & 1) * BUFSZ;
        const size_t ao = (size_t)s * 64;
        const size_t bo = (size_t)s * 32 * LDN * 2;
        cpa16(bb + ad0, pA0 + ao, vA0);
        cpa16(bb + ad1, pA1 + ao, vA1);
#pragma unroll
        for (int j = 0; j < 4; j++)
            cpa16(bb + OBH + bd0 + j * 128, pB + bo + j * 128, 1);
        asm volatile("cp.async.commit_group;" ::: "memory");
    };

    issue(0);
#pragma unroll 1
    for (int s = 0; s < NST; s++) {
        if (s + 1 < NST) {
            issue(s + 1);
            asm volatile("cp.async.wait_group 1;" ::: "memory");
        } else {
            asm volatile("cp.async.wait_group 0;" ::: "memory");
        }
        __syncthreads();

        const uint32_t bb = sb + (uint32_t)(s & 1) * BUFSZ;
        const uint32_t abase = bb + (uint32_t)(wm * 64) * 80 + aoff;
        const uint32_t bbase = bb + OBH + blane + (uint32_t)wn * 128;
#pragma unroll
        for (int kk = 0; kk < 2; kk++) {
            const uint32_t kbA = kk * 32;
            const uint32_t kbB = kk * 8448;
            uint32_t aH[4][4], bH[8][2];
#pragma unroll
            for (int mt = 0; mt < 4; mt++)
                ldsm4(aH[mt], abase + mt * (16 * 80) + kbA);
#pragma unroll
            for (int nn = 0; nn < 4; nn++) {
                uint32_t r[4];
                ldsm4t(r, bbase + kbB + nn * 32);
                bH[2 * nn][0] = r[0]; bH[2 * nn][1] = r[1];
                bH[2 * nn + 1][0] = r[2]; bH[2 * nn + 1][1] = r[3];
            }
#pragma unroll
            for (int mt = 0; mt < 4; mt++)
#pragma unroll
                for (int nt = 0; nt < 8; nt++)
                    mma_h(c[mt][nt], aH[mt], bH[nt]);
        }
        __syncthreads();
    }

    const int gid = lane >> 2, tig = lane & 3;
#pragma unroll
    for (int mt = 0; mt < 4; mt++) {
#pragma unroll
        for (int nt = 0; nt < 8; nt++) {
            const int ng = n0 + wn * 64 + nt * 8 + tig * 2;
#pragma unroll
            for (int h = 0; h < 2; h++) {
                const int ml = wm * 64 + mt * 16 + gid + 8 * h;
                float v0 = c[mt][nt][2 * h], v1 = c[mt][nt][2 * h + 1];
                if (MODE == 0) {
                    const int m = m0 + ml;
                    const int which = ng >> 10, hh = (ng >> 6) & 15, hs = ng & 63;
                    const int bb_ = m >> 10, t = m & 1023;
                    float sc = (which == 0) ? 0.03125f : 1.0f;
                    __half* outp = (which == 0) ? g_qh : ((which == 1) ? g_kh : g_vh);
                    size_t idx = (((size_t)(bb_ * HH + hh)) * TT + t) * HSZ + hs;
                    *(uint32_t*)&outp[idx] = pack2h(__float2half_rn(v0 * sc),
                                                    __float2half_rn(v1 * sc));
                } else if (MODE == 1) {
                    const int m = m0 + ml;
                    const size_t o = (size_t)m * DD + ng;
                    float2 rr = *(const float2*)&resid[o];
                    *(float2*)&g_x2[o] = make_float2(v0 + bias[ng] + rr.x,
                                                     v1 + bias[ng + 1] + rr.y);
                } else if (MODE == 2) {
                    const int i = m0 + ml;
                    if (i < cnt) {
                        float a0 = fmaxf(v0 + bias[(size_t)e * DFF_ + ng], 0.f);
                        float a1 = fmaxf(v1 + bias[(size_t)e * DFF_ + ng + 1], 0.f);
                        size_t idx = (size_t)(base + i) * DFF_ + ng;
                        *(uint32_t*)&g_h[idx] = pack2h(__float2half_rn(a0),
                                                       __float2half_rn(a1));
                    }
                } else {
                    const int i = m0 + ml;
                    if (i < cnt) {
                        *(float2*)&g_eo[(size_t)(base + i) * DD + ng] =
                            make_float2(v0 + bias[(size_t)e * DD + ng],
                                        v1 + bias[(size_t)e * DD + ng + 1]);
                    }
                }
            }
        }
    }
}

// ---------------- HMMA fp16 flash attention: 64q x 64s tiles ----------------
// smem: Q[0,9216) ; K0[9216,18432) V0[18432,27648) ; K1[27648,36864) V1[36864,46080)
#define ASTR 144

__global__ void __launch_bounds__(128, 1) attn_kernel() {
    __shared__ __align__(16) char sma[46080];
    const uint32_t sb = smem_u32(sma);
    const int tid = threadIdx.x;
    const int wid = tid >> 5, lane = tid & 31;
    const int bh = blockIdx.x, qt = blockIdx.y;

    const __half* qb  = g_qh + (size_t)bh * TT * HSZ + (size_t)qt * 64 * HSZ;
    const __half* kb0 = g_kh + (size_t)bh * TT * HSZ;
    const __half* vb0 = g_vh + (size_t)bh * TT * HSZ;

    const int row = tid >> 1, cb = (tid & 1) * 64;

    // Q load (once)
    {
        const char* src = (const char*)qb + row * 128 + cb;
#pragma unroll
        for (int j = 0; j < 4; j++)
            *(uint4*)(sma + row * ASTR + cb + j * 16) = *(const uint4*)(src + j * 16);
    }

    auto issueKV = [&](int kt) {
        const uint32_t base = sb + 9216 + (uint32_t)(kt & 1) * 18432;
        const char* ks = (const char*)(kb0 + (size_t)kt * 64 * HSZ) + row * 128 + cb;
        const char* vs = (const char*)(vb0 + (size_t)kt * 64 * HSZ) + row * 128 + cb;
#pragma unroll
        for (int j = 0; j < 4; j++) {
            cpa16(base + row * ASTR + cb + j * 16, ks + j * 16, 1);
            cpa16(base + 9216 + row * ASTR + cb + j * 16, vs + j * 16, 1);
        }
        asm volatile("cp.async.commit_group;" ::: "memory");
    };

    const uint32_t aoff = (uint32_t)(wid * 16 * ASTR + (lane & 15) * ASTR + (lane >> 4) * 16);
    const uint32_t kbo  = (uint32_t)(((lane & 7) + ((lane >> 4) << 3)) * ASTR + (((lane >> 3) & 1) << 4));
    const uint32_t vbo  = (uint32_t)(((((lane >> 3) & 1) << 3) + (lane & 7)) * ASTR + ((lane >> 4) << 4));

    float O[8][4];
#pragma unroll
    for (int nt = 0; nt < 8; nt++)
#pragma unroll
        for (int q = 0; q < 4; q++) O[nt][q] = 0.f;
    float m0 = -1e30f, m1 = -1e30f, l0 = 0.f, l1 = 0.f;

    issueKV(0);
#pragma unroll 1
    for (int kt = 0; kt < 16; kt++) {
        if (kt + 1 < 16) {
            issueKV(kt + 1);
            asm volatile("cp.async.wait_group 1;" ::: "memory");
        } else {
            asm volatile("cp.async.wait_group 0;" ::: "memory");
        }
        __syncthreads();

        const uint32_t kbase = sb + 9216 + (uint32_t)(kt & 1) * 18432;
        const uint32_t vbase = kbase + 9216;

        // ---- S = Q K^T ----
        float S[8][4];
#pragma unroll
        for (int nt = 0; nt < 8; nt++)
#pragma unroll
            for (int q = 0; q < 4; q++) S[nt][q] = 0.f;
#pragma unroll
        for (int kc = 0; kc < 4; kc++) {
            uint32_t aH[4], bK[8][2];
            ldsm4(aH, sb + aoff + kc * 32);
#pragma unroll
            for (int nn = 0; nn < 4; nn++) {
                uint32_t r[4];
                ldsm4(r, kbase + kbo + nn * (16 * ASTR) + kc * 32);
                bK[2 * nn][0] = r[0]; bK[2 * nn][1] = r[1];
                bK[2 * nn + 1][0] = r[2]; bK[2 * nn + 1][1] = r[3];
            }
#pragma unroll
            for (int nt = 0; nt < 8; nt++)
                mma_h(S[nt], aH, bK[nt]);
        }

        // ---- online softmax (rows lane>>2 and +8) ----
        float mx0 = -1e30f, mx1 = -1e30f;
#pragma unroll
        for (int nt = 0; nt < 8; nt++) {
            mx0 = fmaxf(mx0, fmaxf(S[nt][0], S[nt][1]));
            mx1 = fmaxf(mx1, fmaxf(S[nt][2], S[nt][3]));
        }
        mx0 = fmaxf(mx0, __shfl_xor_sync(0xffffffffu, mx0, 1));
        mx0 = fmaxf(mx0, __shfl_xor_sync(0xffffffffu, mx0, 2));
        mx1 = fmaxf(mx1, __shfl_xor_sync(0xffffffffu, mx1, 1));
        mx1 = fmaxf(mx1, __shfl_xor_sync(0xffffffffu, mx1, 2));
        float mn0 = fmaxf(m0, mx0), mn1 = fmaxf(m1, mx1);
        float al0 = __expf(m0 - mn0), al1 = __expf(m1 - mn1);
        float rs0 = 0.f, rs1 = 0.f;
        uint32_t ph[8][2];
#pragma unroll
        for (int nt = 0; nt < 8; nt++) {
            float p0 = __expf(S[nt][0] - mn0), p1 = __expf(S[nt][1] - mn0);
            float p2 = __expf(S[nt][2] - mn1), p3 = __expf(S[nt][3] - mn1);
            rs0 += p0 + p1; rs1 += p2 + p3;
            ph[nt][0] = pack2h(__float2half_rn(p0), __float2half_rn(p1));
            ph[nt][1] = pack2h(__float2half_rn(p2), __float2half_rn(p3));
        }
        rs0 += __shfl_xor_sync(0xffffffffu, rs0, 1);
        rs0 += __shfl_xor_sync(0xffffffffu, rs0, 2);
        rs1 += __shfl_xor_sync(0xffffffffu, rs1, 1);
        rs1 += __shfl_xor_sync(0xffffffffu, rs1, 2);
        l0 = l0 * al0 + rs0; l1 = l1 * al1 + rs1;
        m0 = mn0; m1 = mn1;
#pragma unroll
        for (int nt = 0; nt < 8; nt++) {
            O[nt][0] *= al0; O[nt][1] *= al0;
            O[nt][2] *= al1; O[nt][3] *= al1;
        }

        // ---- O += P V ----
#pragma unroll
        for (int kc = 0; kc < 4; kc++) {
            uint32_t aP[4] = {ph[2 * kc][0], ph[2 * kc][1],
                              ph[2 * kc + 1][0], ph[2 * kc + 1][1]};
            uint32_t bV[8][2];
#pragma unroll
            for (int nn = 0; nn < 4; nn++) {
                uint32_t r[4];
                ldsm4t(r, vbase + vbo + kc * (16 * ASTR) + nn * 32);
                bV[2 * nn][0] = r[0]; bV[2 * nn][1] = r[1];
                bV[2 * nn + 1][0] = r[2]; bV[2 * nn + 1][1] = r[3];
            }
#pragma unroll
            for (int nt = 0; nt < 8; nt++)
                mma_h(O[nt], aP, bV[nt]);
        }
        __syncthreads();
    }

    // ---- epilogue: O / l -> g_hd fp16 ----
    const int b = bh >> 4, head = bh & 15;
    const float inv0 = 1.f / l0, inv1 = 1.f / l1;
    const int r0 = qt * 64 + wid * 16 + (lane >> 2);
#pragma unroll
    for (int nt = 0; nt < 8; nt++) {
        const int col = head * 64 + nt * 8 + (lane & 3) * 2;
#pragma unroll
        for (int h = 0; h < 2; h++) {
            const int t = r0 + 8 * h;
            float inv = h ? inv1 : inv0;
            size_t idx = ((size_t)(b * TT + t)) * DD + col;
            *(uint32_t*)&g_hd[idx] = pack2h(__float2half_rn(O[nt][2 * h] * inv),
                                            __float2half_rn(O[nt][2 * h + 1] * inv));
        }
    }
}

// ---------------- routing ----------------
__global__ void zero_cnt_kernel() {
    if (threadIdx.x < EE) g_cnt[threadIdx.x] = 0;
}

__global__ void route_kernel(const float* __restrict__ noise,
                             const float* __restrict__ w_route,
                             const float* __restrict__ b_route,
                             const float* __restrict__ w_noise,
                             const float* __restrict__ b_noise) {
    int tok = blockIdx.x;
    __shared__ float xs[DD];
    __shared__ float dots[16];
    for (int i = threadIdx.x; i < DD; i += 256)
        xs[i] = g_xn2[(size_t)tok * DD + i];
    __syncthreads();

    int j = threadIdx.x >> 4, lane = threadIdx.x & 15;
    const float* W = (j < 8) ? w_route : w_noise;
    int col = j & 7;
    float s = 0.f;
    for (int d = lane; d < DD; d += 16) s += xs[d] * W[(size_t)d * EE + col];
    for (int o = 8; o; o >>= 1) s += __shfl_down_sync(0xffffffffu, s, o, 16);
    if (lane == 0) dots[j] = s + ((j < 8) ? b_route[col] : b_noise[col]);
    __syncthreads();

    if (threadIdx.x == 0) {
        float noisy[EE];
        for (int ee = 0; ee < EE; ee++) {
            float nl = dots[8 + ee];
            float sp = (nl > 20.f) ? nl : log1pf(expf(nl));
            noisy[ee] = dots[ee] + noise[(size_t)tok * EE + ee] * sp;
        }
        int i1 = 0;
        for (int ee = 1; ee < EE; ee++) if (noisy[ee] > noisy[i1]) i1 = ee;
        int i2 = -1;
        for (int ee = 0; ee < EE; ee++) {
            if (ee == i1) continue;
            if (i2 < 0 || noisy[ee] > noisy[i2]) i2 = ee;
        }
        float e2 = expf(noisy[i2] - noisy[i1]);
        float inv = 1.f / (1.f + e2);
        float p1 = inv, p2 = e2 * inv;
        int pos1 = atomicAdd(&g_cnt[i1], 1);
        g_tok[i1 * BT + pos1] = tok;
        int pos2 = atomicAdd(&g_cnt[i2], 1);
        g_tok[i2 * BT + pos2] = tok;
        g_texp[tok * 2] = i1; g_tpos[tok * 2] = pos1; g_tgate[tok * 2] = p1;
        g_texp[tok * 2 + 1] = i2; g_tpos[tok * 2 + 1] = pos2; g_tgate[tok * 2 + 1] = p2;
    }
}

__global__ void scan_kernel() {
    if (threadIdx.x == 0) {
        int b = 0;
        for (int e = 0; e < EE; e++) { g_base[e] = b; b += g_cnt[e]; }
    }
}

// ---------------- final combine ----------------
__global__ void combine_kernel(float* __restrict__ out) {
    int tok = blockIdx.x;
    int e1 = g_texp[tok * 2], e2 = g_texp[tok * 2 + 1];
    float gt1 = g_tgate[tok * 2], gt2 = g_tgate[tok * 2 + 1];
    size_t s1 = (size_t)(g_base[e1] + g_tpos[tok * 2]) * DD;
    size_t s2 = (size_t)(g_base[e2] + g_tpos[tok * 2 + 1]) * DD;
    size_t o = (size_t)tok * DD;
    for (int i = threadIdx.x * 4; i < DD; i += 256 * 4) {
        float4 a = *(float4*)&g_xn2[o + i];
        float4 u = *(float4*)&g_eo[s1 + i];
        float4 w = *(float4*)&g_eo[s2 + i];
        float4 r = make_float4(a.x + gt1 * u.x + gt2 * w.x,
                               a.y + gt1 * u.y + gt2 * w.y,
                               a.z + gt1 * u.z + gt2 * w.z,
                               a.w + gt1 * u.w + gt2 * w.w);
        *(float4*)&out[o + i] = r;
    }
}

// ---------------- launch ----------------
extern "C" void kernel_launch(void* const* d_in, const int* in_sizes, int n_in,
                              void* d_out, int out_size) {
    const float* x       = (const float*)d_in[0];
    const float* noise   = (const float*)d_in[1];
    const float* ln1_g   = (const float*)d_in[2];
    const float* ln1_b   = (const float*)d_in[3];
    const float* wq      = (const float*)d_in[4];
    const float* wk      = (const float*)d_in[5];
    const float* wv      = (const float*)d_in[6];
    const float* w_proj  = (const float*)d_in[7];
    const float* b_proj  = (const float*)d_in[8];
    const float* ln2_g   = (const float*)d_in[9];
    const float* ln2_b   = (const float*)d_in[10];
    const float* w_route = (const float*)d_in[11];
    const float* b_route = (const float*)d_in[12];
    const float* w_noise = (const float*)d_in[13];
    const float* b_noise = (const float*)d_in[14];
    const float* w1      = (const float*)d_in[15];
    const float* b1      = (const float*)d_in[16];
    const float* w2      = (const float*)d_in[17];
    const float* b2      = (const float*)d_in[18];
    float* out = (float*)d_out;

    cudaFuncSetAttribute(hmma_gemm<0>, cudaFuncAttributeMaxDynamicSharedMemorySize, SMEM_BYTES);
    cudaFuncSetAttribute(hmma_gemm<1>, cudaFuncAttributeMaxDynamicSharedMemorySize, SMEM_BYTES);
    cudaFuncSetAttribute(hmma_gemm<2>, cudaFuncAttributeMaxDynamicSharedMemorySize, SMEM_BYTES);
    cudaFuncSetAttribute(hmma_gemm<3>, cudaFuncAttributeMaxDynamicSharedMemorySize, SMEM_BYTES);

    __half *xn, *xn2h, *wqkv, *wp, *w1h, *w2h;
    float *x2, *xn2;
    cudaGetSymbolAddress((void**)&xn,    g_xn);
    cudaGetSymbolAddress((void**)&xn2h,  g_xn2h);
    cudaGetSymbolAddress((void**)&wqkv,  g_wqkv);
    cudaGetSymbolAddress((void**)&wp,    g_wp);
    cudaGetSymbolAddress((void**)&w1h,   g_w1);
    cudaGetSymbolAddress((void**)&w2h,   g_w2);
    cudaGetSymbolAddress((void**)&x2,    g_x2);
    cudaGetSymbolAddress((void**)&xn2,   g_xn2);

    // --- launches ordered so ncu slot 5 = hmma_gemm<0>, 6 = attn ---
    conv_qkv<<<1024, 256>>>(wq, wqkv);                      // 0
    conv_qkv<<<1024, 256>>>(wk, wqkv + 1024);               // 1
    conv_qkv<<<1024, 256>>>(wv, wqkv + 2048);               // 2
    ln_kernel<<<BT, 256>>>(x, ln1_g, ln1_b, nullptr, xn);                       // 3
    conv_stream<<<1024, 256>>>((const float4*)w_proj, (uint2*)wp, DD * DD / 4); // 4
    hmma_gemm<0><<<dim3(12, 32, 1), 256, SMEM_BYTES>>>(nullptr, nullptr);       // 5

    // fp16 HMMA flash attention -> g_hd
    attn_kernel<<<dim3(BB * HH, TT / 64), 128>>>();                             // 6

    // out proj + bias + residual -> g_x2
    hmma_gemm<1><<<dim3(4, 32, 1), 256, SMEM_BYTES>>>(b_proj, x);

    // LN2 -> xn2 (fp32 + fp16)
    ln_kernel<<<BT, 256>>>(x2, ln2_g, ln2_b, xn2, xn2h);

    // routing
    zero_cnt_kernel<<<1, 32>>>();
    route_kernel<<<BT, 256>>>(noise, w_route, b_route, w_noise, b_noise);
    scan_kernel<<<1, 32>>>();

    // MoE weight conversion
    conv_stream<<<2048, 256>>>((const float4*)w1, (uint2*)w1h, EE * DD * DFF_ / 4);
    conv_stream<<<2048, 256>>>((const float4*)w2, (uint2*)w2h, EE * DFF_ * DD / 4);

    // MoE expert GEMMs
    hmma_gemm<2><<<dim3(16, 32, EE), 256, SMEM_BYTES>>>(b1, nullptr);
    hmma_gemm<3><<<dim3(4, 32, EE), 256, SMEM_BYTES>>>(b2, nullptr);

    // combine
    combine_kernel<<<BT, 256>>>(out);
}

// round 15
// speedup vs baseline: 3.3108x; 1.0619x over previous
#include <cuda_runtime.h>
#include <cuda_fp16.h>
#include <math.h>
#include <stdint.h>

#define BB   4
#define TT   1024
#define DD   1024
#define HH   16
#define HSZ  64
#define EE   8
#define DFF_ 4096
#define BT   4096
#define NSLOT (BT*2)

// ---------------- device scratch ----------------
__device__ float g_x2 [BT*DD];
__device__ float g_xn2[BT*DD];
__device__ float g_eo [NSLOT*DD];

__device__ __align__(16) __half g_qh  [BT*DD];
__device__ __align__(16) __half g_kh  [BT*DD];
__device__ __align__(16) __half g_vh  [BT*DD];
__device__ __align__(16) __half g_xn  [BT*DD];
__device__ __align__(16) __half g_hd  [BT*DD];
__device__ __align__(16) __half g_xn2h[BT*DD];
__device__ __align__(16) __half g_h   [NSLOT*DFF_];
__device__ __align__(16) __half g_wqkv[DD*3*DD];
__device__ __align__(16) __half g_wp  [DD*DD];
__device__ __align__(16) __half g_w1  [EE*DD*DFF_];
__device__ __align__(16) __half g_w2  [EE*DFF_*DD];

__device__ int   g_cnt [EE];
__device__ int   g_base[EE];
__device__ int   g_tok [EE*BT];
__device__ int   g_texp[BT*2];
__device__ int   g_tpos[BT*2];
__device__ float g_tgate[BT*2];

// ---------------- helpers ----------------
__device__ __forceinline__ uint32_t smem_u32(const void* p) {
    uint32_t a;
    asm("{ .reg .u64 t; cvta.to.shared.u64 t, %1; cvt.u32.u64 %0, t; }" : "=r"(a) : "l"(p));
    return a;
}
__device__ __forceinline__ void cpa16(uint32_t dst, const void* src, int valid) {
    asm volatile("cp.async.cg.shared.global [%0], [%1], 16, %2;"
                 :: "r"(dst), "l"(src), "r"(valid ? 16 : 0) : "memory");
}
__device__ __forceinline__ void ldsm4(uint32_t* r, uint32_t addr) {
    asm volatile("ldmatrix.sync.aligned.m8n8.x4.shared.b16 {%0,%1,%2,%3}, [%4];"
                 : "=r"(r[0]), "=r"(r[1]), "=r"(r[2]), "=r"(r[3]) : "r"(addr));
}
__device__ __forceinline__ void ldsm4t(uint32_t* r, uint32_t addr) {
    asm volatile("ldmatrix.sync.aligned.m8n8.x4.trans.shared.b16 {%0,%1,%2,%3}, [%4];"
                 : "=r"(r[0]), "=r"(r[1]), "=r"(r[2]), "=r"(r[3]) : "r"(addr));
}
__device__ __forceinline__ void mma_h(float* c, const uint32_t* a, const uint32_t* b) {
    asm volatile(
        "mma.sync.aligned.m16n8k16.row.col.f32.f16.f16.f32 "
        "{%0,%1,%2,%3},{%4,%5,%6,%7},{%8,%9},{%0,%1,%2,%3};"
        : "+f"(c[0]), "+f"(c[1]), "+f"(c[2]), "+f"(c[3])
        : "r"(a[0]), "r"(a[1]), "r"(a[2]), "r"(a[3]), "r"(b[0]), "r"(b[1]));
}
__device__ __forceinline__ uint32_t pack2h(__half a, __half b) {
    return ((uint32_t)__half_as_ushort(b) << 16) | (uint32_t)__half_as_ushort(a);
}

// ---------------- LayerNorm (+ fp16 output) ----------------
__global__ void ln_kernel(const float* __restrict__ x,
                          const float* __restrict__ g,
                          const float* __restrict__ b,
                          float* __restrict__ out,
                          __half* __restrict__ oh) {
    int row = blockIdx.x;
    const float* xr = x + (size_t)row * DD;
    float s = 0.f, s2 = 0.f;
    for (int i = threadIdx.x; i < DD; i += 256) {
        float v = xr[i]; s += v; s2 += v * v;
    }
    for (int o = 16; o; o >>= 1) {
        s  += __shfl_xor_sync(0xffffffffu, s,  o);
        s2 += __shfl_xor_sync(0xffffffffu, s2, o);
    }
    __shared__ float ss[8], ss2[8];
    __shared__ float mu, rs;
    if ((threadIdx.x & 31) == 0) { ss[threadIdx.x >> 5] = s; ss2[threadIdx.x >> 5] = s2; }
    __syncthreads();
    if (threadIdx.x == 0) {
        float t = 0.f, t2 = 0.f;
        for (int i = 0; i < 8; i++) { t += ss[i]; t2 += ss2[i]; }
        float m = t / (float)DD;
        mu = m; rs = rsqrtf(t2 / (float)DD - m * m + 1e-5f);
    }
    __syncthreads();
    float m = mu, r = rs;
    for (int i = threadIdx.x; i < DD; i += 256) {
        float v = (xr[i] - m) * r * g[i] + b[i];
        if (out) out[(size_t)row * DD + i] = v;
        oh[(size_t)row * DD + i] = __float2half_rn(v);
    }
}

// ---------------- streaming weight convert: fp32 -> fp16 ----------------
__global__ void conv_stream(const float4* __restrict__ in,
                            uint2* __restrict__ oh, int n4) {
    for (int i = blockIdx.x * blockDim.x + threadIdx.x; i < n4;
         i += gridDim.x * blockDim.x) {
        float4 v = in[i];
        oh[i] = make_uint2(pack2h(__float2half_rn(v.x), __float2half_rn(v.y)),
                           pack2h(__float2half_rn(v.z), __float2half_rn(v.w)));
    }
}

// QKV: [H][D][HS] fp32 -> rows d of [1024][3072] fp16
__global__ void conv_qkv(const float* __restrict__ in,
                         __half* __restrict__ oh) {
    int idx = blockIdx.x * 256 + threadIdx.x;
    int hs4 = idx & 15;
    int d   = (idx >> 4) & 1023;
    int h   = idx >> 14;
    float4 v = *(const float4*)(in + (((size_t)h << 10) + d) * 64 + hs4 * 4);
    size_t o = (size_t)d * 3072 + h * 64 + hs4 * 4;
    *(uint2*)(oh + o) = make_uint2(pack2h(__float2half_rn(v.x), __float2half_rn(v.y)),
                                   pack2h(__float2half_rn(v.z), __float2half_rn(v.w)));
}

// ---------------- HMMA fp16 GEMM: 128x256 tile, warp 64x64, K=64/stage ----------------
// Buffer layout: [A0 10240][A1 10240][B0 16896][B1 16896]  (two 32-k sub-blocks)
#define APL 10240
#define BPL 16896
#define OB0 (2*APL)
#define OB1 (2*APL + BPL)
#define BUFSZ (2*APL + 2*BPL)          // 54272
#define SMEM_BYTES (2*BUFSZ)           // 108544

template<int MODE>
__global__ void __launch_bounds__(256, 1)
hmma_gemm(const float* __restrict__ bias, const float* __restrict__ resid) {
    constexpr int KD  = (MODE == 3) ? DFF_ : DD;
    constexpr int LDN = (MODE == 0) ? 3 * DD : ((MODE == 2) ? DFF_ : DD);
    constexpr int NST = KD / 64;
    const int n0 = blockIdx.x * 256, m0 = blockIdx.y * 128, e = blockIdx.z;

    int cnt = 1 << 30, base = 0;
    const __half *Aw, *Bw;
    if (MODE == 0)      { Aw = g_xn;   Bw = g_wqkv; }
    else if (MODE == 1) { Aw = g_hd;   Bw = g_wp; }
    else if (MODE == 2) { Aw = g_xn2h; Bw = g_w1; }
    else                { Aw = g_h;    Bw = g_w2; }
    if (MODE == 2 || MODE == 3) {
        cnt = g_cnt[e];
        if (m0 >= cnt) return;
        base = g_base[e];
        Bw += (size_t)e * DD * DFF_;
    }

    extern __shared__ __align__(16) char smem[];
    const uint32_t sb = smem_u32(smem);
    const int tid = threadIdx.x;
    const int wid = tid >> 5, lane = tid & 31;
    const int wm = wid >> 2, wn = wid & 3;

    const int rloc = tid >> 2, kc = tid & 3;
    int gA0, gA1, vA0 = 1, vA1 = 1;
    {
        int i0 = m0 + rloc, i1 = m0 + rloc + 64;
        if (MODE == 2) {
            vA0 = i0 < cnt; vA1 = i1 < cnt;
            gA0 = vA0 ? g_tok[e * BT + i0] : 0;
            gA1 = vA1 ? g_tok[e * BT + i1] : 0;
        } else if (MODE == 3) {
            vA0 = i0 < cnt; vA1 = i1 < cnt;
            gA0 = base + (vA0 ? i0 : 0);
            gA1 = base + (vA1 ? i1 : 0);
        } else { gA0 = i0; gA1 = i1; }
    }
    const char* pA0 = (const char*)(Aw + (size_t)gA0 * KD) + kc * 16;
    const char* pA1 = (const char*)(Aw + (size_t)gA1 * KD) + kc * 16;
    const uint32_t ad0 = rloc * 80 + kc * 16;
    const uint32_t ad1 = (rloc + 64) * 80 + kc * 16;

    const int brow = tid >> 3, bc = tid & 7;
    const char* pB = (const char*)(Bw + (size_t)brow * LDN + n0 + bc * 8);
    const uint32_t bd0 = brow * 528 + bc * 16;

    const uint32_t aoff = (uint32_t)((lane & 15) * 80 + (lane >> 4) * 16);
    const uint32_t blane = (uint32_t)((((lane >> 3) & 1) * 8 + (lane & 7)) * 528 + (lane >> 4) * 16);

    float c[4][8][4];
#pragma unroll
    for (int i = 0; i < 4; i++)
#pragma unroll
        for (int j = 0; j < 8; j++)
#pragma unroll
            for (int q = 0; q < 4; q++) c[i][j][q] = 0.f;

    auto issue = [&](int s) {
        const uint32_t bb = sb + (uint32_t)(s & 1) * BUFSZ;
#pragma unroll
        for (int sub = 0; sub < 2; sub++) {
            const size_t ao = (size_t)s * 128 + sub * 64;          // 64B per 32-k sub
            const size_t bo = (size_t)(s * 64 + sub * 32) * LDN * 2;
            const uint32_t asub = bb + sub * APL;
            const uint32_t bsub = bb + (sub ? OB1 : OB0);
            cpa16(asub + ad0, pA0 + ao, vA0);
            cpa16(asub + ad1, pA1 + ao, vA1);
#pragma unroll
            for (int j = 0; j < 4; j++)
                cpa16(bsub + bd0 + j * 128, pB + bo + j * 128, 1);
        }
        asm volatile("cp.async.commit_group;" ::: "memory");
    };

    issue(0);
#pragma unroll 1
    for (int s = 0; s < NST; s++) {
        if (s + 1 < NST) {
            issue(s + 1);
            asm volatile("cp.async.wait_group 1;" ::: "memory");
        } else {
            asm volatile("cp.async.wait_group 0;" ::: "memory");
        }
        __syncthreads();

        const uint32_t bb = sb + (uint32_t)(s & 1) * BUFSZ;
#pragma unroll
        for (int kk = 0; kk < 4; kk++) {
            const int sub = kk >> 1, kkk = kk & 1;
            const uint32_t abase = bb + sub * APL + (uint32_t)(wm * 64) * 80 + aoff;
            const uint32_t bbase = bb + (sub ? OB1 : OB0) + blane + (uint32_t)wn * 128;
            const uint32_t kbA = kkk * 32;
            const uint32_t kbB = kkk * 8448;
            uint32_t aH[4][4], bH[8][2];
#pragma unroll
            for (int mt = 0; mt < 4; mt++)
                ldsm4(aH[mt], abase + mt * (16 * 80) + kbA);
#pragma unroll
            for (int nn = 0; nn < 4; nn++) {
                uint32_t r[4];
                ldsm4t(r, bbase + kbB + nn * 32);
                bH[2 * nn][0] = r[0]; bH[2 * nn][1] = r[1];
                bH[2 * nn + 1][0] = r[2]; bH[2 * nn + 1][1] = r[3];
            }
#pragma unroll
            for (int mt = 0; mt < 4; mt++)
#pragma unroll
                for (int nt = 0; nt < 8; nt++)
                    mma_h(c[mt][nt], aH[mt], bH[nt]);
        }
        __syncthreads();
    }

    const int gid = lane >> 2, tig = lane & 3;
#pragma unroll
    for (int mt = 0; mt < 4; mt++) {
#pragma unroll
        for (int nt = 0; nt < 8; nt++) {
            const int ng = n0 + wn * 64 + nt * 8 + tig * 2;
#pragma unroll
            for (int h = 0; h < 2; h++) {
                const int ml = wm * 64 + mt * 16 + gid + 8 * h;
                float v0 = c[mt][nt][2 * h], v1 = c[mt][nt][2 * h + 1];
                if (MODE == 0) {
                    const int m = m0 + ml;
                    const int which = ng >> 10, hh = (ng >> 6) & 15, hs = ng & 63;
                    const int bb_ = m >> 10, t = m & 1023;
                    float sc = (which == 0) ? 0.03125f : 1.0f;
                    __half* outp = (which == 0) ? g_qh : ((which == 1) ? g_kh : g_vh);
                    size_t idx = (((size_t)(bb_ * HH + hh)) * TT + t) * HSZ + hs;
                    *(uint32_t*)&outp[idx] = pack2h(__float2half_rn(v0 * sc),
                                                    __float2half_rn(v1 * sc));
                } else if (MODE == 1) {
                    const int m = m0 + ml;
                    const size_t o = (size_t)m * DD + ng;
                    float2 rr = *(const float2*)&resid[o];
                    *(float2*)&g_x2[o] = make_float2(v0 + bias[ng] + rr.x,
                                                     v1 + bias[ng + 1] + rr.y);
                } else if (MODE == 2) {
                    const int i = m0 + ml;
                    if (i < cnt) {
                        float a0 = fmaxf(v0 + bias[(size_t)e * DFF_ + ng], 0.f);
                        float a1 = fmaxf(v1 + bias[(size_t)e * DFF_ + ng + 1], 0.f);
                        size_t idx = (size_t)(base + i) * DFF_ + ng;
                        *(uint32_t*)&g_h[idx] = pack2h(__float2half_rn(a0),
                                                       __float2half_rn(a1));
                    }
                } else {
                    const int i = m0 + ml;
                    if (i < cnt) {
                        *(float2*)&g_eo[(size_t)(base + i) * DD + ng] =
                            make_float2(v0 + bias[(size_t)e * DD + ng],
                                        v1 + bias[(size_t)e * DD + ng + 1]);
                    }
                }
            }
        }
    }
}

// ---------------- HMMA fp16 flash attention: 64q x 64s tiles ----------------
#define ASTR 144

__global__ void __launch_bounds__(128, 1) attn_kernel() {
    __shared__ __align__(16) char sma[46080];
    const uint32_t sb = smem_u32(sma);
    const int tid = threadIdx.x;
    const int wid = tid >> 5, lane = tid & 31;
    const int bh = blockIdx.x, qt = blockIdx.y;

    const __half* qb  = g_qh + (size_t)bh * TT * HSZ + (size_t)qt * 64 * HSZ;
    const __half* kb0 = g_kh + (size_t)bh * TT * HSZ;
    const __half* vb0 = g_vh + (size_t)bh * TT * HSZ;

    const int row = tid >> 1, cb = (tid & 1) * 64;

    {
        const char* src = (const char*)qb + row * 128 + cb;
#pragma unroll
        for (int j = 0; j < 4; j++)
            *(uint4*)(sma + row * ASTR + cb + j * 16) = *(const uint4*)(src + j * 16);
    }

    auto issueKV = [&](int kt) {
        const uint32_t base = sb + 9216 + (uint32_t)(kt & 1) * 18432;
        const char* ks = (const char*)(kb0 + (size_t)kt * 64 * HSZ) + row * 128 + cb;
        const char* vs = (const char*)(vb0 + (size_t)kt * 64 * HSZ) + row * 128 + cb;
#pragma unroll
        for (int j = 0; j < 4; j++) {
            cpa16(base + row * ASTR + cb + j * 16, ks + j * 16, 1);
            cpa16(base + 9216 + row * ASTR + cb + j * 16, vs + j * 16, 1);
        }
        asm volatile("cp.async.commit_group;" ::: "memory");
    };

    const uint32_t aoff = (uint32_t)(wid * 16 * ASTR + (lane & 15) * ASTR + (lane >> 4) * 16);
    const uint32_t kbo  = (uint32_t)(((lane & 7) + ((lane >> 4) << 3)) * ASTR + (((lane >> 3) & 1) << 4));
    const uint32_t vbo  = (uint32_t)(((((lane >> 3) & 1) << 3) + (lane & 7)) * ASTR + ((lane >> 4) << 4));

    float O[8][4];
#pragma unroll
    for (int nt = 0; nt < 8; nt++)
#pragma unroll
        for (int q = 0; q < 4; q++) O[nt][q] = 0.f;
    float m0 = -1e30f, m1 = -1e30f, l0 = 0.f, l1 = 0.f;

    issueKV(0);
#pragma unroll 1
    for (int kt = 0; kt < 16; kt++) {
        if (kt + 1 < 16) {
            issueKV(kt + 1);
            asm volatile("cp.async.wait_group 1;" ::: "memory");
        } else {
            asm volatile("cp.async.wait_group 0;" ::: "memory");
        }
        __syncthreads();

        const uint32_t kbase = sb + 9216 + (uint32_t)(kt & 1) * 18432;
        const uint32_t vbase = kbase + 9216;

        float S[8][4];
#pragma unroll
        for (int nt = 0; nt < 8; nt++)
#pragma unroll
            for (int q = 0; q < 4; q++) S[nt][q] = 0.f;
#pragma unroll
        for (int kc = 0; kc < 4; kc++) {
            uint32_t aH[4], bK[8][2];
            ldsm4(aH, sb + aoff + kc * 32);
#pragma unroll
            for (int nn = 0; nn < 4; nn++) {
                uint32_t r[4];
                ldsm4(r, kbase + kbo + nn * (16 * ASTR) + kc * 32);
                bK[2 * nn][0] = r[0]; bK[2 * nn][1] = r[1];
                bK[2 * nn + 1][0] = r[2]; bK[2 * nn + 1][1] = r[3];
            }
#pragma unroll
            for (int nt = 0; nt < 8; nt++)
                mma_h(S[nt], aH, bK[nt]);
        }

        float mx0 = -1e30f, mx1 = -1e30f;
#pragma unroll
        for (int nt = 0; nt < 8; nt++) {
            mx0 = fmaxf(mx0, fmaxf(S[nt][0], S[nt][1]));
            mx1 = fmaxf(mx1, fmaxf(S[nt][2], S[nt][3]));
        }
        mx0 = fmaxf(mx0, __shfl_xor_sync(0xffffffffu, mx0, 1));
        mx0 = fmaxf(mx0, __shfl_xor_sync(0xffffffffu, mx0, 2));
        mx1 = fmaxf(mx1, __shfl_xor_sync(0xffffffffu, mx1, 1));
        mx1 = fmaxf(mx1, __shfl_xor_sync(0xffffffffu, mx1, 2));
        float mn0 = fmaxf(m0, mx0), mn1 = fmaxf(m1, mx1);
        float al0 = __expf(m0 - mn0), al1 = __expf(m1 - mn1);
        float rs0 = 0.f, rs1 = 0.f;
        uint32_t ph[8][2];
#pragma unroll
        for (int nt = 0; nt < 8; nt++) {
            float p0 = __expf(S[nt][0] - mn0), p1 = __expf(S[nt][1] - mn0);
            float p2 = __expf(S[nt][2] - mn1), p3 = __expf(S[nt][3] - mn1);
            rs0 += p0 + p1; rs1 += p2 + p3;
            ph[nt][0] = pack2h(__float2half_rn(p0), __float2half_rn(p1));
            ph[nt][1] = pack2h(__float2half_rn(p2), __float2half_rn(p3));
        }
        rs0 += __shfl_xor_sync(0xffffffffu, rs0, 1);
        rs0 += __shfl_xor_sync(0xffffffffu, rs0, 2);
        rs1 += __shfl_xor_sync(0xffffffffu, rs1, 1);
        rs1 += __shfl_xor_sync(0xffffffffu, rs1, 2);
        l0 = l0 * al0 + rs0; l1 = l1 * al1 + rs1;
        m0 = mn0; m1 = mn1;
#pragma unroll
        for (int nt = 0; nt < 8; nt++) {
            O[nt][0] *= al0; O[nt][1] *= al0;
            O[nt][2] *= al1; O[nt][3] *= al1;
        }

#pragma unroll
        for (int kc = 0; kc < 4; kc++) {
            uint32_t aP[4] = {ph[2 * kc][0], ph[2 * kc][1],
                              ph[2 * kc + 1][0], ph[2 * kc + 1][1]};
            uint32_t bV[8][2];
#pragma unroll
            for (int nn = 0; nn < 4; nn++) {
                uint32_t r[4];
                ldsm4t(r, vbase + vbo + kc * (16 * ASTR) + nn * 32);
                bV[2 * nn][0] = r[0]; bV[2 * nn][1] = r[1];
                bV[2 * nn + 1][0] = r[2]; bV[2 * nn + 1][1] = r[3];
            }
#pragma unroll
            for (int nt = 0; nt < 8; nt++)
                mma_h(O[nt], aP, bV[nt]);
        }
        __syncthreads();
    }

    const int b = bh >> 4, head = bh & 15;
    const float inv0 = 1.f / l0, inv1 = 1.f / l1;
    const int r0 = qt * 64 + wid * 16 + (lane >> 2);
#pragma unroll
    for (int nt = 0; nt < 8; nt++) {
        const int col = head * 64 + nt * 8 + (lane & 3) * 2;
#pragma unroll
        for (int h = 0; h < 2; h++) {
            const int t = r0 + 8 * h;
            float inv = h ? inv1 : inv0;
            size_t idx = ((size_t)(b * TT + t)) * DD + col;
            *(uint32_t*)&g_hd[idx] = pack2h(__float2half_rn(O[nt][2 * h] * inv),
                                            __float2half_rn(O[nt][2 * h + 1] * inv));
        }
    }
}

// ---------------- routing ----------------
__global__ void zero_cnt_kernel() {
    if (threadIdx.x < EE) g_cnt[threadIdx.x] = 0;
}

__global__ void route_kernel(const float* __restrict__ noise,
                             const float* __restrict__ w_route,
                             const float* __restrict__ b_route,
                             const float* __restrict__ w_noise,
                             const float* __restrict__ b_noise) {
    int tok = blockIdx.x;
    __shared__ float xs[DD];
    __shared__ float dots[16];
    for (int i = threadIdx.x; i < DD; i += 256)
        xs[i] = g_xn2[(size_t)tok * DD + i];
    __syncthreads();

    int j = threadIdx.x >> 4, lane = threadIdx.x & 15;
    const float* W = (j < 8) ? w_route : w_noise;
    int col = j & 7;
    float s = 0.f;
    for (int d = lane; d < DD; d += 16) s += xs[d] * W[(size_t)d * EE + col];
    for (int o = 8; o; o >>= 1) s += __shfl_down_sync(0xffffffffu, s, o, 16);
    if (lane == 0) dots[j] = s + ((j < 8) ? b_route[col] : b_noise[col]);
    __syncthreads();

    if (threadIdx.x == 0) {
        float noisy[EE];
        for (int ee = 0; ee < EE; ee++) {
            float nl = dots[8 + ee];
            float sp = (nl > 20.f) ? nl : log1pf(expf(nl));
            noisy[ee] = dots[ee] + noise[(size_t)tok * EE + ee] * sp;
        }
        int i1 = 0;
        for (int ee = 1; ee < EE; ee++) if (noisy[ee] > noisy[i1]) i1 = ee;
        int i2 = -1;
        for (int ee = 0; ee < EE; ee++) {
            if (ee == i1) continue;
            if (i2 < 0 || noisy[ee] > noisy[i2]) i2 = ee;
        }
        float e2 = expf(noisy[i2] - noisy[i1]);
        float inv = 1.f / (1.f + e2);
        float p1 = inv, p2 = e2 * inv;
        int pos1 = atomicAdd(&g_cnt[i1], 1);
        g_tok[i1 * BT + pos1] = tok;
        int pos2 = atomicAdd(&g_cnt[i2], 1);
        g_tok[i2 * BT + pos2] = tok;
        g_texp[tok * 2] = i1; g_tpos[tok * 2] = pos1; g_tgate[tok * 2] = p1;
        g_texp[tok * 2 + 1] = i2; g_tpos[tok * 2 + 1] = pos2; g_tgate[tok * 2 + 1] = p2;
    }
}

__global__ void scan_kernel() {
    if (threadIdx.x == 0) {
        int b = 0;
        for (int e = 0; e < EE; e++) { g_base[e] = b; b += g_cnt[e]; }
    }
}

// ---------------- final combine ----------------
__global__ void combine_kernel(float* __restrict__ out) {
    int tok = blockIdx.x;
    int e1 = g_texp[tok * 2], e2 = g_texp[tok * 2 + 1];
    float gt1 = g_tgate[tok * 2], gt2 = g_tgate[tok * 2 + 1];
    size_t s1 = (size_t)(g_base[e1] + g_tpos[tok * 2]) * DD;
    size_t s2 = (size_t)(g_base[e2] + g_tpos[tok * 2 + 1]) * DD;
    size_t o = (size_t)tok * DD;
    for (int i = threadIdx.x * 4; i < DD; i += 256 * 4) {
        float4 a = *(float4*)&g_xn2[o + i];
        float4 u = *(float4*)&g_eo[s1 + i];
        float4 w = *(float4*)&g_eo[s2 + i];
        float4 r = make_float4(a.x + gt1 * u.x + gt2 * w.x,
                               a.y + gt1 * u.y + gt2 * w.y,
                               a.z + gt1 * u.z + gt2 * w.z,
                               a.w + gt1 * u.w + gt2 * w.w);
        *(float4*)&out[o + i] = r;
    }
}

// ---------------- launch ----------------
extern "C" void kernel_launch(void* const* d_in, const int* in_sizes, int n_in,
                              void* d_out, int out_size) {
    const float* x       = (const float*)d_in[0];
    const float* noise   = (const float*)d_in[1];
    const float* ln1_g   = (const float*)d_in[2];
    const float* ln1_b   = (const float*)d_in[3];
    const float* wq      = (const float*)d_in[4];
    const float* wk      = (const float*)d_in[5];
    const float* wv      = (const float*)d_in[6];
    const float* w_proj  = (const float*)d_in[7];
    const float* b_proj  = (const float*)d_in[8];
    const float* ln2_g   = (const float*)d_in[9];
    const float* ln2_b   = (const float*)d_in[10];
    const float* w_route = (const float*)d_in[11];
    const float* b_route = (const float*)d_in[12];
    const float* w_noise = (const float*)d_in[13];
    const float* b_noise = (const float*)d_in[14];
    const float* w1      = (const float*)d_in[15];
    const float* b1      = (const float*)d_in[16];
    const float* w2      = (const float*)d_in[17];
    const float* b2      = (const float*)d_in[18];
    float* out = (float*)d_out;

    cudaFuncSetAttribute(hmma_gemm<0>, cudaFuncAttributeMaxDynamicSharedMemorySize, SMEM_BYTES);
    cudaFuncSetAttribute(hmma_gemm<1>, cudaFuncAttributeMaxDynamicSharedMemorySize, SMEM_BYTES);
    cudaFuncSetAttribute(hmma_gemm<2>, cudaFuncAttributeMaxDynamicSharedMemorySize, SMEM_BYTES);
    cudaFuncSetAttribute(hmma_gemm<3>, cudaFuncAttributeMaxDynamicSharedMemorySize, SMEM_BYTES);

    __half *xn, *xn2h, *wqkv, *wp, *w1h, *w2h;
    float *x2, *xn2;
    cudaGetSymbolAddress((void**)&xn,    g_xn);
    cudaGetSymbolAddress((void**)&xn2h,  g_xn2h);
    cudaGetSymbolAddress((void**)&wqkv,  g_wqkv);
    cudaGetSymbolAddress((void**)&wp,    g_wp);
    cudaGetSymbolAddress((void**)&w1h,   g_w1);
    cudaGetSymbolAddress((void**)&w2h,   g_w2);
    cudaGetSymbolAddress((void**)&x2,    g_x2);
    cudaGetSymbolAddress((void**)&xn2,   g_xn2);

    conv_qkv<<<1024, 256>>>(wq, wqkv);
    conv_qkv<<<1024, 256>>>(wk, wqkv + 1024);
    conv_qkv<<<1024, 256>>>(wv, wqkv + 2048);
    ln_kernel<<<BT, 256>>>(x, ln1_g, ln1_b, nullptr, xn);
    conv_stream<<<1024, 256>>>((const float4*)w_proj, (uint2*)wp, DD * DD / 4);
    hmma_gemm<0><<<dim3(12, 32, 1), 256, SMEM_BYTES>>>(nullptr, nullptr);

    attn_kernel<<<dim3(BB * HH, TT / 64), 128>>>();

    hmma_gemm<1><<<dim3(4, 32, 1), 256, SMEM_BYTES>>>(b_proj, x);

    ln_kernel<<<BT, 256>>>(x2, ln2_g, ln2_b, xn2, xn2h);

    zero_cnt_kernel<<<1, 32>>>();
    route_kernel<<<BT, 256>>>(noise, w_route, b_route, w_noise, b_noise);
    scan_kernel<<<1, 32>>>();

    conv_stream<<<2048, 256>>>((const float4*)w1, (uint2*)w1h, EE * DD * DFF_ / 4);
    conv_stream<<<2048, 256>>>((const float4*)w2, (uint2*)w2h, EE * DFF_ * DD / 4);

    hmma_gemm<2><<<dim3(16, 32, EE), 256, SMEM_BYTES>>>(b1, nullptr);
    hmma_gemm<3><<<dim3(4, 32, EE), 256, SMEM_BYTES>>>(b2, nullptr);

    combine_kernel<<<BT, 256>>>(out);
}

// round 16
// speedup vs baseline: 3.4002x; 1.0270x over previous
#include <cuda_runtime.h>
#include <cuda_fp16.h>
#include <math.h>
#include <stdint.h>

#define BB   4
#define TT   1024
#define DD   1024
#define HH   16
#define HSZ  64
#define EE   8
#define DFF_ 4096
#define BT   4096
#define NSLOT (BT*2)

// ---------------- device scratch ----------------
__device__ float g_x2 [BT*DD];
__device__ float g_xn2[BT*DD];
__device__ float g_eo [NSLOT*DD];

__device__ __align__(16) __half g_qh  [BT*DD];
__device__ __align__(16) __half g_kh  [BT*DD];
__device__ __align__(16) __half g_vh  [BT*DD];
__device__ __align__(16) __half g_xn  [BT*DD];
__device__ __align__(16) __half g_hd  [BT*DD];
__device__ __align__(16) __half g_xn2h[BT*DD];
__device__ __align__(16) __half g_h   [NSLOT*DFF_];
__device__ __align__(16) __half g_wqkv[DD*3*DD];
__device__ __align__(16) __half g_wp  [DD*DD];
__device__ __align__(16) __half g_w1  [EE*DD*DFF_];
__device__ __align__(16) __half g_w2  [EE*DFF_*DD];

__device__ int   g_cnt [EE];
__device__ int   g_base[EE];
__device__ int   g_tok [EE*BT];
__device__ int   g_texp[BT*2];
__device__ int   g_tpos[BT*2];
__device__ float g_tgate[BT*2];

// ---------------- helpers ----------------
__device__ __forceinline__ uint32_t smem_u32(const void* p) {
    uint32_t a;
    asm("{ .reg .u64 t; cvta.to.shared.u64 t, %1; cvt.u32.u64 %0, t; }" : "=r"(a) : "l"(p));
    return a;
}
__device__ __forceinline__ void cpa16(uint32_t dst, const void* src, int valid) {
    asm volatile("cp.async.cg.shared.global [%0], [%1], 16, %2;"
                 :: "r"(dst), "l"(src), "r"(valid ? 16 : 0) : "memory");
}
__device__ __forceinline__ void ldsm4(uint32_t* r, uint32_t addr) {
    asm volatile("ldmatrix.sync.aligned.m8n8.x4.shared.b16 {%0,%1,%2,%3}, [%4];"
                 : "=r"(r[0]), "=r"(r[1]), "=r"(r[2]), "=r"(r[3]) : "r"(addr));
}
__device__ __forceinline__ void ldsm4t(uint32_t* r, uint32_t addr) {
    asm volatile("ldmatrix.sync.aligned.m8n8.x4.trans.shared.b16 {%0,%1,%2,%3}, [%4];"
                 : "=r"(r[0]), "=r"(r[1]), "=r"(r[2]), "=r"(r[3]) : "r"(addr));
}
__device__ __forceinline__ void mma_h(float* c, const uint32_t* a, const uint32_t* b) {
    asm volatile(
        "mma.sync.aligned.m16n8k16.row.col.f32.f16.f16.f32 "
        "{%0,%1,%2,%3},{%4,%5,%6,%7},{%8,%9},{%0,%1,%2,%3};"
        : "+f"(c[0]), "+f"(c[1]), "+f"(c[2]), "+f"(c[3])
        : "r"(a[0]), "r"(a[1]), "r"(a[2]), "r"(a[3]), "r"(b[0]), "r"(b[1]));
}
__device__ __forceinline__ uint32_t pack2h(__half a, __half b) {
    return ((uint32_t)__half_as_ushort(b) << 16) | (uint32_t)__half_as_ushort(a);
}

// ---------------- LayerNorm (+ fp16 output) ----------------
__global__ void ln_kernel(const float* __restrict__ x,
                          const float* __restrict__ g,
                          const float* __restrict__ b,
                          float* __restrict__ out,
                          __half* __restrict__ oh) {
    int row = blockIdx.x;
    const float* xr = x + (size_t)row * DD;
    float s = 0.f, s2 = 0.f;
    for (int i = threadIdx.x; i < DD; i += 256) {
        float v = xr[i]; s += v; s2 += v * v;
    }
    for (int o = 16; o; o >>= 1) {
        s  += __shfl_xor_sync(0xffffffffu, s,  o);
        s2 += __shfl_xor_sync(0xffffffffu, s2, o);
    }
    __shared__ float ss[8], ss2[8];
    __shared__ float mu, rs;
    if ((threadIdx.x & 31) == 0) { ss[threadIdx.x >> 5] = s; ss2[threadIdx.x >> 5] = s2; }
    __syncthreads();
    if (threadIdx.x == 0) {
        float t = 0.f, t2 = 0.f;
        for (int i = 0; i < 8; i++) { t += ss[i]; t2 += ss2[i]; }
        float m = t / (float)DD;
        mu = m; rs = rsqrtf(t2 / (float)DD - m * m + 1e-5f);
    }
    __syncthreads();
    float m = mu, r = rs;
    for (int i = threadIdx.x; i < DD; i += 256) {
        float v = (xr[i] - m) * r * g[i] + b[i];
        if (out) out[(size_t)row * DD + i] = v;
        oh[(size_t)row * DD + i] = __float2half_rn(v);
    }
}

// ---------------- streaming weight convert: fp32 -> fp16 ----------------
__global__ void conv_stream(const float4* __restrict__ in,
                            uint2* __restrict__ oh, int n4) {
    for (int i = blockIdx.x * blockDim.x + threadIdx.x; i < n4;
         i += gridDim.x * blockDim.x) {
        float4 v = in[i];
        oh[i] = make_uint2(pack2h(__float2half_rn(v.x), __float2half_rn(v.y)),
                           pack2h(__float2half_rn(v.z), __float2half_rn(v.w)));
    }
}

// QKV: [H][D][HS] fp32 -> rows d of [1024][3072] fp16
__global__ void conv_qkv(const float* __restrict__ in,
                         __half* __restrict__ oh) {
    int idx = blockIdx.x * 256 + threadIdx.x;
    int hs4 = idx & 15;
    int d   = (idx >> 4) & 1023;
    int h   = idx >> 14;
    float4 v = *(const float4*)(in + (((size_t)h << 10) + d) * 64 + hs4 * 4);
    size_t o = (size_t)d * 3072 + h * 64 + hs4 * 4;
    *(uint2*)(oh + o) = make_uint2(pack2h(__float2half_rn(v.x), __float2half_rn(v.y)),
                                   pack2h(__float2half_rn(v.z), __float2half_rn(v.w)));
}

// ---------------- HMMA fp16 GEMM: 128x256 tile, warp 64x64, K=64/stage, 3-deep ----------------
#define APL 10240
#define BPL 16896
#define OB0 (2*APL)
#define OB1 (2*APL + BPL)
#define BUFSZ (2*APL + 2*BPL)          // 54272
#define SMEM_BYTES (3*BUFSZ)           // 162816

template<int MODE>
__global__ void __launch_bounds__(256, 1)
hmma_gemm(const float* __restrict__ bias, const float* __restrict__ resid) {
    constexpr int KD  = (MODE == 3) ? DFF_ : DD;
    constexpr int LDN = (MODE == 0) ? 3 * DD : ((MODE == 2) ? DFF_ : DD);
    constexpr int NST = KD / 64;
    const int n0 = blockIdx.x * 256, m0 = blockIdx.y * 128, e = blockIdx.z;

    int cnt = 1 << 30, base = 0;
    const __half *Aw, *Bw;
    if (MODE == 0)      { Aw = g_xn;   Bw = g_wqkv; }
    else if (MODE == 1) { Aw = g_hd;   Bw = g_wp; }
    else if (MODE == 2) { Aw = g_xn2h; Bw = g_w1; }
    else                { Aw = g_h;    Bw = g_w2; }
    if (MODE == 2 || MODE == 3) {
        cnt = g_cnt[e];
        if (m0 >= cnt) return;
        base = g_base[e];
        Bw += (size_t)e * DD * DFF_;
    }

    extern __shared__ __align__(16) char smem[];
    const uint32_t sb = smem_u32(smem);
    const int tid = threadIdx.x;
    const int wid = tid >> 5, lane = tid & 31;
    const int wm = wid >> 2, wn = wid & 3;

    const int rloc = tid >> 2, kc = tid & 3;
    int gA0, gA1, vA0 = 1, vA1 = 1;
    {
        int i0 = m0 + rloc, i1 = m0 + rloc + 64;
        if (MODE == 2) {
            vA0 = i0 < cnt; vA1 = i1 < cnt;
            gA0 = vA0 ? g_tok[e * BT + i0] : 0;
            gA1 = vA1 ? g_tok[e * BT + i1] : 0;
        } else if (MODE == 3) {
            vA0 = i0 < cnt; vA1 = i1 < cnt;
            gA0 = base + (vA0 ? i0 : 0);
            gA1 = base + (vA1 ? i1 : 0);
        } else { gA0 = i0; gA1 = i1; }
    }
    const char* pA0 = (const char*)(Aw + (size_t)gA0 * KD) + kc * 16;
    const char* pA1 = (const char*)(Aw + (size_t)gA1 * KD) + kc * 16;
    const uint32_t ad0 = rloc * 80 + kc * 16;
    const uint32_t ad1 = (rloc + 64) * 80 + kc * 16;

    const int brow = tid >> 3, bc = tid & 7;
    const char* pB = (const char*)(Bw + (size_t)brow * LDN + n0 + bc * 8);
    const uint32_t bd0 = brow * 528 + bc * 16;

    const uint32_t aoff = (uint32_t)((lane & 15) * 80 + (lane >> 4) * 16);
    const uint32_t blane = (uint32_t)((((lane >> 3) & 1) * 8 + (lane & 7)) * 528 + (lane >> 4) * 16);

    float c[4][8][4];
#pragma unroll
    for (int i = 0; i < 4; i++)
#pragma unroll
        for (int j = 0; j < 8; j++)
#pragma unroll
            for (int q = 0; q < 4; q++) c[i][j][q] = 0.f;

    auto issue = [&](int s) {
        const uint32_t bb = sb + (uint32_t)(s % 3) * BUFSZ;
#pragma unroll
        for (int sub = 0; sub < 2; sub++) {
            const size_t ao = (size_t)s * 128 + sub * 64;
            const size_t bo = (size_t)(s * 64 + sub * 32) * LDN * 2;
            const uint32_t asub = bb + sub * APL;
            const uint32_t bsub = bb + (sub ? OB1 : OB0);
            cpa16(asub + ad0, pA0 + ao, vA0);
            cpa16(asub + ad1, pA1 + ao, vA1);
#pragma unroll
            for (int j = 0; j < 4; j++)
                cpa16(bsub + bd0 + j * 128, pB + bo + j * 128, 1);
        }
        asm volatile("cp.async.commit_group;" ::: "memory");
    };

    issue(0);
    if (NST > 1) issue(1);
#pragma unroll 1
    for (int s = 0; s < NST; s++) {
        if (s + 1 < NST) asm volatile("cp.async.wait_group 1;" ::: "memory");
        else             asm volatile("cp.async.wait_group 0;" ::: "memory");
        __syncthreads();
        if (s + 2 < NST) issue(s + 2);   // writes buf[(s+2)%3]; last read in compute(s-1)

        const uint32_t bb = sb + (uint32_t)(s % 3) * BUFSZ;
#pragma unroll
        for (int kk = 0; kk < 4; kk++) {
            const int sub = kk >> 1, kkk = kk & 1;
            const uint32_t abase = bb + sub * APL + (uint32_t)(wm * 64) * 80 + aoff;
            const uint32_t bbase = bb + (sub ? OB1 : OB0) + blane + (uint32_t)wn * 128;
            const uint32_t kbA = kkk * 32;
            const uint32_t kbB = kkk * 8448;
            uint32_t aH[4][4], bH[8][2];
#pragma unroll
            for (int mt = 0; mt < 4; mt++)
                ldsm4(aH[mt], abase + mt * (16 * 80) + kbA);
#pragma unroll
            for (int nn = 0; nn < 4; nn++) {
                uint32_t r[4];
                ldsm4t(r, bbase + kbB + nn * 32);
                bH[2 * nn][0] = r[0]; bH[2 * nn][1] = r[1];
                bH[2 * nn + 1][0] = r[2]; bH[2 * nn + 1][1] = r[3];
            }
#pragma unroll
            for (int mt = 0; mt < 4; mt++)
#pragma unroll
                for (int nt = 0; nt < 8; nt++)
                    mma_h(c[mt][nt], aH[mt], bH[nt]);
        }
    }

    const int gid = lane >> 2, tig = lane & 3;
#pragma unroll
    for (int mt = 0; mt < 4; mt++) {
#pragma unroll
        for (int nt = 0; nt < 8; nt++) {
            const int ng = n0 + wn * 64 + nt * 8 + tig * 2;
#pragma unroll
            for (int h = 0; h < 2; h++) {
                const int ml = wm * 64 + mt * 16 + gid + 8 * h;
                float v0 = c[mt][nt][2 * h], v1 = c[mt][nt][2 * h + 1];
                if (MODE == 0) {
                    const int m = m0 + ml;
                    const int which = ng >> 10, hh = (ng >> 6) & 15, hs = ng & 63;
                    const int bb_ = m >> 10, t = m & 1023;
                    float sc = (which == 0) ? 0.03125f : 1.0f;
                    __half* outp = (which == 0) ? g_qh : ((which == 1) ? g_kh : g_vh);
                    size_t idx = (((size_t)(bb_ * HH + hh)) * TT + t) * HSZ + hs;
                    *(uint32_t*)&outp[idx] = pack2h(__float2half_rn(v0 * sc),
                                                    __float2half_rn(v1 * sc));
                } else if (MODE == 1) {
                    const int m = m0 + ml;
                    const size_t o = (size_t)m * DD + ng;
                    float2 rr = *(const float2*)&resid[o];
                    *(float2*)&g_x2[o] = make_float2(v0 + bias[ng] + rr.x,
                                                     v1 + bias[ng + 1] + rr.y);
                } else if (MODE == 2) {
                    const int i = m0 + ml;
                    if (i < cnt) {
                        float a0 = fmaxf(v0 + bias[(size_t)e * DFF_ + ng], 0.f);
                        float a1 = fmaxf(v1 + bias[(size_t)e * DFF_ + ng + 1], 0.f);
                        size_t idx = (size_t)(base + i) * DFF_ + ng;
                        *(uint32_t*)&g_h[idx] = pack2h(__float2half_rn(a0),
                                                       __float2half_rn(a1));
                    }
                } else {
                    const int i = m0 + ml;
                    if (i < cnt) {
                        *(float2*)&g_eo[(size_t)(base + i) * DD + ng] =
                            make_float2(v0 + bias[(size_t)e * DD + ng],
                                        v1 + bias[(size_t)e * DD + ng + 1]);
                    }
                }
            }
        }
    }
}

// ---------------- HMMA fp16 flash attention: 64q x 64s tiles ----------------
#define ASTR 144

__global__ void __launch_bounds__(128, 1) attn_kernel() {
    __shared__ __align__(16) char sma[46080];
    const uint32_t sb = smem_u32(sma);
    const int tid = threadIdx.x;
    const int wid = tid >> 5, lane = tid & 31;
    const int bh = blockIdx.x, qt = blockIdx.y;

    const __half* qb  = g_qh + (size_t)bh * TT * HSZ + (size_t)qt * 64 * HSZ;
    const __half* kb0 = g_kh + (size_t)bh * TT * HSZ;
    const __half* vb0 = g_vh + (size_t)bh * TT * HSZ;

    const int row = tid >> 1, cb = (tid & 1) * 64;

    {
        const char* src = (const char*)qb + row * 128 + cb;
#pragma unroll
        for (int j = 0; j < 4; j++)
            *(uint4*)(sma + row * ASTR + cb + j * 16) = *(const uint4*)(src + j * 16);
    }

    auto issueKV = [&](int kt) {
        const uint32_t base = sb + 9216 + (uint32_t)(kt & 1) * 18432;
        const char* ks = (const char*)(kb0 + (size_t)kt * 64 * HSZ) + row * 128 + cb;
        const char* vs = (const char*)(vb0 + (size_t)kt * 64 * HSZ) + row * 128 + cb;
#pragma unroll
        for (int j = 0; j < 4; j++) {
            cpa16(base + row * ASTR + cb + j * 16, ks + j * 16, 1);
            cpa16(base + 9216 + row * ASTR + cb + j * 16, vs + j * 16, 1);
        }
        asm volatile("cp.async.commit_group;" ::: "memory");
    };

    const uint32_t aoff = (uint32_t)(wid * 16 * ASTR + (lane & 15) * ASTR + (lane >> 4) * 16);
    const uint32_t kbo  = (uint32_t)(((lane & 7) + ((lane >> 4) << 3)) * ASTR + (((lane >> 3) & 1) << 4));
    const uint32_t vbo  = (uint32_t)(((((lane >> 3) & 1) << 3) + (lane & 7)) * ASTR + ((lane >> 4) << 4));

    float O[8][4];
#pragma unroll
    for (int nt = 0; nt < 8; nt++)
#pragma unroll
        for (int q = 0; q < 4; q++) O[nt][q] = 0.f;
    float m0 = -1e30f, m1 = -1e30f, l0 = 0.f, l1 = 0.f;

    issueKV(0);
#pragma unroll 1
    for (int kt = 0; kt < 16; kt++) {
        if (kt + 1 < 16) {
            issueKV(kt + 1);
            asm volatile("cp.async.wait_group 1;" ::: "memory");
        } else {
            asm volatile("cp.async.wait_group 0;" ::: "memory");
        }
        __syncthreads();

        const uint32_t kbase = sb + 9216 + (uint32_t)(kt & 1) * 18432;
        const uint32_t vbase = kbase + 9216;

        float S[8][4];
#pragma unroll
        for (int nt = 0; nt < 8; nt++)
#pragma unroll
            for (int q = 0; q < 4; q++) S[nt][q] = 0.f;
#pragma unroll
        for (int kc = 0; kc < 4; kc++) {
            uint32_t aH[4], bK[8][2];
            ldsm4(aH, sb + aoff + kc * 32);
#pragma unroll
            for (int nn = 0; nn < 4; nn++) {
                uint32_t r[4];
                ldsm4(r, kbase + kbo + nn * (16 * ASTR) + kc * 32);
                bK[2 * nn][0] = r[0]; bK[2 * nn][1] = r[1];
                bK[2 * nn + 1][0] = r[2]; bK[2 * nn + 1][1] = r[3];
            }
#pragma unroll
            for (int nt = 0; nt < 8; nt++)
                mma_h(S[nt], aH, bK[nt]);
        }

        float mx0 = -1e30f, mx1 = -1e30f;
#pragma unroll
        for (int nt = 0; nt < 8; nt++) {
            mx0 = fmaxf(mx0, fmaxf(S[nt][0], S[nt][1]));
            mx1 = fmaxf(mx1, fmaxf(S[nt][2], S[nt][3]));
        }
        mx0 = fmaxf(mx0, __shfl_xor_sync(0xffffffffu, mx0, 1));
        mx0 = fmaxf(mx0, __shfl_xor_sync(0xffffffffu, mx0, 2));
        mx1 = fmaxf(mx1, __shfl_xor_sync(0xffffffffu, mx1, 1));
        mx1 = fmaxf(mx1, __shfl_xor_sync(0xffffffffu, mx1, 2));
        float mn0 = fmaxf(m0, mx0), mn1 = fmaxf(m1, mx1);
        float al0 = __expf(m0 - mn0), al1 = __expf(m1 - mn1);
        float rs0 = 0.f, rs1 = 0.f;
        uint32_t ph[8][2];
#pragma unroll
        for (int nt = 0; nt < 8; nt++) {
            float p0 = __expf(S[nt][0] - mn0), p1 = __expf(S[nt][1] - mn0);
            float p2 = __expf(S[nt][2] - mn1), p3 = __expf(S[nt][3] - mn1);
            rs0 += p0 + p1; rs1 += p2 + p3;
            ph[nt][0] = pack2h(__float2half_rn(p0), __float2half_rn(p1));
            ph[nt][1] = pack2h(__float2half_rn(p2), __float2half_rn(p3));
        }
        rs0 += __shfl_xor_sync(0xffffffffu, rs0, 1);
        rs0 += __shfl_xor_sync(0xffffffffu, rs0, 2);
        rs1 += __shfl_xor_sync(0xffffffffu, rs1, 1);
        rs1 += __shfl_xor_sync(0xffffffffu, rs1, 2);
        l0 = l0 * al0 + rs0; l1 = l1 * al1 + rs1;
        m0 = mn0; m1 = mn1;
#pragma unroll
        for (int nt = 0; nt < 8; nt++) {
            O[nt][0] *= al0; O[nt][1] *= al0;
            O[nt][2] *= al1; O[nt][3] *= al1;
        }

#pragma unroll
        for (int kc = 0; kc < 4; kc++) {
            uint32_t aP[4] = {ph[2 * kc][0], ph[2 * kc][1],
                              ph[2 * kc + 1][0], ph[2 * kc + 1][1]};
            uint32_t bV[8][2];
#pragma unroll
            for (int nn = 0; nn < 4; nn++) {
                uint32_t r[4];
                ldsm4t(r, vbase + vbo + kc * (16 * ASTR) + nn * 32);
                bV[2 * nn][0] = r[0]; bV[2 * nn][1] = r[1];
                bV[2 * nn + 1][0] = r[2]; bV[2 * nn + 1][1] = r[3];
            }
#pragma unroll
            for (int nt = 0; nt < 8; nt++)
                mma_h(O[nt], aP, bV[nt]);
        }
        __syncthreads();
    }

    const int b = bh >> 4, head = bh & 15;
    const float inv0 = 1.f / l0, inv1 = 1.f / l1;
    const int r0 = qt * 64 + wid * 16 + (lane >> 2);
#pragma unroll
    for (int nt = 0; nt < 8; nt++) {
        const int col = head * 64 + nt * 8 + (lane & 3) * 2;
#pragma unroll
        for (int h = 0; h < 2; h++) {
            const int t = r0 + 8 * h;
            float inv = h ? inv1 : inv0;
            size_t idx = ((size_t)(b * TT + t)) * DD + col;
            *(uint32_t*)&g_hd[idx] = pack2h(__float2half_rn(O[nt][2 * h] * inv),
                                            __float2half_rn(O[nt][2 * h + 1] * inv));
        }
    }
}

// ---------------- routing ----------------
__global__ void zero_cnt_kernel() {
    if (threadIdx.x < EE) g_cnt[threadIdx.x] = 0;
}

__global__ void route_kernel(const float* __restrict__ noise,
                             const float* __restrict__ w_route,
                             const float* __restrict__ b_route,
                             const float* __restrict__ w_noise,
                             const float* __restrict__ b_noise) {
    int tok = blockIdx.x;
    __shared__ float xs[DD];
    __shared__ float dots[16];
    for (int i = threadIdx.x; i < DD; i += 256)
        xs[i] = g_xn2[(size_t)tok * DD + i];
    __syncthreads();

    int j = threadIdx.x >> 4, lane = threadIdx.x & 15;
    const float* W = (j < 8) ? w_route : w_noise;
    int col = j & 7;
    float s = 0.f;
    for (int d = lane; d < DD; d += 16) s += xs[d] * W[(size_t)d * EE + col];
    for (int o = 8; o; o >>= 1) s += __shfl_down_sync(0xffffffffu, s, o, 16);
    if (lane == 0) dots[j] = s + ((j < 8) ? b_route[col] : b_noise[col]);
    __syncthreads();

    if (threadIdx.x == 0) {
        float noisy[EE];
        for (int ee = 0; ee < EE; ee++) {
            float nl = dots[8 + ee];
            float sp = (nl > 20.f) ? nl : log1pf(expf(nl));
            noisy[ee] = dots[ee] + noise[(size_t)tok * EE + ee] * sp;
        }
        int i1 = 0;
        for (int ee = 1; ee < EE; ee++) if (noisy[ee] > noisy[i1]) i1 = ee;
        int i2 = -1;
        for (int ee = 0; ee < EE; ee++) {
            if (ee == i1) continue;
            if (i2 < 0 || noisy[ee] > noisy[i2]) i2 = ee;
        }
        float e2 = expf(noisy[i2] - noisy[i1]);
        float inv = 1.f / (1.f + e2);
        float p1 = inv, p2 = e2 * inv;
        int pos1 = atomicAdd(&g_cnt[i1], 1);
        g_tok[i1 * BT + pos1] = tok;
        int pos2 = atomicAdd(&g_cnt[i2], 1);
        g_tok[i2 * BT + pos2] = tok;
        g_texp[tok * 2] = i1; g_tpos[tok * 2] = pos1; g_tgate[tok * 2] = p1;
        g_texp[tok * 2 + 1] = i2; g_tpos[tok * 2 + 1] = pos2; g_tgate[tok * 2 + 1] = p2;
    }
}

__global__ void scan_kernel() {
    if (threadIdx.x == 0) {
        int b = 0;
        for (int e = 0; e < EE; e++) { g_base[e] = b; b += g_cnt[e]; }
    }
}

// ---------------- final combine ----------------
__global__ void combine_kernel(float* __restrict__ out) {
    int tok = blockIdx.x;
    int e1 = g_texp[tok * 2], e2 = g_texp[tok * 2 + 1];
    float gt1 = g_tgate[tok * 2], gt2 = g_tgate[tok * 2 + 1];
    size_t s1 = (size_t)(g_base[e1] + g_tpos[tok * 2]) * DD;
    size_t s2 = (size_t)(g_base[e2] + g_tpos[tok * 2 + 1]) * DD;
    size_t o = (size_t)tok * DD;
    for (int i = threadIdx.x * 4; i < DD; i += 256 * 4) {
        float4 a = *(float4*)&g_xn2[o + i];
        float4 u = *(float4*)&g_eo[s1 + i];
        float4 w = *(float4*)&g_eo[s2 + i];
        float4 r = make_float4(a.x + gt1 * u.x + gt2 * w.x,
                               a.y + gt1 * u.y + gt2 * w.y,
                               a.z + gt1 * u.z + gt2 * w.z,
                               a.w + gt1 * u.w + gt2 * w.w);
        *(float4*)&out[o + i] = r;
    }
}

// ---------------- launch ----------------
extern "C" void kernel_launch(void* const* d_in, const int* in_sizes, int n_in,
                              void* d_out, int out_size) {
    const float* x       = (const float*)d_in[0];
    const float* noise   = (const float*)d_in[1];
    const float* ln1_g   = (const float*)d_in[2];
    const float* ln1_b   = (const float*)d_in[3];
    const float* wq      = (const float*)d_in[4];
    const float* wk      = (const float*)d_in[5];
    const float* wv      = (const float*)d_in[6];
    const float* w_proj  = (const float*)d_in[7];
    const float* b_proj  = (const float*)d_in[8];
    const float* ln2_g   = (const float*)d_in[9];
    const float* ln2_b   = (const float*)d_in[10];
    const float* w_route = (const float*)d_in[11];
    const float* b_route = (const float*)d_in[12];
    const float* w_noise = (const float*)d_in[13];
    const float* b_noise = (const float*)d_in[14];
    const float* w1      = (const float*)d_in[15];
    const float* b1      = (const float*)d_in[16];
    const float* w2      = (const float*)d_in[17];
    const float* b2      = (const float*)d_in[18];
    float* out = (float*)d_out;

    cudaFuncSetAttribute(hmma_gemm<0>, cudaFuncAttributeMaxDynamicSharedMemorySize, SMEM_BYTES);
    cudaFuncSetAttribute(hmma_gemm<1>, cudaFuncAttributeMaxDynamicSharedMemorySize, SMEM_BYTES);
    cudaFuncSetAttribute(hmma_gemm<2>, cudaFuncAttributeMaxDynamicSharedMemorySize, SMEM_BYTES);
    cudaFuncSetAttribute(hmma_gemm<3>, cudaFuncAttributeMaxDynamicSharedMemorySize, SMEM_BYTES);

    __half *xn, *xn2h, *wqkv, *wp, *w1h, *w2h;
    float *x2, *xn2;
    cudaGetSymbolAddress((void**)&xn,    g_xn);
    cudaGetSymbolAddress((void**)&xn2h,  g_xn2h);
    cudaGetSymbolAddress((void**)&wqkv,  g_wqkv);
    cudaGetSymbolAddress((void**)&wp,    g_wp);
    cudaGetSymbolAddress((void**)&w1h,   g_w1);
    cudaGetSymbolAddress((void**)&w2h,   g_w2);
    cudaGetSymbolAddress((void**)&x2,    g_x2);
    cudaGetSymbolAddress((void**)&xn2,   g_xn2);

    // ---- fork a side stream for weight conversions (graph-capture fork/join) ----
    cudaStream_t s2;
    cudaStreamCreateWithFlags(&s2, cudaStreamNonBlocking);
    cudaEvent_t evFork, evQKVW, evMoEW;
    cudaEventCreateWithFlags(&evFork, cudaEventDisableTiming);
    cudaEventCreateWithFlags(&evQKVW, cudaEventDisableTiming);
    cudaEventCreateWithFlags(&evMoEW, cudaEventDisableTiming);

    cudaEventRecord(evFork, 0);
    cudaStreamWaitEvent(s2, evFork, 0);

    // side stream: all weight conversions
    conv_qkv<<<1024, 256, 0, s2>>>(wq, wqkv);
    conv_qkv<<<1024, 256, 0, s2>>>(wk, wqkv + 1024);
    conv_qkv<<<1024, 256, 0, s2>>>(wv, wqkv + 2048);
    conv_stream<<<1024, 256, 0, s2>>>((const float4*)w_proj, (uint2*)wp, DD * DD / 4);
    cudaEventRecord(evQKVW, s2);
    conv_stream<<<2048, 256, 0, s2>>>((const float4*)w1, (uint2*)w1h, EE * DD * DFF_ / 4);
    conv_stream<<<2048, 256, 0, s2>>>((const float4*)w2, (uint2*)w2h, EE * DFF_ * DD / 4);
    cudaEventRecord(evMoEW, s2);

    // main stream
    ln_kernel<<<BT, 256>>>(x, ln1_g, ln1_b, nullptr, xn);

    cudaStreamWaitEvent(0, evQKVW, 0);
    hmma_gemm<0><<<dim3(12, 32, 1), 256, SMEM_BYTES>>>(nullptr, nullptr);

    attn_kernel<<<dim3(BB * HH, TT / 64), 128>>>();

    hmma_gemm<1><<<dim3(4, 32, 1), 256, SMEM_BYTES>>>(b_proj, x);

    ln_kernel<<<BT, 256>>>(x2, ln2_g, ln2_b, xn2, xn2h);

    zero_cnt_kernel<<<1, 32>>>();
    route_kernel<<<BT, 256>>>(noise, w_route, b_route, w_noise, b_noise);
    scan_kernel<<<1, 32>>>();

    cudaStreamWaitEvent(0, evMoEW, 0);
    hmma_gemm<2><<<dim3(16, 32, EE), 256, SMEM_BYTES>>>(b1, nullptr);
    hmma_gemm<3><<<dim3(4, 32, EE), 256, SMEM_BYTES>>>(b2, nullptr);

    combine_kernel<<<BT, 256>>>(out);

    cudaEventDestroy(evFork);
    cudaEventDestroy(evQKVW);
    cudaEventDestroy(evMoEW);
    cudaStreamDestroy(s2);
}